// round 6
// baseline (speedup 1.0000x reference)
#include <cuda_runtime.h>
#include <cuda_bf16.h>
#include <math.h>
#include <stdint.h>

// Problem constants
#define B_Q   256
#define M_MEM 200000
#define D_DIM 384
#define H_DIM 512
#define TOPK  5
#define TM    128
#define NSLAB ((M_MEM + TM - 1) / TM)   // 1563

// ---------------- device scratch ----------------
__device__ float g_center[2];
__device__ float g_act[M_MEM];
__device__ float g_rn[M_MEM];
__device__ __align__(16) __nv_bfloat16 g_mhi[(size_t)M_MEM * D_DIM];
__device__ __align__(16) __nv_bfloat16 g_mlo[(size_t)M_MEM * D_DIM];
__device__ __align__(16) __nv_bfloat16 g_qhi[B_Q * D_DIM];
__device__ __align__(16) __nv_bfloat16 g_qlo[B_Q * D_DIM];
__device__ float g_cand_val[(size_t)NSLAB * B_Q * TOPK];
__device__ int   g_cand_idx[(size_t)NSLAB * B_Q * TOPK];
__device__ int   g_topk[B_Q * TOPK];
// RNN path scratch
__device__ __align__(16) __nv_bfloat16 g_whh_h[H_DIM * H_DIM];
__device__ __align__(16) __nv_bfloat16 g_whh_l[H_DIM * H_DIM];
__device__ __align__(16) __nv_bfloat16 g_wcat_h[1024 * D_DIM];
__device__ __align__(16) __nv_bfloat16 g_wcat_l[1024 * D_DIM];
__device__ float g_xp[1536 * 1024];
__device__ __align__(16) __nv_bfloat16 g_hbh[2][B_Q * H_DIM];
__device__ __align__(16) __nv_bfloat16 g_hbl[2][B_Q * H_DIM];
__device__ float g_hf[B_Q * H_DIM];

// ---------------- helpers ----------------
__device__ __forceinline__ uint32_t smem_u32(const void* p) {
    uint32_t a;
    asm("{ .reg .u64 t; cvta.to.shared.u64 t, %1; cvt.u32.u64 %0, t; }" : "=r"(a) : "l"(p));
    return a;
}
#define CPA16(s, g)  asm volatile("cp.async.cg.shared.global [%0], [%1], 16;" :: "r"(s), "l"(g) : "memory")
#define CPA_COMMIT() asm volatile("cp.async.commit_group;" ::: "memory")
#define CPA_WAIT0()  asm volatile("cp.async.wait_group 0;" ::: "memory")
#define CPA_WAIT1()  asm volatile("cp.async.wait_group 1;" ::: "memory")

__device__ __forceinline__ void ldsm4(uint32_t* r, uint32_t addr) {
    asm volatile("ldmatrix.sync.aligned.m8n8.x4.shared.b16 {%0,%1,%2,%3}, [%4];"
        : "=r"(r[0]), "=r"(r[1]), "=r"(r[2]), "=r"(r[3]) : "r"(addr));
}
__device__ __forceinline__ void mma16816(float* d, const uint32_t* a, uint32_t b0, uint32_t b1) {
    asm volatile("mma.sync.aligned.m16n8k16.row.col.f32.bf16.bf16.f32 "
        "{%0,%1,%2,%3}, {%4,%5,%6,%7}, {%8,%9}, {%0,%1,%2,%3};"
        : "+f"(d[0]), "+f"(d[1]), "+f"(d[2]), "+f"(d[3])
        : "r"(a[0]), "r"(a[1]), "r"(a[2]), "r"(a[3]), "r"(b0), "r"(b1));
}
__device__ __forceinline__ void splt2(float x, float y, uint32_t& hw, uint32_t& lw) {
    __nv_bfloat16 hx = __float2bfloat16(x), hy = __float2bfloat16(y);
    __nv_bfloat16 lx = __float2bfloat16(x - __bfloat162float(hx));
    __nv_bfloat16 ly = __float2bfloat16(y - __bfloat162float(hy));
    __nv_bfloat162 hp = __halves2bfloat162(hx, hy);
    __nv_bfloat162 lp = __halves2bfloat162(lx, ly);
    hw = *(uint32_t*)&hp; lw = *(uint32_t*)&lp;
}

__device__ __forceinline__ bool better(float v, int i, float w, int j) {
    return (v > w) || (v == w && i < j);
}
__device__ __forceinline__ void ins5(float v, int i, float tv[TOPK], int ti[TOPK]) {
    if (!better(v, i, tv[TOPK - 1], ti[TOPK - 1])) return;
#pragma unroll
    for (int r = 0; r < TOPK; r++) {
        if (better(v, i, tv[r], ti[r])) {
            float fv = tv[r]; int fi = ti[r];
            tv[r] = v; ti[r] = i;
            v = fv; i = fi;
        }
    }
}

// ---------------- kernel A0: center ----------------
__global__ void k_center(const float* __restrict__ sw) {
    __shared__ float sx[256], sy[256];
    int tid = threadIdx.x;
    float x = 0.f, y = 0.f;
    for (int i = tid; i < H_DIM; i += 256) { x += sw[2 * i]; y += sw[2 * i + 1]; }
    sx[tid] = x; sy[tid] = y;
    __syncthreads();
    for (int o = 128; o > 0; o >>= 1) {
        if (tid < o) { sx[tid] += sx[tid + o]; sy[tid] += sy[tid + o]; }
        __syncthreads();
    }
    if (tid == 0) {
        g_center[0] = sx[0] / (float)H_DIM;
        g_center[1] = sy[0] / (float)H_DIM;
    }
}

// ---------------- kernel A1: activations ----------------
__global__ void k_act(const float* __restrict__ coords) {
    int i = blockIdx.x * blockDim.x + threadIdx.x;
    if (i < M_MEM) {
        float dx = coords[2 * i]     - g_center[0];
        float dy = coords[2 * i + 1] - g_center[1];
        g_act[i] = 1.0f / (1.0f + sqrtf(dx * dx + dy * dy));
    }
}

// ---------------- kernel A2: memory split -> bf16 hi/lo + row norms ----------------
__global__ __launch_bounds__(128) void k_msplit(const float* __restrict__ mem) {
    __shared__ float red[128];
    const int row = blockIdx.x, tid = threadIdx.x;
    float nsq = 0.f;
    if (tid < 96) {
        float4 v = ((const float4*)(mem + (size_t)row * D_DIM))[tid];
        nsq = v.x * v.x + v.y * v.y + v.z * v.z + v.w * v.w;
        uint32_t h0, l0, h1, l1;
        splt2(v.x, v.y, h0, l0);
        splt2(v.z, v.w, h1, l1);
        size_t o = (size_t)row * D_DIM + tid * 4;
        *(uint2*)(g_mhi + o) = make_uint2(h0, h1);
        *(uint2*)(g_mlo + o) = make_uint2(l0, l1);
    }
    red[tid] = nsq;
    __syncthreads();
    for (int o = 64; o > 0; o >>= 1) {
        if (tid < o) red[tid] += red[tid + o];
        __syncthreads();
    }
    if (tid == 0) g_rn[row] = 1.0f / fmaxf(sqrtf(red[0]), 1e-8f);
}

// ---------------- kernel A3: normalize queries -> bf16 hi/lo ----------------
__global__ void k_qnorm(const float* __restrict__ q) {
    __shared__ float red[128];
    int b = blockIdx.x, tid = threadIdx.x;
    float s = 0.f;
    for (int d = tid; d < D_DIM; d += 128) {
        float v = q[(size_t)b * D_DIM + d];
        s += v * v;
    }
    red[tid] = s;
    __syncthreads();
    for (int o = 64; o > 0; o >>= 1) {
        if (tid < o) red[tid] += red[tid + o];
        __syncthreads();
    }
    float r = 1.0f / fmaxf(sqrtf(red[0]), 1e-8f);
    for (int d = tid; d < D_DIM; d += 128) {
        float qn = q[(size_t)b * D_DIM + d] * r;
        __nv_bfloat16 h = __float2bfloat16(qn);
        g_qhi[(size_t)b * D_DIM + d] = h;
        g_qlo[(size_t)b * D_DIM + d] = __float2bfloat16(qn - __bfloat162float(h));
    }
}

// ---------------- kernel A4: weight split prep ----------------
__global__ void k_prep(const float* __restrict__ Whh, const float* __restrict__ Wih,
                       const float* __restrict__ gW) {
    int i = blockIdx.x * blockDim.x + threadIdx.x;
    if (i < H_DIM * H_DIM) {
        float v = Whh[i];
        __nv_bfloat16 h = __float2bfloat16(v);
        g_whh_h[i] = h;
        g_whh_l[i] = __float2bfloat16(v - __bfloat162float(h));
    } else if (i < H_DIM * H_DIM + 1024 * D_DIM) {
        int j = i - H_DIM * H_DIM;
        int row = j / D_DIM, col = j % D_DIM;
        float v = (row < 512) ? Wih[row * D_DIM + col] : gW[(row - 512) * D_DIM + col];
        __nv_bfloat16 h = __float2bfloat16(v);
        g_wcat_h[j] = h;
        g_wcat_l[j] = __float2bfloat16(v - __bfloat162float(h));
    }
}

// ---------------- kernel B: pure-pipeline mma sims + fused top-5 ----------------
// chunk K=64 bf16, PADB=144 per row. Stage: Ahi|Alo|Bhi|Blo.
#define S_AHI 0
#define S_ALO 18432
#define S_BHI 36864
#define S_BLO 73728
#define STG_SZ 110592
#define HDR   4096
#define SIMS_SMEM (HDR + 2 * STG_SZ)   // 225280
// epilogue reuse:
#define E_STG HDR
#define E_PV  (HDR + 135168)
#define E_PI  (E_PV + 10240)

__device__ __forceinline__ void load_chunk(uint32_t st, int c, int m0, int tid) {
#pragma unroll
    for (int i = 0; i < 2; i++) {
        int idx = i * 512 + tid;
        int row = idx >> 3, s = idx & 7;
        int gr = m0 + row; if (gr >= M_MEM) gr = M_MEM - 1;
        size_t go = (size_t)gr * D_DIM + c * 64 + s * 8;
        uint32_t d = st + (uint32_t)(row * 144 + s * 16);
        CPA16(d + S_AHI, (const void*)(g_mhi + go));
        CPA16(d + S_ALO, (const void*)(g_mlo + go));
    }
#pragma unroll
    for (int i = 0; i < 4; i++) {
        int idx = i * 512 + tid;
        int row = idx >> 3, s = idx & 7;
        size_t go = (size_t)row * D_DIM + c * 64 + s * 8;
        uint32_t d = st + (uint32_t)(row * 144 + s * 16);
        CPA16(d + S_BHI, (const void*)(g_qhi + go));
        CPA16(d + S_BLO, (const void*)(g_qlo + go));
    }
    CPA_COMMIT();
}

__global__ __launch_bounds__(512, 1) void k_sims_mma(const float* __restrict__ mem) {
    extern __shared__ char smem[];
    const uint32_t sb = smem_u32(smem);
    float* s_rn  = (float*)smem;
    float* s_act = (float*)(smem + 512);

    const int tid = threadIdx.x;
    const int l   = tid & 31;
    const int w   = tid >> 5;
    const int wm  = w & 3;
    const int wn  = w >> 2;        // 0..3, 64 cols each
    const int m0  = blockIdx.x * TM;

    if (tid < 128) {
        bool ok = (m0 + tid) < M_MEM;
        s_rn[tid]  = ok ? g_rn[m0 + tid] : 0.0f;
        s_act[tid] = ok ? g_act[m0 + tid] : -1e30f;
    }

    float acc[2][8][4];
#pragma unroll
    for (int a = 0; a < 2; a++)
#pragma unroll
        for (int p = 0; p < 8; p++)
#pragma unroll
            for (int r = 0; r < 4; r++) acc[a][p][r] = 0.f;

    const uint32_t aoff = (uint32_t)((wm * 32 + (l & 15)) * 144 + (l >> 4) * 16);
    const uint32_t boff = (uint32_t)((wn * 64 + (l & 15)) * 144 + (l >> 4) * 16);

    // depth-2 prologue
    load_chunk(sb + HDR, 0, m0, tid);
    load_chunk(sb + HDR + STG_SZ, 1, m0, tid);

#pragma unroll 1
    for (int c = 0; c < 6; c++) {
        const uint32_t st = sb + HDR + (c & 1) * STG_SZ;
        if (c == 5) CPA_WAIT0(); else CPA_WAIT1();
        __syncthreads();

        const uint32_t aB = st + S_AHI + aoff;
        const uint32_t bB = st + S_BHI + boff;
#pragma unroll
        for (int kk = 0; kk < 4; kk++) {
            uint32_t bh[16], bl[16];
#pragma unroll
            for (int pp = 0; pp < 4; pp++) {
                uint32_t ba = bB + (uint32_t)(pp * 16 * 144 + kk * 32);
                ldsm4(bh + pp * 4, ba);
                ldsm4(bl + pp * 4, ba + (S_BLO - S_BHI));
            }
#pragma unroll
            for (int a = 0; a < 2; a++) {
                uint32_t ah4[4], al4[4];
                uint32_t aa = aB + (uint32_t)(a * 16 * 144 + kk * 32);
                ldsm4(ah4, aa);
                ldsm4(al4, aa + (S_ALO - S_AHI));
#pragma unroll
                for (int p = 0; p < 8; p++) {
                    int pp = p >> 1, hi = p & 1;
                    uint32_t b0h = bh[pp * 4 + hi], b1h = bh[pp * 4 + hi + 2];
                    uint32_t b0l = bl[pp * 4 + hi], b1l = bl[pp * 4 + hi + 2];
                    mma16816(acc[a][p], ah4, b0h, b1h);
                    mma16816(acc[a][p], ah4, b0l, b1l);
                    mma16816(acc[a][p], al4, b0h, b1h);
                }
            }
        }

        if (c < 4) {
            __syncthreads();
            load_chunk(st, c + 2, m0, tid);
        }
    }
    __syncthreads();

    // ---- epilogue: scale + bias, stage query-major, fused top-5 ----
    float* stg = (float*)(smem + E_STG);
#pragma unroll
    for (int a = 0; a < 2; a++) {
        int mA = wm * 32 + a * 16 + (l >> 2);
        float rnA = s_rn[mA],     acA = s_act[mA];
        float rnB = s_rn[mA + 8], acB = s_act[mA + 8];
#pragma unroll
        for (int p = 0; p < 8; p++) {
            int q = wn * 64 + p * 8 + (l & 3) * 2;
            stg[q * 132 + mA]           = acc[a][p][0] * rnA + acA;
            stg[(q + 1) * 132 + mA]     = acc[a][p][1] * rnA + acA;
            stg[q * 132 + mA + 8]       = acc[a][p][2] * rnB + acB;
            stg[(q + 1) * 132 + mA + 8] = acc[a][p][3] * rnB + acB;
        }
    }
    __syncthreads();

    {
        float* pv = (float*)(smem + E_PV);
        int*   pi = (int*)(smem + E_PI);
        int q = tid >> 1, h = tid & 1;
        float tv[TOPK]; int ti[TOPK];
#pragma unroll
        for (int r = 0; r < TOPK; r++) { tv[r] = -3.4e38f; ti[r] = 0x7fffffff; }
        const float4* col = (const float4*)(stg + q * 132 + h * 64);
#pragma unroll 4
        for (int i = 0; i < 16; i++) {
            float4 v = col[i];
            int mb = m0 + h * 64 + i * 4;
            ins5(v.x, mb,     tv, ti);
            ins5(v.y, mb + 1, tv, ti);
            ins5(v.z, mb + 2, tv, ti);
            ins5(v.w, mb + 3, tv, ti);
        }
#pragma unroll
        for (int r = 0; r < TOPK; r++) { pv[tid * TOPK + r] = tv[r]; pi[tid * TOPK + r] = ti[r]; }
        __syncthreads();

        if (tid < 256) {
            float fv[TOPK]; int fi[TOPK];
#pragma unroll
            for (int r = 0; r < TOPK; r++) {
                fv[r] = pv[(2 * tid) * TOPK + r];
                fi[r] = pi[(2 * tid) * TOPK + r];
            }
#pragma unroll
            for (int r = 0; r < TOPK; r++)
                ins5(pv[(2 * tid + 1) * TOPK + r], pi[(2 * tid + 1) * TOPK + r], fv, fi);
            size_t base = ((size_t)blockIdx.x * B_Q + tid) * TOPK;
#pragma unroll
            for (int r = 0; r < TOPK; r++) {
                g_cand_val[base + r] = fv[r];
                g_cand_idx[base + r] = fi[r];
            }
        }
    }
}

// ---------------- kernel C: merge ----------------
__device__ __forceinline__ void merge5(float* av, int* ai, const float* bv, const int* bi) {
    float ov[TOPK]; int oi[TOPK];
    int ia = 0, ib = 0;
#pragma unroll
    for (int r = 0; r < TOPK; r++) {
        bool ta = (ib >= TOPK) || (ia < TOPK && better(av[ia], ai[ia], bv[ib], bi[ib]));
        if (ta) { ov[r] = av[ia]; oi[r] = ai[ia]; ia++; }
        else    { ov[r] = bv[ib]; oi[r] = bi[ib]; ib++; }
    }
#pragma unroll
    for (int r = 0; r < TOPK; r++) { av[r] = ov[r]; ai[r] = oi[r]; }
}

__global__ void k_merge() {
    const int q = blockIdx.x, tid = threadIdx.x;
    float tv[TOPK]; int ti[TOPK];
#pragma unroll
    for (int r = 0; r < TOPK; r++) { tv[r] = -3.4e38f; ti[r] = 0x7fffffff; }
    for (int s = tid; s < NSLAB; s += 256) {
        size_t base = ((size_t)s * B_Q + q) * TOPK;
#pragma unroll
        for (int r = 0; r < TOPK; r++)
            ins5(g_cand_val[base + r], g_cand_idx[base + r], tv, ti);
    }
    __shared__ float sv[256][TOPK];
    __shared__ int   si[256][TOPK];
#pragma unroll
    for (int r = 0; r < TOPK; r++) { sv[tid][r] = tv[r]; si[tid][r] = ti[r]; }
    __syncthreads();
    for (int o = 128; o > 0; o >>= 1) {
        if (tid < o) merge5(sv[tid], si[tid], sv[tid + o], si[tid + o]);
        __syncthreads();
    }
    if (tid == 0) {
#pragma unroll
        for (int r = 0; r < TOPK; r++)
            g_topk[q * TOPK + r] = si[0][r];
    }
}

// ---------------- kernel D1: x_proj + gate GEMM [1536 x 1024 x 384] ----------------
#define XP_AHI 0
#define XP_ALO 34816
#define XP_BHI 69632
#define XP_BLO 104448
#define XP_SMEM 139264

__global__ __launch_bounds__(256, 1) void k_xproj(
    const float* __restrict__ query, const float* __restrict__ mem,
    const float* __restrict__ bih, const float* __restrict__ gb)
{
    extern __shared__ char smem[];
    const uint32_t sb = smem_u32(smem);
    const int tid = threadIdx.x, l = tid & 31, w = tid >> 5;
    const int wm = w & 3, wn = w >> 2;   // wn 0..1
    const int bm = blockIdx.x, bn = blockIdx.y;

    const int lrow = tid >> 1, kh = tid & 1;
    int r = bm * 128 + lrow;
    int t = r >> 8, q = r & 255;
    const float* aptr;
    if (t == 0) aptr = query + (size_t)q * D_DIM;
    else        aptr = mem + (size_t)g_topk[q * TOPK + t - 1] * D_DIM;
    aptr += kh * 64;

    float acc[2][8][4];
#pragma unroll
    for (int a = 0; a < 2; a++)
#pragma unroll
        for (int p = 0; p < 8; p++)
#pragma unroll
            for (int rr = 0; rr < 4; rr++) acc[a][p][rr] = 0.f;

#pragma unroll 1
    for (int c = 0; c < 3; c++) {
        __syncthreads();
#pragma unroll
        for (int i = 0; i < 8; i++) {
            int idx = i * 256 + tid;
            int row = idx >> 4, s = idx & 15;
            uint32_t d = sb + (uint32_t)(row * 272 + s * 16);
            size_t go = (size_t)(bn * 128 + row) * D_DIM + c * 128 + s * 8;
            CPA16(d + XP_BHI, (const void*)(g_wcat_h + go));
            CPA16(d + XP_BLO, (const void*)(g_wcat_l + go));
        }
        CPA_COMMIT();
        {
            char* ah = smem + XP_AHI;
            char* al = smem + XP_ALO;
            const float4* src = (const float4*)(aptr + c * 128);
#pragma unroll
            for (int i = 0; i < 16; i++) {
                float4 v = src[i];
                uint32_t h0, l0, h1, l1;
                splt2(v.x, v.y, h0, l0);
                splt2(v.z, v.w, h1, l1);
                uint32_t so = (uint32_t)(lrow * 272 + kh * 128 + i * 8);
                *(uint2*)(ah + so) = make_uint2(h0, h1);
                *(uint2*)(al + so) = make_uint2(l0, l1);
            }
        }
        CPA_WAIT0();
        __syncthreads();

        const uint32_t aB = sb + XP_AHI + (uint32_t)((wm * 32 + (l & 15)) * 272 + (l >> 4) * 16);
        const uint32_t bB = sb + XP_BHI + (uint32_t)((wn * 64 + (l & 15)) * 272 + (l >> 4) * 16);
#pragma unroll 1
        for (int kk = 0; kk < 8; kk++) {
            uint32_t bh[16], bl[16];
#pragma unroll
            for (int pp = 0; pp < 4; pp++) {
                uint32_t ba = bB + (uint32_t)(pp * 16 * 272 + kk * 32);
                ldsm4(bh + pp * 4, ba);
                ldsm4(bl + pp * 4, ba + (XP_BLO - XP_BHI));
            }
#pragma unroll
            for (int a = 0; a < 2; a++) {
                uint32_t ah4[4], al4[4];
                uint32_t aa = aB + (uint32_t)(a * 16 * 272 + kk * 32);
                ldsm4(ah4, aa);
                ldsm4(al4, aa + (XP_ALO - XP_AHI));
#pragma unroll
                for (int p = 0; p < 8; p++) {
                    int pp = p >> 1, hi = p & 1;
                    mma16816(acc[a][p], ah4, bh[pp * 4 + hi], bh[pp * 4 + hi + 2]);
                    mma16816(acc[a][p], ah4, bl[pp * 4 + hi], bl[pp * 4 + hi + 2]);
                    mma16816(acc[a][p], al4, bh[pp * 4 + hi], bh[pp * 4 + hi + 2]);
                }
            }
        }
    }

#pragma unroll
    for (int a = 0; a < 2; a++) {
        int rA = bm * 128 + wm * 32 + a * 16 + (l >> 2);
#pragma unroll
        for (int p = 0; p < 8; p++) {
            int cg = bn * 128 + wn * 64 + p * 8 + (l & 3) * 2;
            float b0 = (cg < 512) ? bih[cg] : gb[cg - 512];
            float b1 = (cg < 512) ? bih[cg + 1] : gb[cg + 1 - 512];
            g_xp[(size_t)rA * 1024 + cg]           = acc[a][p][0] + b0;
            g_xp[(size_t)rA * 1024 + cg + 1]       = acc[a][p][1] + b1;
            g_xp[(size_t)(rA + 8) * 1024 + cg]     = acc[a][p][2] + b0;
            g_xp[(size_t)(rA + 8) * 1024 + cg + 1] = acc[a][p][3] + b1;
        }
    }
}

// ---------------- kernel D2: h0 = tanh(xp[0] + bhh) ----------------
__global__ void k_h0(const float* __restrict__ bhh) {
    int i = blockIdx.x * blockDim.x + threadIdx.x;
    int q = i >> 9, h = i & 511;
    float v = tanhf(g_xp[(size_t)q * 1024 + h] + bhh[h]);
    __nv_bfloat16 hi = __float2bfloat16(v);
    g_hbh[0][i] = hi;
    g_hbl[0][i] = __float2bfloat16(v - __bfloat162float(hi));
    g_hf[i] = v;
}

// ---------------- kernel D3: recurrence step GEMM ----------------
#define ST_AHI 0
#define ST_ALO 17408
#define ST_BHI 34816
#define ST_BLO 69632
#define ST_SMEM 104448

__global__ __launch_bounds__(256, 1) void k_step(int t, const float* __restrict__ bhh) {
    extern __shared__ char smem[];
    const uint32_t sb = smem_u32(smem);
    const int tid = threadIdx.x, l = tid & 31, w = tid >> 5;
    const int wm = w & 3, wn = w >> 2;
    const int mt = blockIdx.x, nt = blockIdx.y;
    const int bin = (t + 1) & 1, bout = t & 1;
    const __nv_bfloat16* Ah = g_hbh[bin];
    const __nv_bfloat16* Al = g_hbl[bin];

    float acc[8][4];
#pragma unroll
    for (int p = 0; p < 8; p++)
#pragma unroll
        for (int rr = 0; rr < 4; rr++) acc[p][rr] = 0.f;

#pragma unroll 1
    for (int c = 0; c < 4; c++) {
        __syncthreads();
#pragma unroll
        for (int i = 0; i < 4; i++) {
            int idx = i * 256 + tid;
            int row = idx >> 4, s = idx & 15;
            uint32_t d = sb + (uint32_t)(row * 272 + s * 16);
            size_t go = (size_t)(mt * 64 + row) * H_DIM + c * 128 + s * 8;
            CPA16(d + ST_AHI, (const void*)(Ah + go));
            CPA16(d + ST_ALO, (const void*)(Al + go));
        }
#pragma unroll
        for (int i = 0; i < 8; i++) {
            int idx = i * 256 + tid;
            int row = idx >> 4, s = idx & 15;
            uint32_t d = sb + ST_BHI + (uint32_t)(row * 272 + s * 16);
            size_t go = (size_t)(nt * 128 + row) * H_DIM + c * 128 + s * 8;
            CPA16(d, (const void*)(g_whh_h + go));
            CPA16(d + (ST_BLO - ST_BHI), (const void*)(g_whh_l + go));
        }
        CPA_COMMIT();
        CPA_WAIT0();
        __syncthreads();

        const uint32_t aB = sb + ST_AHI + (uint32_t)((wm * 16 + (l & 15)) * 272 + (l >> 4) * 16);
        const uint32_t bB = sb + ST_BHI + (uint32_t)((wn * 64 + (l & 15)) * 272 + (l >> 4) * 16);
#pragma unroll 1
        for (int kk = 0; kk < 8; kk++) {
            uint32_t bh[16], bl[16];
#pragma unroll
            for (int pp = 0; pp < 4; pp++) {
                uint32_t ba = bB + (uint32_t)(pp * 16 * 272 + kk * 32);
                ldsm4(bh + pp * 4, ba);
                ldsm4(bl + pp * 4, ba + (ST_BLO - ST_BHI));
            }
            uint32_t ah4[4], al4[4];
            ldsm4(ah4, aB + (uint32_t)(kk * 32));
            ldsm4(al4, aB + (uint32_t)(kk * 32) + (ST_ALO - ST_AHI));
#pragma unroll
            for (int p = 0; p < 8; p++) {
                int pp = p >> 1, hi = p & 1;
                mma16816(acc[p], ah4, bh[pp * 4 + hi], bh[pp * 4 + hi + 2]);
                mma16816(acc[p], ah4, bl[pp * 4 + hi], bl[pp * 4 + hi + 2]);
                mma16816(acc[p], al4, bh[pp * 4 + hi], bh[pp * 4 + hi + 2]);
            }
        }
    }

    int q0 = mt * 64 + wm * 16 + (l >> 2);
#pragma unroll
    for (int p = 0; p < 8; p++) {
        int h = nt * 128 + wn * 64 + p * 8 + (l & 3) * 2;
#pragma unroll
        for (int rr = 0; rr < 4; rr++) {
            int qq = q0 + ((rr >> 1) ? 8 : 0);
            int hh = h + (rr & 1);
            float v = acc[p][rr] + g_xp[(size_t)(t * 256 + qq) * 1024 + hh] + bhh[hh];
            float ht = tanhf(v);
            size_t o = (size_t)qq * H_DIM + hh;
            g_hf[o] = ht;
            __nv_bfloat16 hb = __float2bfloat16(ht);
            g_hbh[bout][o] = hb;
            g_hbl[bout][o] = __float2bfloat16(ht - __bfloat162float(hb));
        }
    }
}

// ---------------- kernel D4: output gate mix ----------------
__global__ void k_out(float* __restrict__ out) {
    int i = blockIdx.x * blockDim.x + threadIdx.x;
    int q = i >> 9, h = i & 511;
    float gpre = g_xp[(size_t)q * 1024 + 512 + h];
    float g = 1.0f / (1.0f + expf(-gpre));
    float proj = g_xp[(size_t)q * 1024 + h];
    out[i] = g * g_hf[i] + (1.0f - g) * proj;
}

// ---------------- launch ----------------
extern "C" void kernel_launch(void* const* d_in, const int* in_sizes, int n_in,
                              void* d_out, int out_size) {
    const float* query  = (const float*)d_in[0];
    const float* mem    = (const float*)d_in[1];
    const float* coords = (const float*)d_in[2];
    const float* sw     = (const float*)d_in[3];
    const float* Wih    = (const float*)d_in[4];
    const float* bih    = (const float*)d_in[5];
    const float* Whh    = (const float*)d_in[6];
    const float* bhh    = (const float*)d_in[7];
    const float* gW     = (const float*)d_in[8];
    const float* gb     = (const float*)d_in[9];
    float* out = (float*)d_out;

    cudaFuncSetAttribute(k_sims_mma, cudaFuncAttributeMaxDynamicSharedMemorySize, SIMS_SMEM);
    cudaFuncSetAttribute(k_xproj,    cudaFuncAttributeMaxDynamicSharedMemorySize, XP_SMEM);
    cudaFuncSetAttribute(k_step,     cudaFuncAttributeMaxDynamicSharedMemorySize, ST_SMEM);

    k_center<<<1, 256>>>(sw);
    k_act<<<(M_MEM + 255) / 256, 256>>>(coords);
    k_msplit<<<M_MEM, 128>>>(mem);
    k_qnorm<<<B_Q, 128>>>(query);
    k_prep<<<(H_DIM * H_DIM + 1024 * D_DIM + 255) / 256, 256>>>(Whh, Wih, gW);
    k_sims_mma<<<NSLAB, 512, SIMS_SMEM>>>(mem);
    k_merge<<<B_Q, 256>>>();
    k_xproj<<<dim3(12, 8), 256, XP_SMEM>>>(query, mem, bih, gb);
    k_h0<<<(B_Q * H_DIM) / 256, 256>>>(bhh);
    for (int t = 1; t <= TOPK; t++)
        k_step<<<dim3(4, 4), 256, ST_SMEM>>>(t, bhh);
    k_out<<<(B_Q * H_DIM) / 256, 256>>>(out);
}

// round 7
// speedup vs baseline: 1.0279x; 1.0279x over previous
#include <cuda_runtime.h>
#include <cuda_bf16.h>
#include <math.h>
#include <stdint.h>

// Problem constants
#define B_Q   256
#define M_MEM 200000
#define D_DIM 384
#define H_DIM 512
#define TOPK  5
#define TM    128
#define NSLAB ((M_MEM + TM - 1) / TM)   // 1563

// ---------------- device scratch ----------------
__device__ float g_center[2];
__device__ float g_act[M_MEM];
__device__ __align__(16) __nv_bfloat16 g_qhi[B_Q * D_DIM];
__device__ __align__(16) __nv_bfloat16 g_qlo[B_Q * D_DIM];
__device__ float g_cand_val[(size_t)NSLAB * B_Q * TOPK];
__device__ int   g_cand_idx[(size_t)NSLAB * B_Q * TOPK];
__device__ int   g_topk[B_Q * TOPK];
// RNN path scratch
__device__ __align__(16) __nv_bfloat16 g_whh_h[H_DIM * H_DIM];
__device__ __align__(16) __nv_bfloat16 g_whh_l[H_DIM * H_DIM];
__device__ __align__(16) __nv_bfloat16 g_wcat_h[1024 * D_DIM];
__device__ __align__(16) __nv_bfloat16 g_wcat_l[1024 * D_DIM];
__device__ float g_xp[1536 * 1024];
__device__ __align__(16) __nv_bfloat16 g_hbh[2][B_Q * H_DIM];
__device__ __align__(16) __nv_bfloat16 g_hbl[2][B_Q * H_DIM];
__device__ float g_hf[B_Q * H_DIM];

// ---------------- helpers ----------------
__device__ __forceinline__ uint32_t smem_u32(const void* p) {
    uint32_t a;
    asm("{ .reg .u64 t; cvta.to.shared.u64 t, %1; cvt.u32.u64 %0, t; }" : "=r"(a) : "l"(p));
    return a;
}
#define CPA16(s, g)  asm volatile("cp.async.cg.shared.global [%0], [%1], 16;" :: "r"(s), "l"(g) : "memory")
#define CPA_COMMIT() asm volatile("cp.async.commit_group;" ::: "memory")
#define CPA_WAIT0()  asm volatile("cp.async.wait_group 0;" ::: "memory")
#define CPA_WAIT1()  asm volatile("cp.async.wait_group 1;" ::: "memory")

__device__ __forceinline__ void ldsm4(uint32_t* r, uint32_t addr) {
    asm volatile("ldmatrix.sync.aligned.m8n8.x4.shared.b16 {%0,%1,%2,%3}, [%4];"
        : "=r"(r[0]), "=r"(r[1]), "=r"(r[2]), "=r"(r[3]) : "r"(addr));
}
__device__ __forceinline__ void mma16816(float* d, const uint32_t* a, uint32_t b0, uint32_t b1) {
    asm volatile("mma.sync.aligned.m16n8k16.row.col.f32.bf16.bf16.f32 "
        "{%0,%1,%2,%3}, {%4,%5,%6,%7}, {%8,%9}, {%0,%1,%2,%3};"
        : "+f"(d[0]), "+f"(d[1]), "+f"(d[2]), "+f"(d[3])
        : "r"(a[0]), "r"(a[1]), "r"(a[2]), "r"(a[3]), "r"(b0), "r"(b1));
}
__device__ __forceinline__ void splt2(float x, float y, uint32_t& hw, uint32_t& lw) {
    __nv_bfloat16 hx = __float2bfloat16(x), hy = __float2bfloat16(y);
    __nv_bfloat16 lx = __float2bfloat16(x - __bfloat162float(hx));
    __nv_bfloat16 ly = __float2bfloat16(y - __bfloat162float(hy));
    __nv_bfloat162 hp = __halves2bfloat162(hx, hy);
    __nv_bfloat162 lp = __halves2bfloat162(lx, ly);
    hw = *(uint32_t*)&hp; lw = *(uint32_t*)&lp;
}

__device__ __forceinline__ bool better(float v, int i, float w, int j) {
    return (v > w) || (v == w && i < j);
}
__device__ __forceinline__ void ins5(float v, int i, float tv[TOPK], int ti[TOPK]) {
    if (!better(v, i, tv[TOPK - 1], ti[TOPK - 1])) return;
#pragma unroll
    for (int r = 0; r < TOPK; r++) {
        if (better(v, i, tv[r], ti[r])) {
            float fv = tv[r]; int fi = ti[r];
            tv[r] = v; ti[r] = i;
            v = fv; i = fi;
        }
    }
}

// ---------------- kernel A0: center ----------------
__global__ void k_center(const float* __restrict__ sw) {
    __shared__ float sx[256], sy[256];
    int tid = threadIdx.x;
    float x = 0.f, y = 0.f;
    for (int i = tid; i < H_DIM; i += 256) { x += sw[2 * i]; y += sw[2 * i + 1]; }
    sx[tid] = x; sy[tid] = y;
    __syncthreads();
    for (int o = 128; o > 0; o >>= 1) {
        if (tid < o) { sx[tid] += sx[tid + o]; sy[tid] += sy[tid + o]; }
        __syncthreads();
    }
    if (tid == 0) {
        g_center[0] = sx[0] / (float)H_DIM;
        g_center[1] = sy[0] / (float)H_DIM;
    }
}

// ---------------- kernel A1: activations ----------------
__global__ void k_act(const float* __restrict__ coords) {
    int i = blockIdx.x * blockDim.x + threadIdx.x;
    if (i < M_MEM) {
        float dx = coords[2 * i]     - g_center[0];
        float dy = coords[2 * i + 1] - g_center[1];
        g_act[i] = 1.0f / (1.0f + sqrtf(dx * dx + dy * dy));
    }
}

// ---------------- kernel A2: normalize queries -> bf16 hi/lo ----------------
__global__ void k_qnorm(const float* __restrict__ q) {
    __shared__ float red[128];
    int b = blockIdx.x, tid = threadIdx.x;
    float s = 0.f;
    for (int d = tid; d < D_DIM; d += 128) {
        float v = q[(size_t)b * D_DIM + d];
        s += v * v;
    }
    red[tid] = s;
    __syncthreads();
    for (int o = 64; o > 0; o >>= 1) {
        if (tid < o) red[tid] += red[tid + o];
        __syncthreads();
    }
    float r = 1.0f / fmaxf(sqrtf(red[0]), 1e-8f);
    for (int d = tid; d < D_DIM; d += 128) {
        float qn = q[(size_t)b * D_DIM + d] * r;
        __nv_bfloat16 h = __float2bfloat16(qn);
        g_qhi[(size_t)b * D_DIM + d] = h;
        g_qlo[(size_t)b * D_DIM + d] = __float2bfloat16(qn - __bfloat162float(h));
    }
}

// ---------------- kernel A3: weight split prep ----------------
__global__ void k_prep(const float* __restrict__ Whh, const float* __restrict__ Wih,
                       const float* __restrict__ gW) {
    int i = blockIdx.x * blockDim.x + threadIdx.x;
    if (i < H_DIM * H_DIM) {
        float v = Whh[i];
        __nv_bfloat16 h = __float2bfloat16(v);
        g_whh_h[i] = h;
        g_whh_l[i] = __float2bfloat16(v - __bfloat162float(h));
    } else if (i < H_DIM * H_DIM + 1024 * D_DIM) {
        int j = i - H_DIM * H_DIM;
        int row = j / D_DIM, col = j % D_DIM;
        float v = (row < 512) ? Wih[row * D_DIM + col] : gW[(row - 512) * D_DIM + col];
        __nv_bfloat16 h = __float2bfloat16(v);
        g_wcat_h[j] = h;
        g_wcat_l[j] = __float2bfloat16(v - __bfloat162float(h));
    }
}

// ---------------- kernel B: 8-warp 64x64-tile mma sims + fused norms + top-5 ----------------
// chunk K=64 bf16, PADB=144 bytes per row. Stage: Ahi|Alo|Bhi|Blo.
#define S_AHI 0
#define S_ALO 18432
#define S_BHI 36864
#define S_BLO 73728
#define STG_SZ 110592
#define HDR   4096
#define SIMS_SMEM (HDR + 2 * STG_SZ)   // 225280
// epilogue reuse:
#define E_STG HDR
#define E_PV  (HDR + 135168)
#define E_PI  (E_PV + 10240)

__global__ __launch_bounds__(256, 1) void k_sims_mma(const float* __restrict__ mem) {
    extern __shared__ char smem[];
    const uint32_t sb = smem_u32(smem);
    float* s_rn  = (float*)smem;
    float* s_act = (float*)(smem + 512);
    float* s_red = (float*)(smem + 1024);

    const int tid = threadIdx.x;
    const int l   = tid & 31;
    const int w   = tid >> 5;       // 0..7
    const int wm  = w & 1;          // M half: rows wm*64..+64
    const int wn  = w >> 1;         // N quarter: cols wn*64..+64
    const int m0  = blockIdx.x * TM;

    if (tid < 128) {
        bool ok = (m0 + tid) < M_MEM;
        s_act[tid] = ok ? g_act[m0 + tid] : -1e30f;
    }

    float acc[4][8][4];
#pragma unroll
    for (int a = 0; a < 4; a++)
#pragma unroll
        for (int p = 0; p < 8; p++)
#pragma unroll
            for (int r = 0; r < 4; r++) acc[a][p][r] = 0.f;

    // A source: 2 threads per memory row, each half = 32 floats (8 float4)
    const int arow = tid >> 1, akh = tid & 1;
    int arg = m0 + arow; if (arg >= M_MEM) arg = M_MEM - 1;
    const float4* asrc = (const float4*)(mem + (size_t)arg * D_DIM + akh * 32);
    const uint32_t asts = (uint32_t)(arow * 144 + akh * 64);

    const uint32_t aoff = (uint32_t)((wm * 64 + (l & 15)) * 144 + (l >> 4) * 16);
    const uint32_t boff = (uint32_t)((wn * 64 + (l & 15)) * 144 + (l >> 4) * 16);

    float nsq = 0.f;
    float4 pf[8];

    // B loads for chunk cc into stage st
#define LOAD_B(st, cc) do {                                                   \
    _Pragma("unroll")                                                         \
    for (int i = 0; i < 8; i++) {                                             \
        int idx = i * 256 + tid;                                              \
        int row = idx >> 3, s = idx & 7;                                      \
        size_t go = (size_t)row * D_DIM + (cc) * 64 + s * 8;                  \
        uint32_t d = (st) + (uint32_t)(row * 144 + s * 16);                   \
        CPA16(d + S_BHI, (const void*)(g_qhi + go));                          \
        CPA16(d + S_BLO, (const void*)(g_qlo + go));                          \
    }                                                                         \
    CPA_COMMIT();                                                             \
} while (0)

// convert pf -> STS into stage base pointer sc (char*), accumulate nsq
#define STORE_A(sc) do {                                                      \
    _Pragma("unroll")                                                         \
    for (int i = 0; i < 4; i++) {                                             \
        float4 v0 = pf[2 * i], v1 = pf[2 * i + 1];                            \
        nsq += v0.x * v0.x + v0.y * v0.y + v0.z * v0.z + v0.w * v0.w          \
             + v1.x * v1.x + v1.y * v1.y + v1.z * v1.z + v1.w * v1.w;         \
        uint32_t h0, l0, h1, l1, h2, l2, h3, l3;                              \
        splt2(v0.x, v0.y, h0, l0); splt2(v0.z, v0.w, h1, l1);                 \
        splt2(v1.x, v1.y, h2, l2); splt2(v1.z, v1.w, h3, l3);                 \
        *(uint4*)((sc) + S_AHI + asts + i * 16) = make_uint4(h0, h1, h2, h3); \
        *(uint4*)((sc) + S_ALO + asts + i * 16) = make_uint4(l0, l1, l2, l3); \
    }                                                                         \
} while (0)

    // ---- prologue: chunks 0 and 1 ----
    LOAD_B(sb + HDR, 0);
    LOAD_B(sb + HDR + STG_SZ, 1);
#pragma unroll
    for (int i = 0; i < 8; i++) pf[i] = asrc[i];
    STORE_A(smem + HDR);
#pragma unroll
    for (int i = 0; i < 8; i++) pf[i] = asrc[16 + i];
    STORE_A(smem + HDR + STG_SZ);

#pragma unroll 1
    for (int c = 0; c < 6; c++) {
        const uint32_t st = sb + HDR + (c & 1) * STG_SZ;
        if (c == 5) CPA_WAIT0(); else CPA_WAIT1();
        __syncthreads();

        // prefetch A chunk c+2 into registers (hidden under GEMM below)
        if (c < 4) {
#pragma unroll
            for (int i = 0; i < 8; i++) pf[i] = asrc[(c + 2) * 16 + i];
        }

        // GEMM: 4 k16 steps, warp tile 64x64
        const uint32_t aB = st + S_AHI + aoff;
        const uint32_t bB = st + S_BHI + boff;
#pragma unroll
        for (int kk = 0; kk < 4; kk++) {
            uint32_t bh[16], bl[16];
#pragma unroll
            for (int pp = 0; pp < 4; pp++) {
                uint32_t ba = bB + (uint32_t)(pp * 16 * 144 + kk * 32);
                ldsm4(bh + pp * 4, ba);
                ldsm4(bl + pp * 4, ba + (S_BLO - S_BHI));
            }
#pragma unroll
            for (int a = 0; a < 4; a++) {
                uint32_t ah4[4], al4[4];
                uint32_t aa = aB + (uint32_t)(a * 16 * 144 + kk * 32);
                ldsm4(ah4, aa);
                ldsm4(al4, aa + (S_ALO - S_AHI));
#pragma unroll
                for (int p = 0; p < 8; p++) {
                    int pp = p >> 1, hi = p & 1;
                    uint32_t b0h = bh[pp * 4 + hi], b1h = bh[pp * 4 + hi + 2];
                    uint32_t b0l = bl[pp * 4 + hi], b1l = bl[pp * 4 + hi + 2];
                    mma16816(acc[a][p], ah4, b0h, b1h);
                    mma16816(acc[a][p], ah4, b0l, b1l);
                    mma16816(acc[a][p], al4, b0h, b1h);
                }
            }
        }

        if (c < 4) {
            __syncthreads();   // all warps done reading this stage
            STORE_A(smem + HDR + (c & 1) * STG_SZ);
            LOAD_B(st, c + 2);
        }
    }

    // ---- norms reduce ----
    __syncthreads();
    s_red[tid] = nsq;
    __syncthreads();
    if (tid < 128) {
        float s = s_red[2 * tid] + s_red[2 * tid + 1];
        bool ok = (m0 + tid) < M_MEM;
        s_rn[tid] = ok ? 1.0f / fmaxf(sqrtf(s), 1e-8f) : 0.0f;
    }
    __syncthreads();

    // ---- epilogue: scale + bias, stage query-major, fused top-5 ----
    float* stg = (float*)(smem + E_STG);
#pragma unroll
    for (int a = 0; a < 4; a++) {
        int mA = wm * 64 + a * 16 + (l >> 2);
        float rnA = s_rn[mA],     acA = s_act[mA];
        float rnB = s_rn[mA + 8], acB = s_act[mA + 8];
#pragma unroll
        for (int p = 0; p < 8; p++) {
            int q = wn * 64 + p * 8 + (l & 3) * 2;
            stg[q * 132 + mA]           = acc[a][p][0] * rnA + acA;
            stg[(q + 1) * 132 + mA]     = acc[a][p][1] * rnA + acA;
            stg[q * 132 + mA + 8]       = acc[a][p][2] * rnB + acB;
            stg[(q + 1) * 132 + mA + 8] = acc[a][p][3] * rnB + acB;
        }
    }
    __syncthreads();

    // one query per thread, full 128-row scan
    {
        float tv[TOPK]; int ti[TOPK];
#pragma unroll
        for (int r = 0; r < TOPK; r++) { tv[r] = -3.4e38f; ti[r] = 0x7fffffff; }
        const float4* col = (const float4*)(stg + tid * 132);
#pragma unroll 4
        for (int i = 0; i < 32; i++) {
            float4 v = col[i];
            int mb = m0 + i * 4;
            ins5(v.x, mb,     tv, ti);
            ins5(v.y, mb + 1, tv, ti);
            ins5(v.z, mb + 2, tv, ti);
            ins5(v.w, mb + 3, tv, ti);
        }
        size_t base = ((size_t)blockIdx.x * B_Q + tid) * TOPK;
#pragma unroll
        for (int r = 0; r < TOPK; r++) {
            g_cand_val[base + r] = tv[r];
            g_cand_idx[base + r] = ti[r];
        }
    }
#undef LOAD_B
#undef STORE_A
}

// ---------------- kernel C: merge ----------------
__device__ __forceinline__ void merge5(float* av, int* ai, const float* bv, const int* bi) {
    float ov[TOPK]; int oi[TOPK];
    int ia = 0, ib = 0;
#pragma unroll
    for (int r = 0; r < TOPK; r++) {
        bool ta = (ib >= TOPK) || (ia < TOPK && better(av[ia], ai[ia], bv[ib], bi[ib]));
        if (ta) { ov[r] = av[ia]; oi[r] = ai[ia]; ia++; }
        else    { ov[r] = bv[ib]; oi[r] = bi[ib]; ib++; }
    }
#pragma unroll
    for (int r = 0; r < TOPK; r++) { av[r] = ov[r]; ai[r] = oi[r]; }
}

__global__ void k_merge() {
    const int q = blockIdx.x, tid = threadIdx.x;
    float tv[TOPK]; int ti[TOPK];
#pragma unroll
    for (int r = 0; r < TOPK; r++) { tv[r] = -3.4e38f; ti[r] = 0x7fffffff; }
    for (int s = tid; s < NSLAB; s += 256) {
        size_t base = ((size_t)s * B_Q + q) * TOPK;
#pragma unroll
        for (int r = 0; r < TOPK; r++)
            ins5(g_cand_val[base + r], g_cand_idx[base + r], tv, ti);
    }
    __shared__ float sv[256][TOPK];
    __shared__ int   si[256][TOPK];
#pragma unroll
    for (int r = 0; r < TOPK; r++) { sv[tid][r] = tv[r]; si[tid][r] = ti[r]; }
    __syncthreads();
    for (int o = 128; o > 0; o >>= 1) {
        if (tid < o) merge5(sv[tid], si[tid], sv[tid + o], si[tid + o]);
        __syncthreads();
    }
    if (tid == 0) {
#pragma unroll
        for (int r = 0; r < TOPK; r++)
            g_topk[q * TOPK + r] = si[0][r];
    }
}

// ---------------- kernel D1: x_proj + gate GEMM [1536 x 1024 x 384] ----------------
#define XP_AHI 0
#define XP_ALO 34816
#define XP_BHI 69632
#define XP_BLO 104448
#define XP_SMEM 139264

__global__ __launch_bounds__(256, 1) void k_xproj(
    const float* __restrict__ query, const float* __restrict__ mem,
    const float* __restrict__ bih, const float* __restrict__ gb)
{
    extern __shared__ char smem[];
    const uint32_t sb = smem_u32(smem);
    const int tid = threadIdx.x, l = tid & 31, w = tid >> 5;
    const int wm = w & 3, wn = w >> 2;   // wn 0..1
    const int bm = blockIdx.x, bn = blockIdx.y;

    const int lrow = tid >> 1, kh = tid & 1;
    int r = bm * 128 + lrow;
    int t = r >> 8, q = r & 255;
    const float* aptr;
    if (t == 0) aptr = query + (size_t)q * D_DIM;
    else        aptr = mem + (size_t)g_topk[q * TOPK + t - 1] * D_DIM;
    aptr += kh * 64;

    float acc[2][8][4];
#pragma unroll
    for (int a = 0; a < 2; a++)
#pragma unroll
        for (int p = 0; p < 8; p++)
#pragma unroll
            for (int rr = 0; rr < 4; rr++) acc[a][p][rr] = 0.f;

#pragma unroll 1
    for (int c = 0; c < 3; c++) {
        __syncthreads();
#pragma unroll
        for (int i = 0; i < 8; i++) {
            int idx = i * 256 + tid;
            int row = idx >> 4, s = idx & 15;
            uint32_t d = sb + (uint32_t)(row * 272 + s * 16);
            size_t go = (size_t)(bn * 128 + row) * D_DIM + c * 128 + s * 8;
            CPA16(d + XP_BHI, (const void*)(g_wcat_h + go));
            CPA16(d + XP_BLO, (const void*)(g_wcat_l + go));
        }
        CPA_COMMIT();
        {
            char* ah = smem + XP_AHI;
            char* al = smem + XP_ALO;
            const float4* src = (const float4*)(aptr + c * 128);
#pragma unroll
            for (int i = 0; i < 16; i++) {
                float4 v = src[i];
                uint32_t h0, l0, h1, l1;
                splt2(v.x, v.y, h0, l0);
                splt2(v.z, v.w, h1, l1);
                uint32_t so = (uint32_t)(lrow * 272 + kh * 128 + i * 8);
                *(uint2*)(ah + so) = make_uint2(h0, h1);
                *(uint2*)(al + so) = make_uint2(l0, l1);
            }
        }
        CPA_WAIT0();
        __syncthreads();

        const uint32_t aB = sb + XP_AHI + (uint32_t)((wm * 32 + (l & 15)) * 272 + (l >> 4) * 16);
        const uint32_t bB = sb + XP_BHI + (uint32_t)((wn * 64 + (l & 15)) * 272 + (l >> 4) * 16);
#pragma unroll 1
        for (int kk = 0; kk < 8; kk++) {
            uint32_t bh[16], bl[16];
#pragma unroll
            for (int pp = 0; pp < 4; pp++) {
                uint32_t ba = bB + (uint32_t)(pp * 16 * 272 + kk * 32);
                ldsm4(bh + pp * 4, ba);
                ldsm4(bl + pp * 4, ba + (XP_BLO - XP_BHI));
            }
#pragma unroll
            for (int a = 0; a < 2; a++) {
                uint32_t ah4[4], al4[4];
                uint32_t aa = aB + (uint32_t)(a * 16 * 272 + kk * 32);
                ldsm4(ah4, aa);
                ldsm4(al4, aa + (XP_ALO - XP_AHI));
#pragma unroll
                for (int p = 0; p < 8; p++) {
                    int pp = p >> 1, hi = p & 1;
                    mma16816(acc[a][p], ah4, bh[pp * 4 + hi], bh[pp * 4 + hi + 2]);
                    mma16816(acc[a][p], ah4, bl[pp * 4 + hi], bl[pp * 4 + hi + 2]);
                    mma16816(acc[a][p], al4, bh[pp * 4 + hi], bh[pp * 4 + hi + 2]);
                }
            }
        }
    }

#pragma unroll
    for (int a = 0; a < 2; a++) {
        int rA = bm * 128 + wm * 32 + a * 16 + (l >> 2);
#pragma unroll
        for (int p = 0; p < 8; p++) {
            int cg = bn * 128 + wn * 64 + p * 8 + (l & 3) * 2;
            float b0 = (cg < 512) ? bih[cg] : gb[cg - 512];
            float b1 = (cg < 512) ? bih[cg + 1] : gb[cg + 1 - 512];
            g_xp[(size_t)rA * 1024 + cg]           = acc[a][p][0] + b0;
            g_xp[(size_t)rA * 1024 + cg + 1]       = acc[a][p][1] + b1;
            g_xp[(size_t)(rA + 8) * 1024 + cg]     = acc[a][p][2] + b0;
            g_xp[(size_t)(rA + 8) * 1024 + cg + 1] = acc[a][p][3] + b1;
        }
    }
}

// ---------------- kernel D2: h0 = tanh(xp[0] + bhh) ----------------
__global__ void k_h0(const float* __restrict__ bhh) {
    int i = blockIdx.x * blockDim.x + threadIdx.x;
    int q = i >> 9, h = i & 511;
    float v = tanhf(g_xp[(size_t)q * 1024 + h] + bhh[h]);
    __nv_bfloat16 hi = __float2bfloat16(v);
    g_hbh[0][i] = hi;
    g_hbl[0][i] = __float2bfloat16(v - __bfloat162float(hi));
    g_hf[i] = v;
}

// ---------------- kernel D3: recurrence step GEMM ----------------
#define ST_AHI 0
#define ST_ALO 17408
#define ST_BHI 34816
#define ST_BLO 69632
#define ST_SMEM 104448

__global__ __launch_bounds__(256, 1) void k_step(int t, const float* __restrict__ bhh) {
    extern __shared__ char smem[];
    const uint32_t sb = smem_u32(smem);
    const int tid = threadIdx.x, l = tid & 31, w = tid >> 5;
    const int wm = w & 3, wn = w >> 2;
    const int mt = blockIdx.x, nt = blockIdx.y;
    const int bin = (t + 1) & 1, bout = t & 1;
    const __nv_bfloat16* Ah = g_hbh[bin];
    const __nv_bfloat16* Al = g_hbl[bin];

    float acc[8][4];
#pragma unroll
    for (int p = 0; p < 8; p++)
#pragma unroll
        for (int rr = 0; rr < 4; rr++) acc[p][rr] = 0.f;

#pragma unroll 1
    for (int c = 0; c < 4; c++) {
        __syncthreads();
#pragma unroll
        for (int i = 0; i < 4; i++) {
            int idx = i * 256 + tid;
            int row = idx >> 4, s = idx & 15;
            uint32_t d = sb + (uint32_t)(row * 272 + s * 16);
            size_t go = (size_t)(mt * 64 + row) * H_DIM + c * 128 + s * 8;
            CPA16(d + ST_AHI, (const void*)(Ah + go));
            CPA16(d + ST_ALO, (const void*)(Al + go));
        }
#pragma unroll
        for (int i = 0; i < 8; i++) {
            int idx = i * 256 + tid;
            int row = idx >> 4, s = idx & 15;
            uint32_t d = sb + ST_BHI + (uint32_t)(row * 272 + s * 16);
            size_t go = (size_t)(nt * 128 + row) * H_DIM + c * 128 + s * 8;
            CPA16(d, (const void*)(g_whh_h + go));
            CPA16(d + (ST_BLO - ST_BHI), (const void*)(g_whh_l + go));
        }
        CPA_COMMIT();
        CPA_WAIT0();
        __syncthreads();

        const uint32_t aB = sb + ST_AHI + (uint32_t)((wm * 16 + (l & 15)) * 272 + (l >> 4) * 16);
        const uint32_t bB = sb + ST_BHI + (uint32_t)((wn * 64 + (l & 15)) * 272 + (l >> 4) * 16);
#pragma unroll 1
        for (int kk = 0; kk < 8; kk++) {
            uint32_t bh[16], bl[16];
#pragma unroll
            for (int pp = 0; pp < 4; pp++) {
                uint32_t ba = bB + (uint32_t)(pp * 16 * 272 + kk * 32);
                ldsm4(bh + pp * 4, ba);
                ldsm4(bl + pp * 4, ba + (ST_BLO - ST_BHI));
            }
            uint32_t ah4[4], al4[4];
            ldsm4(ah4, aB + (uint32_t)(kk * 32));
            ldsm4(al4, aB + (uint32_t)(kk * 32) + (ST_ALO - ST_AHI));
#pragma unroll
            for (int p = 0; p < 8; p++) {
                int pp = p >> 1, hi = p & 1;
                mma16816(acc[p], ah4, bh[pp * 4 + hi], bh[pp * 4 + hi + 2]);
                mma16816(acc[p], ah4, bl[pp * 4 + hi], bl[pp * 4 + hi + 2]);
                mma16816(acc[p], al4, bh[pp * 4 + hi], bh[pp * 4 + hi + 2]);
            }
        }
    }

    int q0 = mt * 64 + wm * 16 + (l >> 2);
#pragma unroll
    for (int p = 0; p < 8; p++) {
        int h = nt * 128 + wn * 64 + p * 8 + (l & 3) * 2;
#pragma unroll
        for (int rr = 0; rr < 4; rr++) {
            int qq = q0 + ((rr >> 1) ? 8 : 0);
            int hh = h + (rr & 1);
            float v = acc[p][rr] + g_xp[(size_t)(t * 256 + qq) * 1024 + hh] + bhh[hh];
            float ht = tanhf(v);
            size_t o = (size_t)qq * H_DIM + hh;
            g_hf[o] = ht;
            __nv_bfloat16 hb = __float2bfloat16(ht);
            g_hbh[bout][o] = hb;
            g_hbl[bout][o] = __float2bfloat16(ht - __bfloat162float(hb));
        }
    }
}

// ---------------- kernel D4: output gate mix ----------------
__global__ void k_out(float* __restrict__ out) {
    int i = blockIdx.x * blockDim.x + threadIdx.x;
    int q = i >> 9, h = i & 511;
    float gpre = g_xp[(size_t)q * 1024 + 512 + h];
    float g = 1.0f / (1.0f + expf(-gpre));
    float proj = g_xp[(size_t)q * 1024 + h];
    out[i] = g * g_hf[i] + (1.0f - g) * proj;
}

// ---------------- launch ----------------
extern "C" void kernel_launch(void* const* d_in, const int* in_sizes, int n_in,
                              void* d_out, int out_size) {
    const float* query  = (const float*)d_in[0];
    const float* mem    = (const float*)d_in[1];
    const float* coords = (const float*)d_in[2];
    const float* sw     = (const float*)d_in[3];
    const float* Wih    = (const float*)d_in[4];
    const float* bih    = (const float*)d_in[5];
    const float* Whh    = (const float*)d_in[6];
    const float* bhh    = (const float*)d_in[7];
    const float* gW     = (const float*)d_in[8];
    const float* gb     = (const float*)d_in[9];
    float* out = (float*)d_out;

    cudaFuncSetAttribute(k_sims_mma, cudaFuncAttributeMaxDynamicSharedMemorySize, SIMS_SMEM);
    cudaFuncSetAttribute(k_xproj,    cudaFuncAttributeMaxDynamicSharedMemorySize, XP_SMEM);
    cudaFuncSetAttribute(k_step,     cudaFuncAttributeMaxDynamicSharedMemorySize, ST_SMEM);

    k_center<<<1, 256>>>(sw);
    k_act<<<(M_MEM + 255) / 256, 256>>>(coords);
    k_qnorm<<<B_Q, 128>>>(query);
    k_prep<<<(H_DIM * H_DIM + 1024 * D_DIM + 255) / 256, 256>>>(Whh, Wih, gW);
    k_sims_mma<<<NSLAB, 256, SIMS_SMEM>>>(mem);
    k_merge<<<B_Q, 256>>>();
    k_xproj<<<dim3(12, 8), 256, XP_SMEM>>>(query, mem, bih, gb);
    k_h0<<<(B_Q * H_DIM) / 256, 256>>>(bhh);
    for (int t = 1; t <= TOPK; t++)
        k_step<<<dim3(4, 4), 256, ST_SMEM>>>(t, bhh);
    k_out<<<(B_Q * H_DIM) / 256, 256>>>(out);
}

// round 8
// speedup vs baseline: 1.3112x; 1.2756x over previous
#include <cuda_runtime.h>
#include <cuda_bf16.h>
#include <math.h>
#include <stdint.h>

// Problem constants
#define B_Q   256
#define M_MEM 200000
#define D_DIM 384
#define H_DIM 512
#define TOPK  5
#define KC    16
#define TM    128
#define NSLAB ((M_MEM + TM - 1) / TM)   // 1563

// ---------------- device scratch ----------------
__device__ float g_center[2];
__device__ float g_act[M_MEM];
__device__ __align__(16) __nv_bfloat16 g_qhi[B_Q * D_DIM];
__device__ float g_cand_val[(size_t)NSLAB * B_Q * TOPK];
__device__ int   g_cand_idx[(size_t)NSLAB * B_Q * TOPK];
__device__ int   g_cand16[B_Q * KC];
__device__ int   g_topk[B_Q * TOPK];
// RNN path scratch
__device__ __align__(16) __nv_bfloat16 g_whh_h[H_DIM * H_DIM];
__device__ __align__(16) __nv_bfloat16 g_whh_l[H_DIM * H_DIM];
__device__ __align__(16) __nv_bfloat16 g_wcat_h[1024 * D_DIM];
__device__ __align__(16) __nv_bfloat16 g_wcat_l[1024 * D_DIM];
__device__ float g_xp[1536 * 1024];
__device__ __align__(16) __nv_bfloat16 g_hbh[2][B_Q * H_DIM];
__device__ __align__(16) __nv_bfloat16 g_hbl[2][B_Q * H_DIM];
__device__ float g_hf[B_Q * H_DIM];

// ---------------- helpers ----------------
__device__ __forceinline__ uint32_t smem_u32(const void* p) {
    uint32_t a;
    asm("{ .reg .u64 t; cvta.to.shared.u64 t, %1; cvt.u32.u64 %0, t; }" : "=r"(a) : "l"(p));
    return a;
}
#define CPA16(s, g)  asm volatile("cp.async.cg.shared.global [%0], [%1], 16;" :: "r"(s), "l"(g) : "memory")
#define CPA_COMMIT() asm volatile("cp.async.commit_group;" ::: "memory")
#define CPA_WAIT0()  asm volatile("cp.async.wait_group 0;" ::: "memory")
#define CPA_WAIT1()  asm volatile("cp.async.wait_group 1;" ::: "memory")

__device__ __forceinline__ void ldsm4(uint32_t* r, uint32_t addr) {
    asm volatile("ldmatrix.sync.aligned.m8n8.x4.shared.b16 {%0,%1,%2,%3}, [%4];"
        : "=r"(r[0]), "=r"(r[1]), "=r"(r[2]), "=r"(r[3]) : "r"(addr));
}
__device__ __forceinline__ void mma16816(float* d, const uint32_t* a, uint32_t b0, uint32_t b1) {
    asm volatile("mma.sync.aligned.m16n8k16.row.col.f32.bf16.bf16.f32 "
        "{%0,%1,%2,%3}, {%4,%5,%6,%7}, {%8,%9}, {%0,%1,%2,%3};"
        : "+f"(d[0]), "+f"(d[1]), "+f"(d[2]), "+f"(d[3])
        : "r"(a[0]), "r"(a[1]), "r"(a[2]), "r"(a[3]), "r"(b0), "r"(b1));
}
__device__ __forceinline__ void splt2(float x, float y, uint32_t& hw, uint32_t& lw) {
    __nv_bfloat16 hx = __float2bfloat16(x), hy = __float2bfloat16(y);
    __nv_bfloat16 lx = __float2bfloat16(x - __bfloat162float(hx));
    __nv_bfloat16 ly = __float2bfloat16(y - __bfloat162float(hy));
    __nv_bfloat162 hp = __halves2bfloat162(hx, hy);
    __nv_bfloat162 lp = __halves2bfloat162(lx, ly);
    hw = *(uint32_t*)&hp; lw = *(uint32_t*)&lp;
}
__device__ __forceinline__ uint32_t pk2hi(float x, float y) {
    __nv_bfloat162 hp = __halves2bfloat162(__float2bfloat16(x), __float2bfloat16(y));
    return *(uint32_t*)&hp;
}

__device__ __forceinline__ bool better(float v, int i, float w, int j) {
    return (v > w) || (v == w && i < j);
}
template <int K>
__device__ __forceinline__ void insK(float v, int i, float* tv, int* ti) {
    if (!better(v, i, tv[K - 1], ti[K - 1])) return;
#pragma unroll
    for (int r = 0; r < K; r++) {
        if (better(v, i, tv[r], ti[r])) {
            float fv = tv[r]; int fi = ti[r];
            tv[r] = v; ti[r] = i;
            v = fv; i = fi;
        }
    }
}
#define ins5 insK<TOPK>

// ---------------- kernel A0: center ----------------
__global__ void k_center(const float* __restrict__ sw) {
    __shared__ float sx[256], sy[256];
    int tid = threadIdx.x;
    float x = 0.f, y = 0.f;
    for (int i = tid; i < H_DIM; i += 256) { x += sw[2 * i]; y += sw[2 * i + 1]; }
    sx[tid] = x; sy[tid] = y;
    __syncthreads();
    for (int o = 128; o > 0; o >>= 1) {
        if (tid < o) { sx[tid] += sx[tid + o]; sy[tid] += sy[tid + o]; }
        __syncthreads();
    }
    if (tid == 0) {
        g_center[0] = sx[0] / (float)H_DIM;
        g_center[1] = sy[0] / (float)H_DIM;
    }
}

// ---------------- kernel A1: activations ----------------
__global__ void k_act(const float* __restrict__ coords) {
    int i = blockIdx.x * blockDim.x + threadIdx.x;
    if (i < M_MEM) {
        float dx = coords[2 * i]     - g_center[0];
        float dy = coords[2 * i + 1] - g_center[1];
        g_act[i] = 1.0f / (1.0f + sqrtf(dx * dx + dy * dy));
    }
}

// ---------------- kernel A2: normalize queries -> bf16 hi ----------------
__global__ void k_qnorm(const float* __restrict__ q) {
    __shared__ float red[128];
    int b = blockIdx.x, tid = threadIdx.x;
    float s = 0.f;
    for (int d = tid; d < D_DIM; d += 128) {
        float v = q[(size_t)b * D_DIM + d];
        s += v * v;
    }
    red[tid] = s;
    __syncthreads();
    for (int o = 64; o > 0; o >>= 1) {
        if (tid < o) red[tid] += red[tid + o];
        __syncthreads();
    }
    float r = 1.0f / fmaxf(sqrtf(red[0]), 1e-8f);
    for (int d = tid; d < D_DIM; d += 128)
        g_qhi[(size_t)b * D_DIM + d] = __float2bfloat16(q[(size_t)b * D_DIM + d] * r);
}

// ---------------- kernel A3: weight split prep ----------------
__global__ void k_prep(const float* __restrict__ Whh, const float* __restrict__ Wih,
                       const float* __restrict__ gW) {
    int i = blockIdx.x * blockDim.x + threadIdx.x;
    if (i < H_DIM * H_DIM) {
        float v = Whh[i];
        __nv_bfloat16 h = __float2bfloat16(v);
        g_whh_h[i] = h;
        g_whh_l[i] = __float2bfloat16(v - __bfloat162float(h));
    } else if (i < H_DIM * H_DIM + 1024 * D_DIM) {
        int j = i - H_DIM * H_DIM;
        int row = j / D_DIM, col = j % D_DIM;
        float v = (row < 512) ? Wih[row * D_DIM + col] : gW[(row - 512) * D_DIM + col];
        __nv_bfloat16 h = __float2bfloat16(v);
        g_wcat_h[j] = h;
        g_wcat_l[j] = __float2bfloat16(v - __bfloat162float(h));
    }
}

// ---------------- kernel B: 1-term coarse sims, 128x128 tile, 2 CTAs/SM ----------------
// chunk K=64 bf16, PADB=144. Stage: Ahi | Bhi (18432 each).
#define S_BHI  18432
#define STG_SZ 36864
#define HDR    2048
#define SIMS_SMEM (HDR + 2 * STG_SZ)   // 75776
#define E_STG  HDR                      // 128 x 132 f32 = 67584

__global__ __launch_bounds__(256, 2) void k_sims_mma(const float* __restrict__ mem) {
    extern __shared__ char smem[];
    const uint32_t sb = smem_u32(smem);
    float* s_rn  = (float*)smem;
    float* s_act = (float*)(smem + 512);
    float* s_red = (float*)(smem + 1024);

    const int tid = threadIdx.x;
    const int l   = tid & 31;
    const int w   = tid >> 5;       // 0..7
    const int wm  = w & 1;          // rows wm*64..+64
    const int wn  = w >> 1;         // queries wn*32..+32
    const int m0  = blockIdx.y * TM;
    const int q0  = blockIdx.x * 128;

    if (tid < 128) {
        bool ok = (m0 + tid) < M_MEM;
        s_act[tid] = ok ? g_act[m0 + tid] : -1e30f;
    }

    float acc[4][4][4];
#pragma unroll
    for (int a = 0; a < 4; a++)
#pragma unroll
        for (int p = 0; p < 4; p++)
#pragma unroll
            for (int r = 0; r < 4; r++) acc[a][p][r] = 0.f;

    // A source: 2 threads per row, each half = 32 floats
    const int arow = tid >> 1, akh = tid & 1;
    int arg = m0 + arow; if (arg >= M_MEM) arg = M_MEM - 1;
    const float4* asrc = (const float4*)(mem + (size_t)arg * D_DIM + akh * 32);
    const uint32_t asts = (uint32_t)(arow * 144 + akh * 64);

    const uint32_t aoff = (uint32_t)((wm * 64 + (l & 15)) * 144 + (l >> 4) * 16);
    const uint32_t boff = S_BHI + (uint32_t)((wn * 32 + (l & 15)) * 144 + (l >> 4) * 16);

    float nsq = 0.f;
    float4 pf[8];

#define LOAD_B(st, cc) do {                                                   \
    _Pragma("unroll")                                                         \
    for (int i = 0; i < 4; i++) {                                             \
        int idx = i * 256 + tid;                                              \
        int row = idx >> 3, s = idx & 7;                                      \
        size_t go = (size_t)(q0 + row) * D_DIM + (cc) * 64 + s * 8;           \
        CPA16((st) + S_BHI + (uint32_t)(row * 144 + s * 16),                  \
              (const void*)(g_qhi + go));                                     \
    }                                                                         \
    CPA_COMMIT();                                                             \
} while (0)

#define STORE_A(sc) do {                                                      \
    _Pragma("unroll")                                                         \
    for (int i = 0; i < 4; i++) {                                             \
        float4 v0 = pf[2 * i], v1 = pf[2 * i + 1];                            \
        nsq += v0.x * v0.x + v0.y * v0.y + v0.z * v0.z + v0.w * v0.w          \
             + v1.x * v1.x + v1.y * v1.y + v1.z * v1.z + v1.w * v1.w;         \
        uint32_t h0 = pk2hi(v0.x, v0.y), h1 = pk2hi(v0.z, v0.w);              \
        uint32_t h2 = pk2hi(v1.x, v1.y), h3 = pk2hi(v1.z, v1.w);              \
        *(uint4*)((sc) + asts + i * 16) = make_uint4(h0, h1, h2, h3);         \
    }                                                                         \
} while (0)

    // ---- prologue: chunks 0, 1 ----
    LOAD_B(sb + HDR, 0);
    LOAD_B(sb + HDR + STG_SZ, 1);
#pragma unroll
    for (int i = 0; i < 8; i++) pf[i] = asrc[i];
    STORE_A(smem + HDR);
#pragma unroll
    for (int i = 0; i < 8; i++) pf[i] = asrc[16 + i];
    STORE_A(smem + HDR + STG_SZ);

#pragma unroll 1
    for (int c = 0; c < 6; c++) {
        const uint32_t st = sb + HDR + (c & 1) * STG_SZ;
        if (c == 5) CPA_WAIT0(); else CPA_WAIT1();
        __syncthreads();

        if (c < 4) {
#pragma unroll
            for (int i = 0; i < 8; i++) pf[i] = asrc[(c + 2) * 16 + i];
        }

        const uint32_t aB = st + aoff;
        const uint32_t bB = st + boff;
#pragma unroll
        for (int kk = 0; kk < 4; kk++) {
            uint32_t bh[8];
#pragma unroll
            for (int pp = 0; pp < 2; pp++)
                ldsm4(bh + pp * 4, bB + (uint32_t)(pp * 16 * 144 + kk * 32));
#pragma unroll
            for (int a = 0; a < 4; a++) {
                uint32_t ah4[4];
                ldsm4(ah4, aB + (uint32_t)(a * 16 * 144 + kk * 32));
#pragma unroll
                for (int p = 0; p < 4; p++) {
                    int pp = p >> 1, hi = p & 1;
                    mma16816(acc[a][p], ah4, bh[pp * 4 + hi], bh[pp * 4 + hi + 2]);
                }
            }
        }

        if (c < 4) {
            __syncthreads();
            STORE_A(smem + HDR + (c & 1) * STG_SZ);
            LOAD_B(st, c + 2);
        }
    }

    // ---- norms reduce ----
    __syncthreads();
    s_red[tid] = nsq;
    __syncthreads();
    if (tid < 128) {
        float s = s_red[2 * tid] + s_red[2 * tid + 1];
        bool ok = (m0 + tid) < M_MEM;
        s_rn[tid] = ok ? 1.0f / fmaxf(sqrtf(s), 1e-8f) : 0.0f;
    }
    __syncthreads();

    // ---- epilogue: scale + bias, stage query-major (128 queries) ----
    float* stg = (float*)(smem + E_STG);
#pragma unroll
    for (int a = 0; a < 4; a++) {
        int mA = wm * 64 + a * 16 + (l >> 2);
        float rnA = s_rn[mA],     acA = s_act[mA];
        float rnB = s_rn[mA + 8], acB = s_act[mA + 8];
#pragma unroll
        for (int p = 0; p < 4; p++) {
            int q = wn * 32 + p * 8 + (l & 3) * 2;
            stg[q * 132 + mA]           = acc[a][p][0] * rnA + acA;
            stg[(q + 1) * 132 + mA]     = acc[a][p][1] * rnA + acA;
            stg[q * 132 + mA + 8]       = acc[a][p][2] * rnB + acB;
            stg[(q + 1) * 132 + mA + 8] = acc[a][p][3] * rnB + acB;
        }
    }
    __syncthreads();

    // top-5: 2 threads per query, shuffle merge
    {
        int q = tid >> 1, h = tid & 1;
        float tv[TOPK]; int ti[TOPK];
#pragma unroll
        for (int r = 0; r < TOPK; r++) { tv[r] = -3.4e38f; ti[r] = 0x7fffffff; }
        const float4* col = (const float4*)(stg + q * 132 + h * 64);
#pragma unroll 4
        for (int i = 0; i < 16; i++) {
            float4 v = col[i];
            int mb = m0 + h * 64 + i * 4;
            ins5(v.x, mb,     tv, ti);
            ins5(v.y, mb + 1, tv, ti);
            ins5(v.z, mb + 2, tv, ti);
            ins5(v.w, mb + 3, tv, ti);
        }
        float ov[TOPK]; int oi[TOPK];
#pragma unroll
        for (int r = 0; r < TOPK; r++) {
            ov[r] = __shfl_down_sync(0xffffffff, tv[r], 1);
            oi[r] = __shfl_down_sync(0xffffffff, ti[r], 1);
        }
        if (h == 0) {
#pragma unroll
            for (int r = 0; r < TOPK; r++) ins5(ov[r], oi[r], tv, ti);
            size_t base = ((size_t)blockIdx.y * B_Q + q0 + q) * TOPK;
#pragma unroll
            for (int r = 0; r < TOPK; r++) {
                g_cand_val[base + r] = tv[r];
                g_cand_idx[base + r] = ti[r];
            }
        }
    }
#undef LOAD_B
#undef STORE_A
}

// ---------------- kernel C: merge -> coarse top-16 pool ----------------
template <int K>
__device__ __forceinline__ void mergeK(float* av, int* ai, const float* bv, const int* bi) {
    float ov[K]; int oi[K];
    int ia = 0, ib = 0;
#pragma unroll
    for (int r = 0; r < K; r++) {
        bool ta = (ib >= K) || (ia < K && better(av[ia], ai[ia], bv[ib], bi[ib]));
        if (ta) { ov[r] = av[ia]; oi[r] = ai[ia]; ia++; }
        else    { ov[r] = bv[ib]; oi[r] = bi[ib]; ib++; }
    }
#pragma unroll
    for (int r = 0; r < K; r++) { av[r] = ov[r]; ai[r] = oi[r]; }
}

__global__ void k_merge() {
    const int q = blockIdx.x, tid = threadIdx.x;
    float tv[KC]; int ti[KC];
#pragma unroll
    for (int r = 0; r < KC; r++) { tv[r] = -3.4e38f; ti[r] = 0x7fffffff; }
    for (int s = tid; s < NSLAB; s += 256) {
        size_t base = ((size_t)s * B_Q + q) * TOPK;
#pragma unroll
        for (int r = 0; r < TOPK; r++)
            insK<KC>(g_cand_val[base + r], g_cand_idx[base + r], tv, ti);
    }
    __shared__ float sv[256][KC];
    __shared__ int   si[256][KC];
#pragma unroll
    for (int r = 0; r < KC; r++) { sv[tid][r] = tv[r]; si[tid][r] = ti[r]; }
    __syncthreads();
    for (int o = 128; o > 0; o >>= 1) {
        if (tid < o) mergeK<KC>(sv[tid], si[tid], sv[tid + o], si[tid + o]);
        __syncthreads();
    }
    if (tid < KC) g_cand16[q * KC + tid] = si[0][tid];
}

// ---------------- kernel C2: exact fp32 refine of 16 candidates -> top-5 ----------------
__global__ __launch_bounds__(128) void k_refine(const float* __restrict__ query,
                                                const float* __restrict__ mem) {
    __shared__ float qv[D_DIM];
    __shared__ float s_part[4];
    __shared__ float sims[KC];
    const int q = blockIdx.x, tid = threadIdx.x;
    const int lane = tid & 31, wr = tid >> 5;

    for (int d = tid; d < D_DIM; d += 128) qv[d] = query[(size_t)q * D_DIM + d];
    float p = 0.f;
    for (int d = tid; d < D_DIM; d += 128) {
        float v = query[(size_t)q * D_DIM + d];
        p += v * v;
    }
#pragma unroll
    for (int o = 16; o > 0; o >>= 1) p += __shfl_xor_sync(0xffffffff, p, o);
    if (lane == 0) s_part[wr] = p;
    __syncthreads();
    float rq = 1.0f / fmaxf(sqrtf(s_part[0] + s_part[1] + s_part[2] + s_part[3]), 1e-8f);

    for (int c = wr; c < KC; c += 4) {
        int mi = g_cand16[q * KC + c];
        const float* mv = mem + (size_t)mi * D_DIM;
        float dot = 0.f, msq = 0.f;
        for (int d = lane; d < D_DIM; d += 32) {
            float m = mv[d];
            dot += qv[d] * m;
            msq += m * m;
        }
#pragma unroll
        for (int o = 16; o > 0; o >>= 1) {
            dot += __shfl_xor_sync(0xffffffff, dot, o);
            msq += __shfl_xor_sync(0xffffffff, msq, o);
        }
        if (lane == 0)
            sims[c] = dot * rq / fmaxf(sqrtf(msq), 1e-8f) + g_act[mi];
    }
    __syncthreads();

    if (tid == 0) {
        float tv[TOPK]; int ti[TOPK];
#pragma unroll
        for (int r = 0; r < TOPK; r++) { tv[r] = -3.4e38f; ti[r] = 0x7fffffff; }
        for (int c = 0; c < KC; c++)
            ins5(sims[c], g_cand16[q * KC + c], tv, ti);
#pragma unroll
        for (int r = 0; r < TOPK; r++)
            g_topk[q * TOPK + r] = ti[r];
    }
}

// ---------------- kernel D1: x_proj + gate GEMM [1536 x 1024 x 384] ----------------
#define XP_AHI 0
#define XP_ALO 34816
#define XP_BHI 69632
#define XP_BLO 104448
#define XP_SMEM 139264

__global__ __launch_bounds__(256, 1) void k_xproj(
    const float* __restrict__ query, const float* __restrict__ mem,
    const float* __restrict__ bih, const float* __restrict__ gb)
{
    extern __shared__ char smem[];
    const uint32_t sb = smem_u32(smem);
    const int tid = threadIdx.x, l = tid & 31, w = tid >> 5;
    const int wm = w & 3, wn = w >> 2;
    const int bm = blockIdx.x, bn = blockIdx.y;

    const int lrow = tid >> 1, kh = tid & 1;
    int r = bm * 128 + lrow;
    int t = r >> 8, q = r & 255;
    const float* aptr;
    if (t == 0) aptr = query + (size_t)q * D_DIM;
    else        aptr = mem + (size_t)g_topk[q * TOPK + t - 1] * D_DIM;
    aptr += kh * 64;

    float acc[2][8][4];
#pragma unroll
    for (int a = 0; a < 2; a++)
#pragma unroll
        for (int p = 0; p < 8; p++)
#pragma unroll
            for (int rr = 0; rr < 4; rr++) acc[a][p][rr] = 0.f;

#pragma unroll 1
    for (int c = 0; c < 3; c++) {
        __syncthreads();
#pragma unroll
        for (int i = 0; i < 8; i++) {
            int idx = i * 256 + tid;
            int row = idx >> 4, s = idx & 15;
            uint32_t d = sb + (uint32_t)(row * 272 + s * 16);
            size_t go = (size_t)(bn * 128 + row) * D_DIM + c * 128 + s * 8;
            CPA16(d + XP_BHI, (const void*)(g_wcat_h + go));
            CPA16(d + XP_BLO, (const void*)(g_wcat_l + go));
        }
        CPA_COMMIT();
        {
            char* ah = smem + XP_AHI;
            char* al = smem + XP_ALO;
            const float4* src = (const float4*)(aptr + c * 128);
#pragma unroll
            for (int i = 0; i < 16; i++) {
                float4 v = src[i];
                uint32_t h0, l0, h1, l1;
                splt2(v.x, v.y, h0, l0);
                splt2(v.z, v.w, h1, l1);
                uint32_t so = (uint32_t)(lrow * 272 + kh * 128 + i * 8);
                *(uint2*)(ah + so) = make_uint2(h0, h1);
                *(uint2*)(al + so) = make_uint2(l0, l1);
            }
        }
        CPA_WAIT0();
        __syncthreads();

        const uint32_t aB = sb + XP_AHI + (uint32_t)((wm * 32 + (l & 15)) * 272 + (l >> 4) * 16);
        const uint32_t bB = sb + XP_BHI + (uint32_t)((wn * 64 + (l & 15)) * 272 + (l >> 4) * 16);
#pragma unroll 1
        for (int kk = 0; kk < 8; kk++) {
            uint32_t bh[16], bl[16];
#pragma unroll
            for (int pp = 0; pp < 4; pp++) {
                uint32_t ba = bB + (uint32_t)(pp * 16 * 272 + kk * 32);
                ldsm4(bh + pp * 4, ba);
                ldsm4(bl + pp * 4, ba + (XP_BLO - XP_BHI));
            }
#pragma unroll
            for (int a = 0; a < 2; a++) {
                uint32_t ah4[4], al4[4];
                uint32_t aa = aB + (uint32_t)(a * 16 * 272 + kk * 32);
                ldsm4(ah4, aa);
                ldsm4(al4, aa + (XP_ALO - XP_AHI));
#pragma unroll
                for (int p = 0; p < 8; p++) {
                    int pp = p >> 1, hi = p & 1;
                    mma16816(acc[a][p], ah4, bh[pp * 4 + hi], bh[pp * 4 + hi + 2]);
                    mma16816(acc[a][p], ah4, bl[pp * 4 + hi], bl[pp * 4 + hi + 2]);
                    mma16816(acc[a][p], al4, bh[pp * 4 + hi], bh[pp * 4 + hi + 2]);
                }
            }
        }
    }

#pragma unroll
    for (int a = 0; a < 2; a++) {
        int rA = bm * 128 + wm * 32 + a * 16 + (l >> 2);
#pragma unroll
        for (int p = 0; p < 8; p++) {
            int cg = bn * 128 + wn * 64 + p * 8 + (l & 3) * 2;
            float b0 = (cg < 512) ? bih[cg] : gb[cg - 512];
            float b1 = (cg < 512) ? bih[cg + 1] : gb[cg + 1 - 512];
            g_xp[(size_t)rA * 1024 + cg]           = acc[a][p][0] + b0;
            g_xp[(size_t)rA * 1024 + cg + 1]       = acc[a][p][1] + b1;
            g_xp[(size_t)(rA + 8) * 1024 + cg]     = acc[a][p][2] + b0;
            g_xp[(size_t)(rA + 8) * 1024 + cg + 1] = acc[a][p][3] + b1;
        }
    }
}

// ---------------- kernel D2: h0 = tanh(xp[0] + bhh) ----------------
__global__ void k_h0(const float* __restrict__ bhh) {
    int i = blockIdx.x * blockDim.x + threadIdx.x;
    int q = i >> 9, h = i & 511;
    float v = tanhf(g_xp[(size_t)q * 1024 + h] + bhh[h]);
    __nv_bfloat16 hi = __float2bfloat16(v);
    g_hbh[0][i] = hi;
    g_hbl[0][i] = __float2bfloat16(v - __bfloat162float(hi));
    g_hf[i] = v;
}

// ---------------- kernel D3: recurrence step GEMM ----------------
#define ST_AHI 0
#define ST_ALO 17408
#define ST_BHI 34816
#define ST_BLO 69632
#define ST_SMEM 104448

__global__ __launch_bounds__(256, 1) void k_step(int t, const float* __restrict__ bhh) {
    extern __shared__ char smem[];
    const uint32_t sb = smem_u32(smem);
    const int tid = threadIdx.x, l = tid & 31, w = tid >> 5;
    const int wm = w & 3, wn = w >> 2;
    const int mt = blockIdx.x, nt = blockIdx.y;
    const int bin = (t + 1) & 1, bout = t & 1;
    const __nv_bfloat16* Ah = g_hbh[bin];
    const __nv_bfloat16* Al = g_hbl[bin];

    float acc[8][4];
#pragma unroll
    for (int p = 0; p < 8; p++)
#pragma unroll
        for (int rr = 0; rr < 4; rr++) acc[p][rr] = 0.f;

#pragma unroll 1
    for (int c = 0; c < 4; c++) {
        __syncthreads();
#pragma unroll
        for (int i = 0; i < 4; i++) {
            int idx = i * 256 + tid;
            int row = idx >> 4, s = idx & 15;
            uint32_t d = sb + (uint32_t)(row * 272 + s * 16);
            size_t go = (size_t)(mt * 64 + row) * H_DIM + c * 128 + s * 8;
            CPA16(d + ST_AHI, (const void*)(Ah + go));
            CPA16(d + ST_ALO, (const void*)(Al + go));
        }
#pragma unroll
        for (int i = 0; i < 8; i++) {
            int idx = i * 256 + tid;
            int row = idx >> 4, s = idx & 15;
            uint32_t d = sb + ST_BHI + (uint32_t)(row * 272 + s * 16);
            size_t go = (size_t)(nt * 128 + row) * H_DIM + c * 128 + s * 8;
            CPA16(d, (const void*)(g_whh_h + go));
            CPA16(d + (ST_BLO - ST_BHI), (const void*)(g_whh_l + go));
        }
        CPA_COMMIT();
        CPA_WAIT0();
        __syncthreads();

        const uint32_t aB = sb + ST_AHI + (uint32_t)((wm * 16 + (l & 15)) * 272 + (l >> 4) * 16);
        const uint32_t bB = sb + ST_BHI + (uint32_t)((wn * 64 + (l & 15)) * 272 + (l >> 4) * 16);
#pragma unroll 1
        for (int kk = 0; kk < 8; kk++) {
            uint32_t bh[16], bl[16];
#pragma unroll
            for (int pp = 0; pp < 4; pp++) {
                uint32_t ba = bB + (uint32_t)(pp * 16 * 272 + kk * 32);
                ldsm4(bh + pp * 4, ba);
                ldsm4(bl + pp * 4, ba + (ST_BLO - ST_BHI));
            }
            uint32_t ah4[4], al4[4];
            ldsm4(ah4, aB + (uint32_t)(kk * 32));
            ldsm4(al4, aB + (uint32_t)(kk * 32) + (ST_ALO - ST_AHI));
#pragma unroll
            for (int p = 0; p < 8; p++) {
                int pp = p >> 1, hi = p & 1;
                mma16816(acc[p], ah4, bh[pp * 4 + hi], bh[pp * 4 + hi + 2]);
                mma16816(acc[p], ah4, bl[pp * 4 + hi], bl[pp * 4 + hi + 2]);
                mma16816(acc[p], al4, bh[pp * 4 + hi], bh[pp * 4 + hi + 2]);
            }
        }
    }

    int q0 = mt * 64 + wm * 16 + (l >> 2);
#pragma unroll
    for (int p = 0; p < 8; p++) {
        int h = nt * 128 + wn * 64 + p * 8 + (l & 3) * 2;
#pragma unroll
        for (int rr = 0; rr < 4; rr++) {
            int qq = q0 + ((rr >> 1) ? 8 : 0);
            int hh = h + (rr & 1);
            float v = acc[p][rr] + g_xp[(size_t)(t * 256 + qq) * 1024 + hh] + bhh[hh];
            float ht = tanhf(v);
            size_t o = (size_t)qq * H_DIM + hh;
            g_hf[o] = ht;
            __nv_bfloat16 hb = __float2bfloat16(ht);
            g_hbh[bout][o] = hb;
            g_hbl[bout][o] = __float2bfloat16(ht - __bfloat162float(hb));
        }
    }
}

// ---------------- kernel D4: output gate mix ----------------
__global__ void k_out(float* __restrict__ out) {
    int i = blockIdx.x * blockDim.x + threadIdx.x;
    int q = i >> 9, h = i & 511;
    float gpre = g_xp[(size_t)q * 1024 + 512 + h];
    float g = 1.0f / (1.0f + expf(-gpre));
    float proj = g_xp[(size_t)q * 1024 + h];
    out[i] = g * g_hf[i] + (1.0f - g) * proj;
}

// ---------------- launch ----------------
extern "C" void kernel_launch(void* const* d_in, const int* in_sizes, int n_in,
                              void* d_out, int out_size) {
    const float* query  = (const float*)d_in[0];
    const float* mem    = (const float*)d_in[1];
    const float* coords = (const float*)d_in[2];
    const float* sw     = (const float*)d_in[3];
    const float* Wih    = (const float*)d_in[4];
    const float* bih    = (const float*)d_in[5];
    const float* Whh    = (const float*)d_in[6];
    const float* bhh    = (const float*)d_in[7];
    const float* gW     = (const float*)d_in[8];
    const float* gb     = (const float*)d_in[9];
    float* out = (float*)d_out;

    cudaFuncSetAttribute(k_sims_mma, cudaFuncAttributeMaxDynamicSharedMemorySize, SIMS_SMEM);
    cudaFuncSetAttribute(k_xproj,    cudaFuncAttributeMaxDynamicSharedMemorySize, XP_SMEM);
    cudaFuncSetAttribute(k_step,     cudaFuncAttributeMaxDynamicSharedMemorySize, ST_SMEM);

    k_center<<<1, 256>>>(sw);
    k_act<<<(M_MEM + 255) / 256, 256>>>(coords);
    k_qnorm<<<B_Q, 128>>>(query);
    k_prep<<<(H_DIM * H_DIM + 1024 * D_DIM + 255) / 256, 256>>>(Whh, Wih, gW);
    k_sims_mma<<<dim3(2, NSLAB), 256, SIMS_SMEM>>>(mem);
    k_merge<<<B_Q, 256>>>();
    k_refine<<<B_Q, 128>>>(query, mem);
    k_xproj<<<dim3(12, 8), 256, XP_SMEM>>>(query, mem, bih, gb);
    k_h0<<<(B_Q * H_DIM) / 256, 256>>>(bhh);
    for (int t = 1; t <= TOPK; t++)
        k_step<<<dim3(4, 4), 256, ST_SMEM>>>(t, bhh);
    k_out<<<(B_Q * H_DIM) / 256, 256>>>(out);
}

// round 9
// speedup vs baseline: 1.4068x; 1.0729x over previous
#include <cuda_runtime.h>
#include <cuda_bf16.h>
#include <math.h>
#include <stdint.h>

// Problem constants
#define B_Q   256
#define M_MEM 200000
#define D_DIM 384
#define H_DIM 512
#define TOPK  5
#define KC    16
#define TM    128
#define NSLAB ((M_MEM + TM - 1) / TM)   // 1563

// ---------------- device scratch ----------------
__device__ float g_center[2];
__device__ float g_act[M_MEM];
__device__ __align__(16) __nv_bfloat16 g_qhi[B_Q * D_DIM];
__device__ float g_cand_val[(size_t)NSLAB * B_Q * TOPK];
__device__ int   g_cand_idx[(size_t)NSLAB * B_Q * TOPK];
__device__ int   g_cand16[B_Q * KC];
__device__ int   g_topk[B_Q * TOPK];
// RNN path scratch
__device__ __align__(16) __nv_bfloat16 g_whh_h[H_DIM * H_DIM];
__device__ __align__(16) __nv_bfloat16 g_whh_l[H_DIM * H_DIM];
__device__ __align__(16) __nv_bfloat16 g_wcat_h[1024 * D_DIM];
__device__ __align__(16) __nv_bfloat16 g_wcat_l[1024 * D_DIM];
__device__ float g_xp[1536 * 1024];
__device__ __align__(16) __nv_bfloat16 g_hbh[2][B_Q * H_DIM];
__device__ __align__(16) __nv_bfloat16 g_hbl[2][B_Q * H_DIM];
__device__ float g_hf[B_Q * H_DIM];

// ---------------- helpers ----------------
__device__ __forceinline__ uint32_t smem_u32(const void* p) {
    uint32_t a;
    asm("{ .reg .u64 t; cvta.to.shared.u64 t, %1; cvt.u32.u64 %0, t; }" : "=r"(a) : "l"(p));
    return a;
}
#define CPA16(s, g)  asm volatile("cp.async.cg.shared.global [%0], [%1], 16;" :: "r"(s), "l"(g) : "memory")
#define CPA_COMMIT() asm volatile("cp.async.commit_group;" ::: "memory")
#define CPA_WAIT0()  asm volatile("cp.async.wait_group 0;" ::: "memory")
#define CPA_WAIT1()  asm volatile("cp.async.wait_group 1;" ::: "memory")

__device__ __forceinline__ void ldsm4(uint32_t* r, uint32_t addr) {
    asm volatile("ldmatrix.sync.aligned.m8n8.x4.shared.b16 {%0,%1,%2,%3}, [%4];"
        : "=r"(r[0]), "=r"(r[1]), "=r"(r[2]), "=r"(r[3]) : "r"(addr));
}
__device__ __forceinline__ void mma16816(float* d, const uint32_t* a, uint32_t b0, uint32_t b1) {
    asm volatile("mma.sync.aligned.m16n8k16.row.col.f32.bf16.bf16.f32 "
        "{%0,%1,%2,%3}, {%4,%5,%6,%7}, {%8,%9}, {%0,%1,%2,%3};"
        : "+f"(d[0]), "+f"(d[1]), "+f"(d[2]), "+f"(d[3])
        : "r"(a[0]), "r"(a[1]), "r"(a[2]), "r"(a[3]), "r"(b0), "r"(b1));
}
__device__ __forceinline__ void splt2(float x, float y, uint32_t& hw, uint32_t& lw) {
    __nv_bfloat16 hx = __float2bfloat16(x), hy = __float2bfloat16(y);
    __nv_bfloat16 lx = __float2bfloat16(x - __bfloat162float(hx));
    __nv_bfloat16 ly = __float2bfloat16(y - __bfloat162float(hy));
    __nv_bfloat162 hp = __halves2bfloat162(hx, hy);
    __nv_bfloat162 lp = __halves2bfloat162(lx, ly);
    hw = *(uint32_t*)&hp; lw = *(uint32_t*)&lp;
}
__device__ __forceinline__ uint32_t pk2hi(float x, float y) {
    __nv_bfloat162 hp = __halves2bfloat162(__float2bfloat16(x), __float2bfloat16(y));
    return *(uint32_t*)&hp;
}

__device__ __forceinline__ bool better(float v, int i, float w, int j) {
    return (v > w) || (v == w && i < j);
}
template <int K>
__device__ __forceinline__ void insK(float v, int i, float* tv, int* ti) {
    if (!better(v, i, tv[K - 1], ti[K - 1])) return;
#pragma unroll
    for (int r = 0; r < K; r++) {
        if (better(v, i, tv[r], ti[r])) {
            float fv = tv[r]; int fi = ti[r];
            tv[r] = v; ti[r] = i;
            v = fv; i = fi;
        }
    }
}
#define ins5 insK<TOPK>

// ---------------- kernel A0: center ----------------
__global__ void k_center(const float* __restrict__ sw) {
    __shared__ float sx[256], sy[256];
    int tid = threadIdx.x;
    float x = 0.f, y = 0.f;
    for (int i = tid; i < H_DIM; i += 256) { x += sw[2 * i]; y += sw[2 * i + 1]; }
    sx[tid] = x; sy[tid] = y;
    __syncthreads();
    for (int o = 128; o > 0; o >>= 1) {
        if (tid < o) { sx[tid] += sx[tid + o]; sy[tid] += sy[tid + o]; }
        __syncthreads();
    }
    if (tid == 0) {
        g_center[0] = sx[0] / (float)H_DIM;
        g_center[1] = sy[0] / (float)H_DIM;
    }
}

// ---------------- kernel A1: activations ----------------
__global__ void k_act(const float* __restrict__ coords) {
    int i = blockIdx.x * blockDim.x + threadIdx.x;
    if (i < M_MEM) {
        float dx = coords[2 * i]     - g_center[0];
        float dy = coords[2 * i + 1] - g_center[1];
        g_act[i] = 1.0f / (1.0f + sqrtf(dx * dx + dy * dy));
    }
}

// ---------------- kernel A2: normalize queries -> bf16 hi ----------------
__global__ void k_qnorm(const float* __restrict__ q) {
    __shared__ float red[128];
    int b = blockIdx.x, tid = threadIdx.x;
    float s = 0.f;
    for (int d = tid; d < D_DIM; d += 128) {
        float v = q[(size_t)b * D_DIM + d];
        s += v * v;
    }
    red[tid] = s;
    __syncthreads();
    for (int o = 64; o > 0; o >>= 1) {
        if (tid < o) red[tid] += red[tid + o];
        __syncthreads();
    }
    float r = 1.0f / fmaxf(sqrtf(red[0]), 1e-8f);
    for (int d = tid; d < D_DIM; d += 128)
        g_qhi[(size_t)b * D_DIM + d] = __float2bfloat16(q[(size_t)b * D_DIM + d] * r);
}

// ---------------- kernel A3: weight split prep ----------------
__global__ void k_prep(const float* __restrict__ Whh, const float* __restrict__ Wih,
                       const float* __restrict__ gW) {
    int i = blockIdx.x * blockDim.x + threadIdx.x;
    if (i < H_DIM * H_DIM) {
        float v = Whh[i];
        __nv_bfloat16 h = __float2bfloat16(v);
        g_whh_h[i] = h;
        g_whh_l[i] = __float2bfloat16(v - __bfloat162float(h));
    } else if (i < H_DIM * H_DIM + 1024 * D_DIM) {
        int j = i - H_DIM * H_DIM;
        int row = j / D_DIM, col = j % D_DIM;
        float v = (row < 512) ? Wih[row * D_DIM + col] : gW[(row - 512) * D_DIM + col];
        __nv_bfloat16 h = __float2bfloat16(v);
        g_wcat_h[j] = h;
        g_wcat_l[j] = __float2bfloat16(v - __bfloat162float(h));
    }
}

// ---------------- kernel B: 1-term coarse sims, 128x128 tile, 2 CTAs/SM ----------------
// chunk K=64 bf16, PADB=144. Stage: Ahi | Bhi (18432 each).
#define S_BHI  18432
#define STG_SZ 36864
#define HDR    2048
#define SIMS_SMEM (HDR + 2 * STG_SZ)   // 75776
#define E_STG  HDR                      // 128 x 132 f32 = 67584

__global__ __launch_bounds__(256, 2) void k_sims_mma(const float* __restrict__ mem) {
    extern __shared__ char smem[];
    const uint32_t sb = smem_u32(smem);
    float* s_rn  = (float*)smem;
    float* s_act = (float*)(smem + 512);
    float* s_red = (float*)(smem + 1024);

    const int tid = threadIdx.x;
    const int l   = tid & 31;
    const int w   = tid >> 5;       // 0..7
    const int wm  = w & 1;          // rows wm*64..+64
    const int wn  = w >> 1;         // queries wn*32..+32
    const int m0  = blockIdx.y * TM;
    const int q0  = blockIdx.x * 128;

    if (tid < 128) {
        bool ok = (m0 + tid) < M_MEM;
        s_act[tid] = ok ? g_act[m0 + tid] : -1e30f;
    }

    float acc[4][4][4];
#pragma unroll
    for (int a = 0; a < 4; a++)
#pragma unroll
        for (int p = 0; p < 4; p++)
#pragma unroll
            for (int r = 0; r < 4; r++) acc[a][p][r] = 0.f;

    const int arow = tid >> 1, akh = tid & 1;
    int arg = m0 + arow; if (arg >= M_MEM) arg = M_MEM - 1;
    const float4* asrc = (const float4*)(mem + (size_t)arg * D_DIM + akh * 32);
    const uint32_t asts = (uint32_t)(arow * 144 + akh * 64);

    const uint32_t aoff = (uint32_t)((wm * 64 + (l & 15)) * 144 + (l >> 4) * 16);
    const uint32_t boff = S_BHI + (uint32_t)((wn * 32 + (l & 15)) * 144 + (l >> 4) * 16);

    float nsq = 0.f;
    float4 pf[8];

#define LOAD_B(st, cc) do {                                                   \
    _Pragma("unroll")                                                         \
    for (int i = 0; i < 4; i++) {                                             \
        int idx = i * 256 + tid;                                              \
        int row = idx >> 3, s = idx & 7;                                      \
        size_t go = (size_t)(q0 + row) * D_DIM + (cc) * 64 + s * 8;           \
        CPA16((st) + S_BHI + (uint32_t)(row * 144 + s * 16),                  \
              (const void*)(g_qhi + go));                                     \
    }                                                                         \
    CPA_COMMIT();                                                             \
} while (0)

#define STORE_A(sc) do {                                                      \
    _Pragma("unroll")                                                         \
    for (int i = 0; i < 4; i++) {                                             \
        float4 v0 = pf[2 * i], v1 = pf[2 * i + 1];                            \
        nsq += v0.x * v0.x + v0.y * v0.y + v0.z * v0.z + v0.w * v0.w          \
             + v1.x * v1.x + v1.y * v1.y + v1.z * v1.z + v1.w * v1.w;         \
        uint32_t h0 = pk2hi(v0.x, v0.y), h1 = pk2hi(v0.z, v0.w);              \
        uint32_t h2 = pk2hi(v1.x, v1.y), h3 = pk2hi(v1.z, v1.w);              \
        *(uint4*)((sc) + asts + i * 16) = make_uint4(h0, h1, h2, h3);         \
    }                                                                         \
} while (0)

    // ---- prologue: chunks 0, 1 ----
    LOAD_B(sb + HDR, 0);
    LOAD_B(sb + HDR + STG_SZ, 1);
#pragma unroll
    for (int i = 0; i < 8; i++) pf[i] = asrc[i];
    STORE_A(smem + HDR);
#pragma unroll
    for (int i = 0; i < 8; i++) pf[i] = asrc[16 + i];
    STORE_A(smem + HDR + STG_SZ);

#pragma unroll 1
    for (int c = 0; c < 6; c++) {
        const uint32_t st = sb + HDR + (c & 1) * STG_SZ;
        if (c == 5) CPA_WAIT0(); else CPA_WAIT1();
        __syncthreads();

        if (c < 4) {
#pragma unroll
            for (int i = 0; i < 8; i++) pf[i] = asrc[(c + 2) * 16 + i];
        }

        const uint32_t aB = st + aoff;
        const uint32_t bB = st + boff;
#pragma unroll
        for (int kk = 0; kk < 4; kk++) {
            uint32_t bh[8];
#pragma unroll
            for (int pp = 0; pp < 2; pp++)
                ldsm4(bh + pp * 4, bB + (uint32_t)(pp * 16 * 144 + kk * 32));
#pragma unroll
            for (int a = 0; a < 4; a++) {
                uint32_t ah4[4];
                ldsm4(ah4, aB + (uint32_t)(a * 16 * 144 + kk * 32));
#pragma unroll
                for (int p = 0; p < 4; p++) {
                    int pp = p >> 1, hi = p & 1;
                    mma16816(acc[a][p], ah4, bh[pp * 4 + hi], bh[pp * 4 + hi + 2]);
                }
            }
        }

        if (c < 4) {
            __syncthreads();
            STORE_A(smem + HDR + (c & 1) * STG_SZ);
            LOAD_B(st, c + 2);
        }
    }

    // ---- norms reduce ----
    __syncthreads();
    s_red[tid] = nsq;
    __syncthreads();
    if (tid < 128) {
        float s = s_red[2 * tid] + s_red[2 * tid + 1];
        bool ok = (m0 + tid) < M_MEM;
        s_rn[tid] = ok ? 1.0f / fmaxf(sqrtf(s), 1e-8f) : 0.0f;
    }
    __syncthreads();

    // ---- epilogue: scale + bias, stage query-major (128 queries) ----
    float* stg = (float*)(smem + E_STG);
#pragma unroll
    for (int a = 0; a < 4; a++) {
        int mA = wm * 64 + a * 16 + (l >> 2);
        float rnA = s_rn[mA],     acA = s_act[mA];
        float rnB = s_rn[mA + 8], acB = s_act[mA + 8];
#pragma unroll
        for (int p = 0; p < 4; p++) {
            int q = wn * 32 + p * 8 + (l & 3) * 2;
            stg[q * 132 + mA]           = acc[a][p][0] * rnA + acA;
            stg[(q + 1) * 132 + mA]     = acc[a][p][1] * rnA + acA;
            stg[q * 132 + mA + 8]       = acc[a][p][2] * rnB + acB;
            stg[(q + 1) * 132 + mA + 8] = acc[a][p][3] * rnB + acB;
        }
    }
    __syncthreads();

    // top-5: 2 threads per query, shuffle merge
    {
        int q = tid >> 1, h = tid & 1;
        float tv[TOPK]; int ti[TOPK];
#pragma unroll
        for (int r = 0; r < TOPK; r++) { tv[r] = -3.4e38f; ti[r] = 0x7fffffff; }
        const float4* col = (const float4*)(stg + q * 132 + h * 64);
#pragma unroll 4
        for (int i = 0; i < 16; i++) {
            float4 v = col[i];
            int mb = m0 + h * 64 + i * 4;
            ins5(v.x, mb,     tv, ti);
            ins5(v.y, mb + 1, tv, ti);
            ins5(v.z, mb + 2, tv, ti);
            ins5(v.w, mb + 3, tv, ti);
        }
        float ov[TOPK]; int oi[TOPK];
#pragma unroll
        for (int r = 0; r < TOPK; r++) {
            ov[r] = __shfl_down_sync(0xffffffff, tv[r], 1);
            oi[r] = __shfl_down_sync(0xffffffff, ti[r], 1);
        }
        if (h == 0) {
#pragma unroll
            for (int r = 0; r < TOPK; r++) ins5(ov[r], oi[r], tv, ti);
            size_t base = ((size_t)blockIdx.y * B_Q + q0 + q) * TOPK;
#pragma unroll
            for (int r = 0; r < TOPK; r++) {
                g_cand_val[base + r] = tv[r];
                g_cand_idx[base + r] = ti[r];
            }
        }
    }
#undef LOAD_B
#undef STORE_A
}

// ---------------- kernel C: merge -> coarse top-16 pool ----------------
template <int K>
__device__ __forceinline__ void mergeK(float* av, int* ai, const float* bv, const int* bi) {
    float ov[K]; int oi[K];
    int ia = 0, ib = 0;
#pragma unroll
    for (int r = 0; r < K; r++) {
        bool ta = (ib >= K) || (ia < K && better(av[ia], ai[ia], bv[ib], bi[ib]));
        if (ta) { ov[r] = av[ia]; oi[r] = ai[ia]; ia++; }
        else    { ov[r] = bv[ib]; oi[r] = bi[ib]; ib++; }
    }
#pragma unroll
    for (int r = 0; r < K; r++) { av[r] = ov[r]; ai[r] = oi[r]; }
}

__global__ void k_merge() {
    const int q = blockIdx.x, tid = threadIdx.x;
    float tv[KC]; int ti[KC];
#pragma unroll
    for (int r = 0; r < KC; r++) { tv[r] = -3.4e38f; ti[r] = 0x7fffffff; }
    for (int s = tid; s < NSLAB; s += 256) {
        size_t base = ((size_t)s * B_Q + q) * TOPK;
#pragma unroll
        for (int r = 0; r < TOPK; r++)
            insK<KC>(g_cand_val[base + r], g_cand_idx[base + r], tv, ti);
    }
    __shared__ float sv[256][KC];
    __shared__ int   si[256][KC];
#pragma unroll
    for (int r = 0; r < KC; r++) { sv[tid][r] = tv[r]; si[tid][r] = ti[r]; }
    __syncthreads();
    for (int o = 128; o > 0; o >>= 1) {
        if (tid < o) mergeK<KC>(sv[tid], si[tid], sv[tid + o], si[tid + o]);
        __syncthreads();
    }
    if (tid < KC) g_cand16[q * KC + tid] = si[0][tid];
}

// ---------------- kernel C2: exact fp32 refine of 16 candidates -> top-5 ----------------
__global__ __launch_bounds__(128) void k_refine(const float* __restrict__ query,
                                                const float* __restrict__ mem) {
    __shared__ float qv[D_DIM];
    __shared__ float s_part[4];
    __shared__ float sims[KC];
    const int q = blockIdx.x, tid = threadIdx.x;
    const int lane = tid & 31, wr = tid >> 5;

    for (int d = tid; d < D_DIM; d += 128) qv[d] = query[(size_t)q * D_DIM + d];
    float p = 0.f;
    for (int d = tid; d < D_DIM; d += 128) {
        float v = query[(size_t)q * D_DIM + d];
        p += v * v;
    }
#pragma unroll
    for (int o = 16; o > 0; o >>= 1) p += __shfl_xor_sync(0xffffffff, p, o);
    if (lane == 0) s_part[wr] = p;
    __syncthreads();
    float rq = 1.0f / fmaxf(sqrtf(s_part[0] + s_part[1] + s_part[2] + s_part[3]), 1e-8f);

    for (int c = wr; c < KC; c += 4) {
        int mi = g_cand16[q * KC + c];
        const float* mv = mem + (size_t)mi * D_DIM;
        float dot = 0.f, msq = 0.f;
        for (int d = lane; d < D_DIM; d += 32) {
            float m = mv[d];
            dot += qv[d] * m;
            msq += m * m;
        }
#pragma unroll
        for (int o = 16; o > 0; o >>= 1) {
            dot += __shfl_xor_sync(0xffffffff, dot, o);
            msq += __shfl_xor_sync(0xffffffff, msq, o);
        }
        if (lane == 0)
            sims[c] = dot * rq / fmaxf(sqrtf(msq), 1e-8f) + g_act[mi];
    }
    __syncthreads();

    if (tid == 0) {
        float tv[TOPK]; int ti[TOPK];
#pragma unroll
        for (int r = 0; r < TOPK; r++) { tv[r] = -3.4e38f; ti[r] = 0x7fffffff; }
        for (int c = 0; c < KC; c++)
            ins5(sims[c], g_cand16[q * KC + c], tv, ti);
#pragma unroll
        for (int r = 0; r < TOPK; r++)
            g_topk[q * TOPK + r] = ti[r];
    }
}

// ---------------- kernel D1: x_proj + gate GEMM [1536 x 1024 x 384], fused h0 ----------------
#define XP_AHI 0
#define XP_ALO 34816
#define XP_BHI 69632
#define XP_BLO 104448
#define XP_SMEM 139264

__global__ __launch_bounds__(256, 1) void k_xproj(
    const float* __restrict__ query, const float* __restrict__ mem,
    const float* __restrict__ bih, const float* __restrict__ gb,
    const float* __restrict__ bhh)
{
    extern __shared__ char smem[];
    const uint32_t sb = smem_u32(smem);
    const int tid = threadIdx.x, l = tid & 31, w = tid >> 5;
    const int wm = w & 3, wn = w >> 2;
    const int bm = blockIdx.x, bn = blockIdx.y;

    const int lrow = tid >> 1, kh = tid & 1;
    int r = bm * 128 + lrow;
    int t = r >> 8, q = r & 255;
    const float* aptr;
    if (t == 0) aptr = query + (size_t)q * D_DIM;
    else        aptr = mem + (size_t)g_topk[q * TOPK + t - 1] * D_DIM;
    aptr += kh * 64;

    float acc[2][8][4];
#pragma unroll
    for (int a = 0; a < 2; a++)
#pragma unroll
        for (int p = 0; p < 8; p++)
#pragma unroll
            for (int rr = 0; rr < 4; rr++) acc[a][p][rr] = 0.f;

#pragma unroll 1
    for (int c = 0; c < 3; c++) {
        __syncthreads();
#pragma unroll
        for (int i = 0; i < 8; i++) {
            int idx = i * 256 + tid;
            int row = idx >> 4, s = idx & 15;
            uint32_t d = sb + (uint32_t)(row * 272 + s * 16);
            size_t go = (size_t)(bn * 128 + row) * D_DIM + c * 128 + s * 8;
            CPA16(d + XP_BHI, (const void*)(g_wcat_h + go));
            CPA16(d + XP_BLO, (const void*)(g_wcat_l + go));
        }
        CPA_COMMIT();
        {
            char* ah = smem + XP_AHI;
            char* al = smem + XP_ALO;
            const float4* src = (const float4*)(aptr + c * 128);
#pragma unroll
            for (int i = 0; i < 16; i++) {
                float4 v = src[i];
                uint32_t h0, l0, h1, l1;
                splt2(v.x, v.y, h0, l0);
                splt2(v.z, v.w, h1, l1);
                uint32_t so = (uint32_t)(lrow * 272 + kh * 128 + i * 8);
                *(uint2*)(ah + so) = make_uint2(h0, h1);
                *(uint2*)(al + so) = make_uint2(l0, l1);
            }
        }
        CPA_WAIT0();
        __syncthreads();

        const uint32_t aB = sb + XP_AHI + (uint32_t)((wm * 32 + (l & 15)) * 272 + (l >> 4) * 16);
        const uint32_t bB = sb + XP_BHI + (uint32_t)((wn * 64 + (l & 15)) * 272 + (l >> 4) * 16);
#pragma unroll 1
        for (int kk = 0; kk < 8; kk++) {
            uint32_t bh[16], bl[16];
#pragma unroll
            for (int pp = 0; pp < 4; pp++) {
                uint32_t ba = bB + (uint32_t)(pp * 16 * 272 + kk * 32);
                ldsm4(bh + pp * 4, ba);
                ldsm4(bl + pp * 4, ba + (XP_BLO - XP_BHI));
            }
#pragma unroll
            for (int a = 0; a < 2; a++) {
                uint32_t ah4[4], al4[4];
                uint32_t aa = aB + (uint32_t)(a * 16 * 272 + kk * 32);
                ldsm4(ah4, aa);
                ldsm4(al4, aa + (XP_ALO - XP_AHI));
#pragma unroll
                for (int p = 0; p < 8; p++) {
                    int pp = p >> 1, hi = p & 1;
                    mma16816(acc[a][p], ah4, bh[pp * 4 + hi], bh[pp * 4 + hi + 2]);
                    mma16816(acc[a][p], ah4, bl[pp * 4 + hi], bl[pp * 4 + hi + 2]);
                    mma16816(acc[a][p], al4, bh[pp * 4 + hi], bh[pp * 4 + hi + 2]);
                }
            }
        }
    }

    const bool fuse_h0 = (bm < 2) && (bn < 4);   // t==0 rows, h-columns
#pragma unroll
    for (int a = 0; a < 2; a++) {
        int rA = bm * 128 + wm * 32 + a * 16 + (l >> 2);
#pragma unroll
        for (int p = 0; p < 8; p++) {
            int cg = bn * 128 + wn * 64 + p * 8 + (l & 3) * 2;
            float b0 = (cg < 512) ? bih[cg] : gb[cg - 512];
            float b1 = (cg < 512) ? bih[cg + 1] : gb[cg + 1 - 512];
            float v00 = acc[a][p][0] + b0, v01 = acc[a][p][1] + b1;
            float v10 = acc[a][p][2] + b0, v11 = acc[a][p][3] + b1;
            g_xp[(size_t)rA * 1024 + cg]           = v00;
            g_xp[(size_t)rA * 1024 + cg + 1]       = v01;
            g_xp[(size_t)(rA + 8) * 1024 + cg]     = v10;
            g_xp[(size_t)(rA + 8) * 1024 + cg + 1] = v11;
            if (fuse_h0) {
                float bh0 = bhh[cg], bh1 = bhh[cg + 1];
                float h00 = tanhf(v00 + bh0), h01 = tanhf(v01 + bh1);
                float h10 = tanhf(v10 + bh0), h11 = tanhf(v11 + bh1);
                size_t o0 = (size_t)rA * H_DIM + cg;
                size_t o1 = (size_t)(rA + 8) * H_DIM + cg;
                g_hf[o0] = h00; g_hf[o0 + 1] = h01;
                g_hf[o1] = h10; g_hf[o1 + 1] = h11;
                __nv_bfloat16 q00 = __float2bfloat16(h00), q01 = __float2bfloat16(h01);
                __nv_bfloat16 q10 = __float2bfloat16(h10), q11 = __float2bfloat16(h11);
                g_hbh[0][o0] = q00; g_hbh[0][o0 + 1] = q01;
                g_hbh[0][o1] = q10; g_hbh[0][o1 + 1] = q11;
                g_hbl[0][o0] = __float2bfloat16(h00 - __bfloat162float(q00));
                g_hbl[0][o0 + 1] = __float2bfloat16(h01 - __bfloat162float(q01));
                g_hbl[0][o1] = __float2bfloat16(h10 - __bfloat162float(q10));
                g_hbl[0][o1 + 1] = __float2bfloat16(h11 - __bfloat162float(q11));
            }
        }
    }
}

// ---------------- kernel D3: recurrence step GEMM, 32 CTAs, double-buffered ----------------
#define ST2_AHI 0
#define ST2_ALO 17408
#define ST2_BHI 34816
#define ST2_BLO 52224
#define ST2_STG 69632
#define ST2_SMEM (2 * ST2_STG)   // 139264

__global__ __launch_bounds__(256, 1) void k_step(int t, const float* __restrict__ bhh) {
    extern __shared__ char smem[];
    const uint32_t sb = smem_u32(smem);
    const int tid = threadIdx.x, l = tid & 31, w = tid >> 5;
    const int wm = w & 3, wn = w >> 2;   // warp tile 16 x 32
    const int mt = blockIdx.x, nt = blockIdx.y;   // (4, 8)
    const int bin = (t + 1) & 1, bout = t & 1;
    const __nv_bfloat16* Ah = g_hbh[bin];
    const __nv_bfloat16* Al = g_hbl[bin];

    float acc[4][4];
#pragma unroll
    for (int p = 0; p < 4; p++)
#pragma unroll
        for (int rr = 0; rr < 4; rr++) acc[p][rr] = 0.f;

#define ST_LOAD(cc) do {                                                      \
    uint32_t stn = sb + ((cc) & 1) * ST2_STG;                                 \
    _Pragma("unroll")                                                         \
    for (int i = 0; i < 4; i++) {                                             \
        int idx = i * 256 + tid;                                              \
        int row = idx >> 4, s = idx & 15;                                     \
        uint32_t d = stn + (uint32_t)(row * 272 + s * 16);                    \
        size_t goA = (size_t)(mt * 64 + row) * H_DIM + (cc) * 128 + s * 8;    \
        size_t goB = (size_t)(nt * 64 + row) * H_DIM + (cc) * 128 + s * 8;    \
        CPA16(d + ST2_AHI, (const void*)(Ah + goA));                          \
        CPA16(d + ST2_ALO, (const void*)(Al + goA));                          \
        CPA16(d + ST2_BHI, (const void*)(g_whh_h + goB));                     \
        CPA16(d + ST2_BLO, (const void*)(g_whh_l + goB));                     \
    }                                                                         \
    CPA_COMMIT();                                                             \
} while (0)

    ST_LOAD(0);

#pragma unroll 1
    for (int c = 0; c < 4; c++) {
        __syncthreads();             // prior compute on target buffer done
        if (c < 3) ST_LOAD(c + 1);
        if (c < 3) CPA_WAIT1(); else CPA_WAIT0();
        __syncthreads();

        const uint32_t st = sb + (c & 1) * ST2_STG;
        const uint32_t aB = st + ST2_AHI + (uint32_t)((wm * 16 + (l & 15)) * 272 + (l >> 4) * 16);
        const uint32_t bB = st + ST2_BHI + (uint32_t)((wn * 32 + (l & 15)) * 272 + (l >> 4) * 16);
#pragma unroll 1
        for (int kk = 0; kk < 8; kk++) {
            uint32_t bh[8], bl[8];
#pragma unroll
            for (int pp = 0; pp < 2; pp++) {
                uint32_t ba = bB + (uint32_t)(pp * 16 * 272 + kk * 32);
                ldsm4(bh + pp * 4, ba);
                ldsm4(bl + pp * 4, ba + (ST2_BLO - ST2_BHI));
            }
            uint32_t ah4[4], al4[4];
            ldsm4(ah4, aB + (uint32_t)(kk * 32));
            ldsm4(al4, aB + (uint32_t)(kk * 32) + (ST2_ALO - ST2_AHI));
#pragma unroll
            for (int p = 0; p < 4; p++) {
                int pp = p >> 1, hi = p & 1;
                mma16816(acc[p], ah4, bh[pp * 4 + hi], bh[pp * 4 + hi + 2]);
                mma16816(acc[p], ah4, bl[pp * 4 + hi], bl[pp * 4 + hi + 2]);
                mma16816(acc[p], al4, bh[pp * 4 + hi], bh[pp * 4 + hi + 2]);
            }
        }
    }

    int q0 = mt * 64 + wm * 16 + (l >> 2);
#pragma unroll
    for (int p = 0; p < 4; p++) {
        int h = nt * 64 + wn * 32 + p * 8 + (l & 3) * 2;
#pragma unroll
        for (int rr = 0; rr < 4; rr++) {
            int qq = q0 + ((rr >> 1) ? 8 : 0);
            int hh = h + (rr & 1);
            float v = acc[p][rr] + g_xp[(size_t)(t * 256 + qq) * 1024 + hh] + bhh[hh];
            float ht = tanhf(v);
            size_t o = (size_t)qq * H_DIM + hh;
            g_hf[o] = ht;
            __nv_bfloat16 hb = __float2bfloat16(ht);
            g_hbh[bout][o] = hb;
            g_hbl[bout][o] = __float2bfloat16(ht - __bfloat162float(hb));
        }
    }
#undef ST_LOAD
}

// ---------------- kernel D4: output gate mix ----------------
__global__ void k_out(float* __restrict__ out) {
    int i = blockIdx.x * blockDim.x + threadIdx.x;
    int q = i >> 9, h = i & 511;
    float gpre = g_xp[(size_t)q * 1024 + 512 + h];
    float g = 1.0f / (1.0f + expf(-gpre));
    float proj = g_xp[(size_t)q * 1024 + h];
    out[i] = g * g_hf[i] + (1.0f - g) * proj;
}

// ---------------- launch ----------------
extern "C" void kernel_launch(void* const* d_in, const int* in_sizes, int n_in,
                              void* d_out, int out_size) {
    const float* query  = (const float*)d_in[0];
    const float* mem    = (const float*)d_in[1];
    const float* coords = (const float*)d_in[2];
    const float* sw     = (const float*)d_in[3];
    const float* Wih    = (const float*)d_in[4];
    const float* bih    = (const float*)d_in[5];
    const float* Whh    = (const float*)d_in[6];
    const float* bhh    = (const float*)d_in[7];
    const float* gW     = (const float*)d_in[8];
    const float* gb     = (const float*)d_in[9];
    float* out = (float*)d_out;

    cudaFuncSetAttribute(k_sims_mma, cudaFuncAttributeMaxDynamicSharedMemorySize, SIMS_SMEM);
    cudaFuncSetAttribute(k_xproj,    cudaFuncAttributeMaxDynamicSharedMemorySize, XP_SMEM);
    cudaFuncSetAttribute(k_step,     cudaFuncAttributeMaxDynamicSharedMemorySize, ST2_SMEM);

    // k_sims as launch #3 -> lands in the ncu capture window
    k_center<<<1, 256>>>(sw);
    k_act<<<(M_MEM + 255) / 256, 256>>>(coords);
    k_qnorm<<<B_Q, 128>>>(query);
    k_sims_mma<<<dim3(2, NSLAB), 256, SIMS_SMEM>>>(mem);
    k_prep<<<(H_DIM * H_DIM + 1024 * D_DIM + 255) / 256, 256>>>(Whh, Wih, gW);
    k_merge<<<B_Q, 256>>>();
    k_refine<<<B_Q, 128>>>(query, mem);
    k_xproj<<<dim3(12, 8), 256, XP_SMEM>>>(query, mem, bih, gb, bhh);
    for (int t = 1; t <= TOPK; t++)
        k_step<<<dim3(4, 8), 256, ST2_SMEM>>>(t, bhh);
    k_out<<<(B_Q * H_DIM) / 256, 256>>>(out);
}

// round 10
// speedup vs baseline: 1.4172x; 1.0074x over previous
#include <cuda_runtime.h>
#include <cuda_bf16.h>
#include <math.h>
#include <stdint.h>

// Problem constants
#define B_Q   256
#define M_MEM 200000
#define D_DIM 384
#define H_DIM 512
#define TOPK  5
#define KC    16
#define TM    128
#define NSLAB ((M_MEM + TM - 1) / TM)   // 1563

// ---------------- device scratch ----------------
__device__ float g_center[2];
__device__ float g_act[M_MEM];
__device__ __align__(16) __nv_bfloat16 g_qhi[B_Q * D_DIM];
__device__ float g_cand_val[(size_t)NSLAB * B_Q * TOPK];
__device__ int   g_cand_idx[(size_t)NSLAB * B_Q * TOPK];
__device__ int   g_cand16[B_Q * KC];
__device__ int   g_topk[B_Q * TOPK];
// RNN path scratch
__device__ __align__(16) __nv_bfloat16 g_whh_h[H_DIM * H_DIM];
__device__ __align__(16) __nv_bfloat16 g_whh_l[H_DIM * H_DIM];
__device__ __align__(16) __nv_bfloat16 g_wcat_h[1024 * D_DIM];
__device__ __align__(16) __nv_bfloat16 g_wcat_l[1024 * D_DIM];
__device__ float g_xp[1536 * 1024];
__device__ __align__(16) __nv_bfloat16 g_hbh[2][B_Q * H_DIM];
__device__ __align__(16) __nv_bfloat16 g_hbl[2][B_Q * H_DIM];
__device__ float g_hf[B_Q * H_DIM];

// ---------------- helpers ----------------
__device__ __forceinline__ uint32_t smem_u32(const void* p) {
    uint32_t a;
    asm("{ .reg .u64 t; cvta.to.shared.u64 t, %1; cvt.u32.u64 %0, t; }" : "=r"(a) : "l"(p));
    return a;
}
#define CPA16(s, g)  asm volatile("cp.async.cg.shared.global [%0], [%1], 16;" :: "r"(s), "l"(g) : "memory")
#define CPA_COMMIT() asm volatile("cp.async.commit_group;" ::: "memory")
#define CPA_WAIT0()  asm volatile("cp.async.wait_group 0;" ::: "memory")
#define CPA_WAIT1()  asm volatile("cp.async.wait_group 1;" ::: "memory")

__device__ __forceinline__ void ldsm4(uint32_t* r, uint32_t addr) {
    asm volatile("ldmatrix.sync.aligned.m8n8.x4.shared.b16 {%0,%1,%2,%3}, [%4];"
        : "=r"(r[0]), "=r"(r[1]), "=r"(r[2]), "=r"(r[3]) : "r"(addr));
}
__device__ __forceinline__ void mma16816(float* d, const uint32_t* a, uint32_t b0, uint32_t b1) {
    asm volatile("mma.sync.aligned.m16n8k16.row.col.f32.bf16.bf16.f32 "
        "{%0,%1,%2,%3}, {%4,%5,%6,%7}, {%8,%9}, {%0,%1,%2,%3};"
        : "+f"(d[0]), "+f"(d[1]), "+f"(d[2]), "+f"(d[3])
        : "r"(a[0]), "r"(a[1]), "r"(a[2]), "r"(a[3]), "r"(b0), "r"(b1));
}
__device__ __forceinline__ void splt2(float x, float y, uint32_t& hw, uint32_t& lw) {
    __nv_bfloat16 hx = __float2bfloat16(x), hy = __float2bfloat16(y);
    __nv_bfloat16 lx = __float2bfloat16(x - __bfloat162float(hx));
    __nv_bfloat16 ly = __float2bfloat16(y - __bfloat162float(hy));
    __nv_bfloat162 hp = __halves2bfloat162(hx, hy);
    __nv_bfloat162 lp = __halves2bfloat162(lx, ly);
    hw = *(uint32_t*)&hp; lw = *(uint32_t*)&lp;
}
__device__ __forceinline__ uint32_t pk2hi(float x, float y) {
    __nv_bfloat162 hp = __halves2bfloat162(__float2bfloat16(x), __float2bfloat16(y));
    return *(uint32_t*)&hp;
}

__device__ __forceinline__ bool better(float v, int i, float w, int j) {
    return (v > w) || (v == w && i < j);
}
template <int K>
__device__ __forceinline__ void insK(float v, int i, float* tv, int* ti) {
    if (!better(v, i, tv[K - 1], ti[K - 1])) return;
#pragma unroll
    for (int r = 0; r < K; r++) {
        if (better(v, i, tv[r], ti[r])) {
            float fv = tv[r]; int fi = ti[r];
            tv[r] = v; ti[r] = i;
            v = fv; i = fi;
        }
    }
}
#define ins5 insK<TOPK>

// ---------------- kernel A0: center ----------------
__global__ void k_center(const float* __restrict__ sw) {
    __shared__ float sx[256], sy[256];
    int tid = threadIdx.x;
    float x = 0.f, y = 0.f;
    for (int i = tid; i < H_DIM; i += 256) { x += sw[2 * i]; y += sw[2 * i + 1]; }
    sx[tid] = x; sy[tid] = y;
    __syncthreads();
    for (int o = 128; o > 0; o >>= 1) {
        if (tid < o) { sx[tid] += sx[tid + o]; sy[tid] += sy[tid + o]; }
        __syncthreads();
    }
    if (tid == 0) {
        g_center[0] = sx[0] / (float)H_DIM;
        g_center[1] = sy[0] / (float)H_DIM;
    }
}

// ---------------- kernel A1: activations ----------------
__global__ void k_act(const float* __restrict__ coords) {
    int i = blockIdx.x * blockDim.x + threadIdx.x;
    if (i < M_MEM) {
        float dx = coords[2 * i]     - g_center[0];
        float dy = coords[2 * i + 1] - g_center[1];
        g_act[i] = 1.0f / (1.0f + sqrtf(dx * dx + dy * dy));
    }
}

// ---------------- kernel A2: normalize queries -> bf16 hi ----------------
__global__ void k_qnorm(const float* __restrict__ q) {
    __shared__ float red[128];
    int b = blockIdx.x, tid = threadIdx.x;
    float s = 0.f;
    for (int d = tid; d < D_DIM; d += 128) {
        float v = q[(size_t)b * D_DIM + d];
        s += v * v;
    }
    red[tid] = s;
    __syncthreads();
    for (int o = 64; o > 0; o >>= 1) {
        if (tid < o) red[tid] += red[tid + o];
        __syncthreads();
    }
    float r = 1.0f / fmaxf(sqrtf(red[0]), 1e-8f);
    for (int d = tid; d < D_DIM; d += 128)
        g_qhi[(size_t)b * D_DIM + d] = __float2bfloat16(q[(size_t)b * D_DIM + d] * r);
}

// ---------------- kernel A3: weight split prep ----------------
__global__ void k_prep(const float* __restrict__ Whh, const float* __restrict__ Wih,
                       const float* __restrict__ gW) {
    int i = blockIdx.x * blockDim.x + threadIdx.x;
    if (i < H_DIM * H_DIM) {
        float v = Whh[i];
        __nv_bfloat16 h = __float2bfloat16(v);
        g_whh_h[i] = h;
        g_whh_l[i] = __float2bfloat16(v - __bfloat162float(h));
    } else if (i < H_DIM * H_DIM + 1024 * D_DIM) {
        int j = i - H_DIM * H_DIM;
        int row = j / D_DIM, col = j % D_DIM;
        float v = (row < 512) ? Wih[row * D_DIM + col] : gW[(row - 512) * D_DIM + col];
        __nv_bfloat16 h = __float2bfloat16(v);
        g_wcat_h[j] = h;
        g_wcat_l[j] = __float2bfloat16(v - __bfloat162float(h));
    }
}

// ---------------- kernel B: 1-term coarse sims, 128m x 256q, 512 threads ----------------
// chunk K=128 bf16 (256B/row, PADB=272). Stage: Ahi (128x272) | Bhi (256x272).
#define S2_B   34816
#define STG2   104448
#define HDR2   4096
#define SIMS_SMEM (HDR2 + 2 * STG2)   // 212992
#define E_STG  HDR2                   // 256 x 132 f32 = 135168

__global__ __launch_bounds__(512, 1) void k_sims_mma(const float* __restrict__ mem) {
    extern __shared__ char smem[];
    const uint32_t sb = smem_u32(smem);
    float* s_rn  = (float*)smem;                 // 128 f32
    float* s_act = (float*)(smem + 512);         // 128 f32
    float* s_red = (float*)(smem + 1024);        // 512 f32

    const int tid = threadIdx.x;
    const int l   = tid & 31;
    const int w   = tid >> 5;       // 0..15
    const int wm  = w & 3;          // m rows wm*32..+32
    const int wn  = w >> 2;         // queries wn*64..+64
    const int m0  = blockIdx.x * TM;

    if (tid < 128) {
        bool ok = (m0 + tid) < M_MEM;
        s_act[tid] = ok ? g_act[m0 + tid] : -1e30f;
    }

    float acc[2][8][4];
#pragma unroll
    for (int a = 0; a < 2; a++)
#pragma unroll
        for (int p = 0; p < 8; p++)
#pragma unroll
            for (int r = 0; r < 4; r++) acc[a][p][r] = 0.f;

    // A source: 4 threads per row, each quarter = 32 floats (8 float4)
    const int arow = tid >> 2, aq = tid & 3;
    int arg = m0 + arow; if (arg >= M_MEM) arg = M_MEM - 1;
    const float4* asrcq = (const float4*)(mem + (size_t)arg * D_DIM) + aq * 8;
    const uint32_t asts = (uint32_t)(arow * 272 + aq * 64);

    const uint32_t aoff = (uint32_t)((wm * 32 + (l & 15)) * 272 + (l >> 4) * 16);
    const uint32_t boff = S2_B + (uint32_t)((wn * 64 + (l & 15)) * 272 + (l >> 4) * 16);

    float nsq = 0.f;
    float4 pf[8];

#define LOAD_B(st, cc) do {                                                   \
    _Pragma("unroll")                                                         \
    for (int i = 0; i < 8; i++) {                                             \
        int idx = i * 512 + tid;                                              \
        int row = idx >> 4, s = idx & 15;                                     \
        size_t go = (size_t)row * D_DIM + (cc) * 128 + s * 8;                 \
        CPA16((st) + S2_B + (uint32_t)(row * 272 + s * 16),                   \
              (const void*)(g_qhi + go));                                     \
    }                                                                         \
    CPA_COMMIT();                                                             \
} while (0)

#define STORE_A(sc) do {                                                      \
    _Pragma("unroll")                                                         \
    for (int i = 0; i < 4; i++) {                                             \
        float4 v0 = pf[2 * i], v1 = pf[2 * i + 1];                            \
        nsq += v0.x * v0.x + v0.y * v0.y + v0.z * v0.z + v0.w * v0.w          \
             + v1.x * v1.x + v1.y * v1.y + v1.z * v1.z + v1.w * v1.w;         \
        uint32_t h0 = pk2hi(v0.x, v0.y), h1 = pk2hi(v0.z, v0.w);              \
        uint32_t h2 = pk2hi(v1.x, v1.y), h3 = pk2hi(v1.z, v1.w);              \
        *(uint4*)((sc) + asts + i * 16) = make_uint4(h0, h1, h2, h3);         \
    }                                                                         \
} while (0)

    // ---- prologue: chunks 0, 1 ----
    LOAD_B(sb + HDR2, 0);
    LOAD_B(sb + HDR2 + STG2, 1);
#pragma unroll
    for (int i = 0; i < 8; i++) pf[i] = asrcq[i];
    STORE_A(smem + HDR2);
#pragma unroll
    for (int i = 0; i < 8; i++) pf[i] = asrcq[32 + i];
    STORE_A(smem + HDR2 + STG2);

#pragma unroll 1
    for (int c = 0; c < 3; c++) {
        const uint32_t st = sb + HDR2 + (c & 1) * STG2;
        if (c == 2) CPA_WAIT0(); else CPA_WAIT1();
        __syncthreads();

        if (c < 1) {
#pragma unroll
            for (int i = 0; i < 8; i++) pf[i] = asrcq[(c + 2) * 32 + i];
        }

        const uint32_t aB = st + aoff;
        const uint32_t bB = st + boff;
#pragma unroll 1
        for (int kk = 0; kk < 8; kk++) {
            uint32_t bh[16];
#pragma unroll
            for (int pp = 0; pp < 4; pp++)
                ldsm4(bh + pp * 4, bB + (uint32_t)(pp * 16 * 272 + kk * 32));
#pragma unroll
            for (int a = 0; a < 2; a++) {
                uint32_t ah4[4];
                ldsm4(ah4, aB + (uint32_t)(a * 16 * 272 + kk * 32));
#pragma unroll
                for (int p = 0; p < 8; p++) {
                    int pp = p >> 1, hi = p & 1;
                    mma16816(acc[a][p], ah4, bh[pp * 4 + hi], bh[pp * 4 + hi + 2]);
                }
            }
        }

        if (c < 1) {
            __syncthreads();
            STORE_A(smem + HDR2 + (c & 1) * STG2);
            LOAD_B(st, c + 2);
        }
    }

    // ---- norms reduce ----
    __syncthreads();
    s_red[tid] = nsq;
    __syncthreads();
    if (tid < 128) {
        float s = s_red[4 * tid] + s_red[4 * tid + 1] + s_red[4 * tid + 2] + s_red[4 * tid + 3];
        bool ok = (m0 + tid) < M_MEM;
        s_rn[tid] = ok ? 1.0f / fmaxf(sqrtf(s), 1e-8f) : 0.0f;
    }
    __syncthreads();

    // ---- epilogue: scale + bias, stage query-major (256 queries) ----
    float* stg = (float*)(smem + E_STG);
#pragma unroll
    for (int a = 0; a < 2; a++) {
        int mA = wm * 32 + a * 16 + (l >> 2);
        float rnA = s_rn[mA],     acA = s_act[mA];
        float rnB = s_rn[mA + 8], acB = s_act[mA + 8];
#pragma unroll
        for (int p = 0; p < 8; p++) {
            int q = wn * 64 + p * 8 + (l & 3) * 2;
            stg[q * 132 + mA]           = acc[a][p][0] * rnA + acA;
            stg[(q + 1) * 132 + mA]     = acc[a][p][1] * rnA + acA;
            stg[q * 132 + mA + 8]       = acc[a][p][2] * rnB + acB;
            stg[(q + 1) * 132 + mA + 8] = acc[a][p][3] * rnB + acB;
        }
    }
    __syncthreads();

    // top-5: 2 threads per query (512 thr / 256 q), shuffle merge
    {
        int q = tid >> 1, h = tid & 1;
        float tv[TOPK]; int ti[TOPK];
#pragma unroll
        for (int r = 0; r < TOPK; r++) { tv[r] = -3.4e38f; ti[r] = 0x7fffffff; }
        const float4* col = (const float4*)(stg + q * 132 + h * 64);
#pragma unroll 4
        for (int i = 0; i < 16; i++) {
            float4 v = col[i];
            int mb = m0 + h * 64 + i * 4;
            ins5(v.x, mb,     tv, ti);
            ins5(v.y, mb + 1, tv, ti);
            ins5(v.z, mb + 2, tv, ti);
            ins5(v.w, mb + 3, tv, ti);
        }
        float ov[TOPK]; int oi[TOPK];
#pragma unroll
        for (int r = 0; r < TOPK; r++) {
            ov[r] = __shfl_down_sync(0xffffffff, tv[r], 1);
            oi[r] = __shfl_down_sync(0xffffffff, ti[r], 1);
        }
        if (h == 0) {
#pragma unroll
            for (int r = 0; r < TOPK; r++) ins5(ov[r], oi[r], tv, ti);
            size_t base = ((size_t)blockIdx.x * B_Q + q) * TOPK;
#pragma unroll
            for (int r = 0; r < TOPK; r++) {
                g_cand_val[base + r] = tv[r];
                g_cand_idx[base + r] = ti[r];
            }
        }
    }
#undef LOAD_B
#undef STORE_A
}

// ---------------- kernel C: merge -> coarse top-16 pool ----------------
template <int K>
__device__ __forceinline__ void mergeK(float* av, int* ai, const float* bv, const int* bi) {
    float ov[K]; int oi[K];
    int ia = 0, ib = 0;
#pragma unroll
    for (int r = 0; r < K; r++) {
        bool ta = (ib >= K) || (ia < K && better(av[ia], ai[ia], bv[ib], bi[ib]));
        if (ta) { ov[r] = av[ia]; oi[r] = ai[ia]; ia++; }
        else    { ov[r] = bv[ib]; oi[r] = bi[ib]; ib++; }
    }
#pragma unroll
    for (int r = 0; r < K; r++) { av[r] = ov[r]; ai[r] = oi[r]; }
}

__global__ void k_merge() {
    const int q = blockIdx.x, tid = threadIdx.x;
    float tv[KC]; int ti[KC];
#pragma unroll
    for (int r = 0; r < KC; r++) { tv[r] = -3.4e38f; ti[r] = 0x7fffffff; }
    for (int s = tid; s < NSLAB; s += 256) {
        size_t base = ((size_t)s * B_Q + q) * TOPK;
#pragma unroll
        for (int r = 0; r < TOPK; r++)
            insK<KC>(g_cand_val[base + r], g_cand_idx[base + r], tv, ti);
    }
    __shared__ float sv[256][KC];
    __shared__ int   si[256][KC];
#pragma unroll
    for (int r = 0; r < KC; r++) { sv[tid][r] = tv[r]; si[tid][r] = ti[r]; }
    __syncthreads();
    for (int o = 128; o > 0; o >>= 1) {
        if (tid < o) mergeK<KC>(sv[tid], si[tid], sv[tid + o], si[tid + o]);
        __syncthreads();
    }
    if (tid < KC) g_cand16[q * KC + tid] = si[0][tid];
}

// ---------------- kernel C2: exact fp32 refine of 16 candidates -> top-5 ----------------
__global__ __launch_bounds__(128) void k_refine(const float* __restrict__ query,
                                                const float* __restrict__ mem) {
    __shared__ float qv[D_DIM];
    __shared__ float s_part[4];
    __shared__ float sims[KC];
    const int q = blockIdx.x, tid = threadIdx.x;
    const int lane = tid & 31, wr = tid >> 5;

    for (int d = tid; d < D_DIM; d += 128) qv[d] = query[(size_t)q * D_DIM + d];
    float p = 0.f;
    for (int d = tid; d < D_DIM; d += 128) {
        float v = query[(size_t)q * D_DIM + d];
        p += v * v;
    }
#pragma unroll
    for (int o = 16; o > 0; o >>= 1) p += __shfl_xor_sync(0xffffffff, p, o);
    if (lane == 0) s_part[wr] = p;
    __syncthreads();
    float rq = 1.0f / fmaxf(sqrtf(s_part[0] + s_part[1] + s_part[2] + s_part[3]), 1e-8f);

    for (int c = wr; c < KC; c += 4) {
        int mi = g_cand16[q * KC + c];
        const float* mv = mem + (size_t)mi * D_DIM;
        float dot = 0.f, msq = 0.f;
        for (int d = lane; d < D_DIM; d += 32) {
            float m = mv[d];
            dot += qv[d] * m;
            msq += m * m;
        }
#pragma unroll
        for (int o = 16; o > 0; o >>= 1) {
            dot += __shfl_xor_sync(0xffffffff, dot, o);
            msq += __shfl_xor_sync(0xffffffff, msq, o);
        }
        if (lane == 0)
            sims[c] = dot * rq / fmaxf(sqrtf(msq), 1e-8f) + g_act[mi];
    }
    __syncthreads();

    if (tid == 0) {
        float tv[TOPK]; int ti[TOPK];
#pragma unroll
        for (int r = 0; r < TOPK; r++) { tv[r] = -3.4e38f; ti[r] = 0x7fffffff; }
        for (int c = 0; c < KC; c++)
            ins5(sims[c], g_cand16[q * KC + c], tv, ti);
#pragma unroll
        for (int r = 0; r < TOPK; r++)
            g_topk[q * TOPK + r] = ti[r];
    }
}

// ---------------- kernel D1: x_proj + gate GEMM [1536 x 1024 x 384], fused h0 ----------------
#define XP_AHI 0
#define XP_ALO 34816
#define XP_BHI 69632
#define XP_BLO 104448
#define XP_SMEM 139264

__global__ __launch_bounds__(256, 1) void k_xproj(
    const float* __restrict__ query, const float* __restrict__ mem,
    const float* __restrict__ bih, const float* __restrict__ gb,
    const float* __restrict__ bhh)
{
    extern __shared__ char smem[];
    const uint32_t sb = smem_u32(smem);
    const int tid = threadIdx.x, l = tid & 31, w = tid >> 5;
    const int wm = w & 3, wn = w >> 2;
    const int bm = blockIdx.x, bn = blockIdx.y;

    const int lrow = tid >> 1, kh = tid & 1;
    int r = bm * 128 + lrow;
    int t = r >> 8, q = r & 255;
    const float* aptr;
    if (t == 0) aptr = query + (size_t)q * D_DIM;
    else        aptr = mem + (size_t)g_topk[q * TOPK + t - 1] * D_DIM;
    aptr += kh * 64;

    float acc[2][8][4];
#pragma unroll
    for (int a = 0; a < 2; a++)
#pragma unroll
        for (int p = 0; p < 8; p++)
#pragma unroll
            for (int rr = 0; rr < 4; rr++) acc[a][p][rr] = 0.f;

#pragma unroll 1
    for (int c = 0; c < 3; c++) {
        __syncthreads();
#pragma unroll
        for (int i = 0; i < 8; i++) {
            int idx = i * 256 + tid;
            int row = idx >> 4, s = idx & 15;
            uint32_t d = sb + (uint32_t)(row * 272 + s * 16);
            size_t go = (size_t)(bn * 128 + row) * D_DIM + c * 128 + s * 8;
            CPA16(d + XP_BHI, (const void*)(g_wcat_h + go));
            CPA16(d + XP_BLO, (const void*)(g_wcat_l + go));
        }
        CPA_COMMIT();
        {
            char* ah = smem + XP_AHI;
            char* al = smem + XP_ALO;
            const float4* src = (const float4*)(aptr + c * 128);
#pragma unroll
            for (int i = 0; i < 16; i++) {
                float4 v = src[i];
                uint32_t h0, l0, h1, l1;
                splt2(v.x, v.y, h0, l0);
                splt2(v.z, v.w, h1, l1);
                uint32_t so = (uint32_t)(lrow * 272 + kh * 128 + i * 8);
                *(uint2*)(ah + so) = make_uint2(h0, h1);
                *(uint2*)(al + so) = make_uint2(l0, l1);
            }
        }
        CPA_WAIT0();
        __syncthreads();

        const uint32_t aB = sb + XP_AHI + (uint32_t)((wm * 32 + (l & 15)) * 272 + (l >> 4) * 16);
        const uint32_t bB = sb + XP_BHI + (uint32_t)((wn * 64 + (l & 15)) * 272 + (l >> 4) * 16);
#pragma unroll 1
        for (int kk = 0; kk < 8; kk++) {
            uint32_t bh[16], bl[16];
#pragma unroll
            for (int pp = 0; pp < 4; pp++) {
                uint32_t ba = bB + (uint32_t)(pp * 16 * 272 + kk * 32);
                ldsm4(bh + pp * 4, ba);
                ldsm4(bl + pp * 4, ba + (XP_BLO - XP_BHI));
            }
#pragma unroll
            for (int a = 0; a < 2; a++) {
                uint32_t ah4[4], al4[4];
                uint32_t aa = aB + (uint32_t)(a * 16 * 272 + kk * 32);
                ldsm4(ah4, aa);
                ldsm4(al4, aa + (XP_ALO - XP_AHI));
#pragma unroll
                for (int p = 0; p < 8; p++) {
                    int pp = p >> 1, hi = p & 1;
                    mma16816(acc[a][p], ah4, bh[pp * 4 + hi], bh[pp * 4 + hi + 2]);
                    mma16816(acc[a][p], ah4, bl[pp * 4 + hi], bl[pp * 4 + hi + 2]);
                    mma16816(acc[a][p], al4, bh[pp * 4 + hi], bh[pp * 4 + hi + 2]);
                }
            }
        }
    }

    const bool fuse_h0 = (bm < 2) && (bn < 4);   // t==0 rows, h-columns
#pragma unroll
    for (int a = 0; a < 2; a++) {
        int rA = bm * 128 + wm * 32 + a * 16 + (l >> 2);
#pragma unroll
        for (int p = 0; p < 8; p++) {
            int cg = bn * 128 + wn * 64 + p * 8 + (l & 3) * 2;
            float b0 = (cg < 512) ? bih[cg] : gb[cg - 512];
            float b1 = (cg < 512) ? bih[cg + 1] : gb[cg + 1 - 512];
            float v00 = acc[a][p][0] + b0, v01 = acc[a][p][1] + b1;
            float v10 = acc[a][p][2] + b0, v11 = acc[a][p][3] + b1;
            g_xp[(size_t)rA * 1024 + cg]           = v00;
            g_xp[(size_t)rA * 1024 + cg + 1]       = v01;
            g_xp[(size_t)(rA + 8) * 1024 + cg]     = v10;
            g_xp[(size_t)(rA + 8) * 1024 + cg + 1] = v11;
            if (fuse_h0) {
                float bh0 = bhh[cg], bh1 = bhh[cg + 1];
                float h00 = tanhf(v00 + bh0), h01 = tanhf(v01 + bh1);
                float h10 = tanhf(v10 + bh0), h11 = tanhf(v11 + bh1);
                size_t o0 = (size_t)rA * H_DIM + cg;
                size_t o1 = (size_t)(rA + 8) * H_DIM + cg;
                g_hf[o0] = h00; g_hf[o0 + 1] = h01;
                g_hf[o1] = h10; g_hf[o1 + 1] = h11;
                __nv_bfloat16 q00 = __float2bfloat16(h00), q01 = __float2bfloat16(h01);
                __nv_bfloat16 q10 = __float2bfloat16(h10), q11 = __float2bfloat16(h11);
                g_hbh[0][o0] = q00; g_hbh[0][o0 + 1] = q01;
                g_hbh[0][o1] = q10; g_hbh[0][o1 + 1] = q11;
                g_hbl[0][o0] = __float2bfloat16(h00 - __bfloat162float(q00));
                g_hbl[0][o0 + 1] = __float2bfloat16(h01 - __bfloat162float(q01));
                g_hbl[0][o1] = __float2bfloat16(h10 - __bfloat162float(q10));
                g_hbl[0][o1 + 1] = __float2bfloat16(h11 - __bfloat162float(q11));
            }
        }
    }
}

// ---------------- kernel D3: recurrence step GEMM, 32 CTAs, double-buffered ----------------
#define ST2_AHI 0
#define ST2_ALO 17408
#define ST2_BHI 34816
#define ST2_BLO 52224
#define ST2_STG 69632
#define ST2_SMEM (2 * ST2_STG)   // 139264

__global__ __launch_bounds__(256, 1) void k_step(int t, const float* __restrict__ bhh) {
    extern __shared__ char smem[];
    const uint32_t sb = smem_u32(smem);
    const int tid = threadIdx.x, l = tid & 31, w = tid >> 5;
    const int wm = w & 3, wn = w >> 2;   // warp tile 16 x 32
    const int mt = blockIdx.x, nt = blockIdx.y;   // (4, 8)
    const int bin = (t + 1) & 1, bout = t & 1;
    const __nv_bfloat16* Ah = g_hbh[bin];
    const __nv_bfloat16* Al = g_hbl[bin];

    float acc[4][4];
#pragma unroll
    for (int p = 0; p < 4; p++)
#pragma unroll
        for (int rr = 0; rr < 4; rr++) acc[p][rr] = 0.f;

#define ST_LOAD(cc) do {                                                      \
    uint32_t stn = sb + ((cc) & 1) * ST2_STG;                                 \
    _Pragma("unroll")                                                         \
    for (int i = 0; i < 4; i++) {                                             \
        int idx = i * 256 + tid;                                              \
        int row = idx >> 4, s = idx & 15;                                     \
        uint32_t d = stn + (uint32_t)(row * 272 + s * 16);                    \
        size_t goA = (size_t)(mt * 64 + row) * H_DIM + (cc) * 128 + s * 8;    \
        size_t goB = (size_t)(nt * 64 + row) * H_DIM + (cc) * 128 + s * 8;    \
        CPA16(d + ST2_AHI, (const void*)(Ah + goA));                          \
        CPA16(d + ST2_ALO, (const void*)(Al + goA));                          \
        CPA16(d + ST2_BHI, (const void*)(g_whh_h + goB));                     \
        CPA16(d + ST2_BLO, (const void*)(g_whh_l + goB));                     \
    }                                                                         \
    CPA_COMMIT();                                                             \
} while (0)

    ST_LOAD(0);

#pragma unroll 1
    for (int c = 0; c < 4; c++) {
        __syncthreads();
        if (c < 3) ST_LOAD(c + 1);
        if (c < 3) CPA_WAIT1(); else CPA_WAIT0();
        __syncthreads();

        const uint32_t st = sb + (c & 1) * ST2_STG;
        const uint32_t aB = st + ST2_AHI + (uint32_t)((wm * 16 + (l & 15)) * 272 + (l >> 4) * 16);
        const uint32_t bB = st + ST2_BHI + (uint32_t)((wn * 32 + (l & 15)) * 272 + (l >> 4) * 16);
#pragma unroll 1
        for (int kk = 0; kk < 8; kk++) {
            uint32_t bh[8], bl[8];
#pragma unroll
            for (int pp = 0; pp < 2; pp++) {
                uint32_t ba = bB + (uint32_t)(pp * 16 * 272 + kk * 32);
                ldsm4(bh + pp * 4, ba);
                ldsm4(bl + pp * 4, ba + (ST2_BLO - ST2_BHI));
            }
            uint32_t ah4[4], al4[4];
            ldsm4(ah4, aB + (uint32_t)(kk * 32));
            ldsm4(al4, aB + (uint32_t)(kk * 32) + (ST2_ALO - ST2_AHI));
#pragma unroll
            for (int p = 0; p < 4; p++) {
                int pp = p >> 1, hi = p & 1;
                mma16816(acc[p], ah4, bh[pp * 4 + hi], bh[pp * 4 + hi + 2]);
                mma16816(acc[p], ah4, bl[pp * 4 + hi], bl[pp * 4 + hi + 2]);
                mma16816(acc[p], al4, bh[pp * 4 + hi], bh[pp * 4 + hi + 2]);
            }
        }
    }

    int q0 = mt * 64 + wm * 16 + (l >> 2);
#pragma unroll
    for (int p = 0; p < 4; p++) {
        int h = nt * 64 + wn * 32 + p * 8 + (l & 3) * 2;
#pragma unroll
        for (int rr = 0; rr < 4; rr++) {
            int qq = q0 + ((rr >> 1) ? 8 : 0);
            int hh = h + (rr & 1);
            float v = acc[p][rr] + g_xp[(size_t)(t * 256 + qq) * 1024 + hh] + bhh[hh];
            float ht = tanhf(v);
            size_t o = (size_t)qq * H_DIM + hh;
            g_hf[o] = ht;
            __nv_bfloat16 hb = __float2bfloat16(ht);
            g_hbh[bout][o] = hb;
            g_hbl[bout][o] = __float2bfloat16(ht - __bfloat162float(hb));
        }
    }
#undef ST_LOAD
}

// ---------------- kernel D4: output gate mix ----------------
__global__ void k_out(float* __restrict__ out) {
    int i = blockIdx.x * blockDim.x + threadIdx.x;
    int q = i >> 9, h = i & 511;
    float gpre = g_xp[(size_t)q * 1024 + 512 + h];
    float g = 1.0f / (1.0f + expf(-gpre));
    float proj = g_xp[(size_t)q * 1024 + h];
    out[i] = g * g_hf[i] + (1.0f - g) * proj;
}

// ---------------- launch ----------------
extern "C" void kernel_launch(void* const* d_in, const int* in_sizes, int n_in,
                              void* d_out, int out_size) {
    const float* query  = (const float*)d_in[0];
    const float* mem    = (const float*)d_in[1];
    const float* coords = (const float*)d_in[2];
    const float* sw     = (const float*)d_in[3];
    const float* Wih    = (const float*)d_in[4];
    const float* bih    = (const float*)d_in[5];
    const float* Whh    = (const float*)d_in[6];
    const float* bhh    = (const float*)d_in[7];
    const float* gW     = (const float*)d_in[8];
    const float* gb     = (const float*)d_in[9];
    float* out = (float*)d_out;

    cudaFuncSetAttribute(k_sims_mma, cudaFuncAttributeMaxDynamicSharedMemorySize, SIMS_SMEM);
    cudaFuncSetAttribute(k_xproj,    cudaFuncAttributeMaxDynamicSharedMemorySize, XP_SMEM);
    cudaFuncSetAttribute(k_step,     cudaFuncAttributeMaxDynamicSharedMemorySize, ST2_SMEM);

    // k_sims as launch #4 -> lands in the ncu capture window (as in R9)
    k_center<<<1, 256>>>(sw);
    k_act<<<(M_MEM + 255) / 256, 256>>>(coords);
    k_qnorm<<<B_Q, 128>>>(query);
    k_sims_mma<<<NSLAB, 512, SIMS_SMEM>>>(mem);
    k_prep<<<(H_DIM * H_DIM + 1024 * D_DIM + 255) / 256, 256>>>(Whh, Wih, gW);
    k_merge<<<B_Q, 256>>>();
    k_refine<<<B_Q, 128>>>(query, mem);
    k_xproj<<<dim3(12, 8), 256, XP_SMEM>>>(query, mem, bih, gb, bhh);
    for (int t = 1; t <= TOPK; t++)
        k_step<<<dim3(4, 8), 256, ST2_SMEM>>>(t, bhh);
    k_out<<<(B_Q * H_DIM) / 256, 256>>>(out);
}

// round 11
// speedup vs baseline: 1.4807x; 1.0448x over previous
#include <cuda_runtime.h>
#include <cuda_bf16.h>
#include <math.h>
#include <stdint.h>

// Problem constants
#define B_Q   256
#define M_MEM 200000
#define D_DIM 384
#define H_DIM 512
#define TOPK  5
#define KC    16
#define TM    128
#define NSLAB ((M_MEM + TM - 1) / TM)   // 1563

// ---------------- device scratch ----------------
__device__ float g_center[2];
__device__ float g_act[M_MEM];
__device__ __align__(16) __nv_bfloat16 g_qhi[B_Q * D_DIM];
__device__ float g_cand_val[(size_t)NSLAB * B_Q * TOPK];
__device__ int   g_cand_idx[(size_t)NSLAB * B_Q * TOPK];
__device__ int   g_topk[B_Q * TOPK];
// RNN path scratch
__device__ __align__(16) __nv_bfloat16 g_whh_h[H_DIM * H_DIM];
__device__ __align__(16) __nv_bfloat16 g_whh_l[H_DIM * H_DIM];
__device__ __align__(16) __nv_bfloat16 g_wcat_h[1024 * D_DIM];
__device__ __align__(16) __nv_bfloat16 g_wcat_l[1024 * D_DIM];
__device__ float g_xp[1536 * 1024];
__device__ __align__(16) __nv_bfloat16 g_hbh[2][B_Q * H_DIM];
__device__ __align__(16) __nv_bfloat16 g_hbl[2][B_Q * H_DIM];
__device__ float g_hf[B_Q * H_DIM];

// ---------------- helpers ----------------
__device__ __forceinline__ uint32_t smem_u32(const void* p) {
    uint32_t a;
    asm("{ .reg .u64 t; cvta.to.shared.u64 t, %1; cvt.u32.u64 %0, t; }" : "=r"(a) : "l"(p));
    return a;
}
#define CPA16(s, g)  asm volatile("cp.async.cg.shared.global [%0], [%1], 16;" :: "r"(s), "l"(g) : "memory")
#define CPA_COMMIT() asm volatile("cp.async.commit_group;" ::: "memory")
#define CPA_WAIT0()  asm volatile("cp.async.wait_group 0;" ::: "memory")
#define CPA_WAIT1()  asm volatile("cp.async.wait_group 1;" ::: "memory")

__device__ __forceinline__ void ldsm4(uint32_t* r, uint32_t addr) {
    asm volatile("ldmatrix.sync.aligned.m8n8.x4.shared.b16 {%0,%1,%2,%3}, [%4];"
        : "=r"(r[0]), "=r"(r[1]), "=r"(r[2]), "=r"(r[3]) : "r"(addr));
}
__device__ __forceinline__ void mma16816(float* d, const uint32_t* a, uint32_t b0, uint32_t b1) {
    asm volatile("mma.sync.aligned.m16n8k16.row.col.f32.bf16.bf16.f32 "
        "{%0,%1,%2,%3}, {%4,%5,%6,%7}, {%8,%9}, {%0,%1,%2,%3};"
        : "+f"(d[0]), "+f"(d[1]), "+f"(d[2]), "+f"(d[3])
        : "r"(a[0]), "r"(a[1]), "r"(a[2]), "r"(a[3]), "r"(b0), "r"(b1));
}
__device__ __forceinline__ void splt2(float x, float y, uint32_t& hw, uint32_t& lw) {
    __nv_bfloat16 hx = __float2bfloat16(x), hy = __float2bfloat16(y);
    __nv_bfloat16 lx = __float2bfloat16(x - __bfloat162float(hx));
    __nv_bfloat16 ly = __float2bfloat16(y - __bfloat162float(hy));
    __nv_bfloat162 hp = __halves2bfloat162(hx, hy);
    __nv_bfloat162 lp = __halves2bfloat162(lx, ly);
    hw = *(uint32_t*)&hp; lw = *(uint32_t*)&lp;
}
__device__ __forceinline__ uint32_t pk2hi(float x, float y) {
    __nv_bfloat162 hp = __halves2bfloat162(__float2bfloat16(x), __float2bfloat16(y));
    return *(uint32_t*)&hp;
}

__device__ __forceinline__ bool better(float v, int i, float w, int j) {
    return (v > w) || (v == w && i < j);
}
template <int K>
__device__ __forceinline__ void insK(float v, int i, float* tv, int* ti) {
    if (!better(v, i, tv[K - 1], ti[K - 1])) return;
#pragma unroll
    for (int r = 0; r < K; r++) {
        if (better(v, i, tv[r], ti[r])) {
            float fv = tv[r]; int fi = ti[r];
            tv[r] = v; ti[r] = i;
            v = fv; i = fi;
        }
    }
}
#define ins5 insK<TOPK>

// ---------------- kernel A0: center ----------------
__global__ void k_center(const float* __restrict__ sw) {
    __shared__ float sx[256], sy[256];
    int tid = threadIdx.x;
    float x = 0.f, y = 0.f;
    for (int i = tid; i < H_DIM; i += 256) { x += sw[2 * i]; y += sw[2 * i + 1]; }
    sx[tid] = x; sy[tid] = y;
    __syncthreads();
    for (int o = 128; o > 0; o >>= 1) {
        if (tid < o) { sx[tid] += sx[tid + o]; sy[tid] += sy[tid + o]; }
        __syncthreads();
    }
    if (tid == 0) {
        g_center[0] = sx[0] / (float)H_DIM;
        g_center[1] = sy[0] / (float)H_DIM;
    }
}

// ---------------- kernel A1: activations ----------------
__global__ void k_act(const float* __restrict__ coords) {
    int i = blockIdx.x * blockDim.x + threadIdx.x;
    if (i < M_MEM) {
        float dx = coords[2 * i]     - g_center[0];
        float dy = coords[2 * i + 1] - g_center[1];
        g_act[i] = 1.0f / (1.0f + sqrtf(dx * dx + dy * dy));
    }
}

// ---------------- kernel A2: normalize queries -> bf16 hi ----------------
__global__ void k_qnorm(const float* __restrict__ q) {
    __shared__ float red[128];
    int b = blockIdx.x, tid = threadIdx.x;
    float s = 0.f;
    for (int d = tid; d < D_DIM; d += 128) {
        float v = q[(size_t)b * D_DIM + d];
        s += v * v;
    }
    red[tid] = s;
    __syncthreads();
    for (int o = 64; o > 0; o >>= 1) {
        if (tid < o) red[tid] += red[tid + o];
        __syncthreads();
    }
    float r = 1.0f / fmaxf(sqrtf(red[0]), 1e-8f);
    for (int d = tid; d < D_DIM; d += 128)
        g_qhi[(size_t)b * D_DIM + d] = __float2bfloat16(q[(size_t)b * D_DIM + d] * r);
}

// ---------------- kernel A3: weight split prep ----------------
__global__ void k_prep(const float* __restrict__ Whh, const float* __restrict__ Wih,
                       const float* __restrict__ gW) {
    int i = blockIdx.x * blockDim.x + threadIdx.x;
    if (i < H_DIM * H_DIM) {
        float v = Whh[i];
        __nv_bfloat16 h = __float2bfloat16(v);
        g_whh_h[i] = h;
        g_whh_l[i] = __float2bfloat16(v - __bfloat162float(h));
    } else if (i < H_DIM * H_DIM + 1024 * D_DIM) {
        int j = i - H_DIM * H_DIM;
        int row = j / D_DIM, col = j % D_DIM;
        float v = (row < 512) ? Wih[row * D_DIM + col] : gW[(row - 512) * D_DIM + col];
        __nv_bfloat16 h = __float2bfloat16(v);
        g_wcat_h[j] = h;
        g_wcat_l[j] = __float2bfloat16(v - __bfloat162float(h));
    }
}

// ---------------- kernel B: 1-term coarse sims, 128m x 256q, 512 threads ----------------
// chunk K=128 bf16 (256B/row, PADB=272). Stage: Ahi (128x272) | Bhi (256x272).
#define S2_B   34816
#define STG2   104448
#define HDR2   4096
#define SIMS_SMEM (HDR2 + 2 * STG2)   // 212992
#define E_STG  HDR2                   // 256 x 132 f32 = 135168

__global__ __launch_bounds__(512, 1) void k_sims_mma(const float* __restrict__ mem) {
    extern __shared__ char smem[];
    const uint32_t sb = smem_u32(smem);
    float* s_rn  = (float*)smem;                 // 128 f32
    float* s_act = (float*)(smem + 512);         // 128 f32
    float* s_red = (float*)(smem + 1024);        // 512 f32

    const int tid = threadIdx.x;
    const int l   = tid & 31;
    const int w   = tid >> 5;       // 0..15
    const int wm  = w & 3;          // m rows wm*32..+32
    const int wn  = w >> 2;         // queries wn*64..+64
    const int m0  = blockIdx.x * TM;

    if (tid < 128) {
        bool ok = (m0 + tid) < M_MEM;
        s_act[tid] = ok ? g_act[m0 + tid] : -1e30f;
    }

    float acc[2][8][4];
#pragma unroll
    for (int a = 0; a < 2; a++)
#pragma unroll
        for (int p = 0; p < 8; p++)
#pragma unroll
            for (int r = 0; r < 4; r++) acc[a][p][r] = 0.f;

    // A source: 4 threads per row, each quarter = 32 floats (8 float4)
    const int arow = tid >> 2, aq = tid & 3;
    int arg = m0 + arow; if (arg >= M_MEM) arg = M_MEM - 1;
    const float4* asrcq = (const float4*)(mem + (size_t)arg * D_DIM) + aq * 8;
    const uint32_t asts = (uint32_t)(arow * 272 + aq * 64);

    const uint32_t aoff = (uint32_t)((wm * 32 + (l & 15)) * 272 + (l >> 4) * 16);
    const uint32_t boff = S2_B + (uint32_t)((wn * 64 + (l & 15)) * 272 + (l >> 4) * 16);

    float nsq = 0.f;

#define LOAD_B(st, cc) do {                                                   \
    _Pragma("unroll")                                                         \
    for (int i = 0; i < 8; i++) {                                             \
        int idx = i * 512 + tid;                                              \
        int row = idx >> 4, s = idx & 15;                                     \
        size_t go = (size_t)row * D_DIM + (cc) * 128 + s * 8;                 \
        CPA16((st) + S2_B + (uint32_t)(row * 272 + s * 16),                   \
              (const void*)(g_qhi + go));                                     \
    }                                                                         \
    CPA_COMMIT();                                                             \
} while (0)

// load A chunk cc into registers and immediately convert+store (transient liveness)
#define LOADSTORE_A(sc, cc) do {                                              \
    float4 pf[8];                                                             \
    _Pragma("unroll")                                                         \
    for (int i = 0; i < 8; i++) pf[i] = asrcq[(cc) * 32 + i];                 \
    _Pragma("unroll")                                                         \
    for (int i = 0; i < 4; i++) {                                             \
        float4 v0 = pf[2 * i], v1 = pf[2 * i + 1];                            \
        nsq += v0.x * v0.x + v0.y * v0.y + v0.z * v0.z + v0.w * v0.w          \
             + v1.x * v1.x + v1.y * v1.y + v1.z * v1.z + v1.w * v1.w;         \
        uint32_t h0 = pk2hi(v0.x, v0.y), h1 = pk2hi(v0.z, v0.w);              \
        uint32_t h2 = pk2hi(v1.x, v1.y), h3 = pk2hi(v1.z, v1.w);              \
        *(uint4*)((sc) + asts + i * 16) = make_uint4(h0, h1, h2, h3);         \
    }                                                                         \
} while (0)

    // ---- prologue: chunks 0, 1 ----
    LOAD_B(sb + HDR2, 0);
    LOAD_B(sb + HDR2 + STG2, 1);
    LOADSTORE_A(smem + HDR2, 0);
    LOADSTORE_A(smem + HDR2 + STG2, 1);

#pragma unroll 1
    for (int c = 0; c < 3; c++) {
        const uint32_t st = sb + HDR2 + (c & 1) * STG2;
        if (c == 2) CPA_WAIT0(); else CPA_WAIT1();
        __syncthreads();

        const uint32_t aB = st + aoff;
        const uint32_t bB = st + boff;
#pragma unroll
        for (int kk = 0; kk < 8; kk++) {
            uint32_t bh[16];
#pragma unroll
            for (int pp = 0; pp < 4; pp++)
                ldsm4(bh + pp * 4, bB + (uint32_t)(pp * 16 * 272 + kk * 32));
#pragma unroll
            for (int a = 0; a < 2; a++) {
                uint32_t ah4[4];
                ldsm4(ah4, aB + (uint32_t)(a * 16 * 272 + kk * 32));
#pragma unroll
                for (int p = 0; p < 8; p++) {
                    int pp = p >> 1, hi = p & 1;
                    mma16816(acc[a][p], ah4, bh[pp * 4 + hi], bh[pp * 4 + hi + 2]);
                }
            }
        }

        if (c < 1) {
            __syncthreads();
            LOADSTORE_A(smem + HDR2 + (c & 1) * STG2, c + 2);
            LOAD_B(st, c + 2);
        }
    }

    // ---- norms reduce ----
    __syncthreads();
    s_red[tid] = nsq;
    __syncthreads();
    if (tid < 128) {
        float s = s_red[4 * tid] + s_red[4 * tid + 1] + s_red[4 * tid + 2] + s_red[4 * tid + 3];
        bool ok = (m0 + tid) < M_MEM;
        s_rn[tid] = ok ? 1.0f / fmaxf(sqrtf(s), 1e-8f) : 0.0f;
    }
    __syncthreads();

    // ---- epilogue: scale + bias, stage query-major (256 queries) ----
    float* stg = (float*)(smem + E_STG);
#pragma unroll
    for (int a = 0; a < 2; a++) {
        int mA = wm * 32 + a * 16 + (l >> 2);
        float rnA = s_rn[mA],     acA = s_act[mA];
        float rnB = s_rn[mA + 8], acB = s_act[mA + 8];
#pragma unroll
        for (int p = 0; p < 8; p++) {
            int q = wn * 64 + p * 8 + (l & 3) * 2;
            stg[q * 132 + mA]           = acc[a][p][0] * rnA + acA;
            stg[(q + 1) * 132 + mA]     = acc[a][p][1] * rnA + acA;
            stg[q * 132 + mA + 8]       = acc[a][p][2] * rnB + acB;
            stg[(q + 1) * 132 + mA + 8] = acc[a][p][3] * rnB + acB;
        }
    }
    __syncthreads();

    // top-5: 2 threads per query, shuffle merge
    {
        int q = tid >> 1, h = tid & 1;
        float tv[TOPK]; int ti[TOPK];
#pragma unroll
        for (int r = 0; r < TOPK; r++) { tv[r] = -3.4e38f; ti[r] = 0x7fffffff; }
        const float4* col = (const float4*)(stg + q * 132 + h * 64);
#pragma unroll 4
        for (int i = 0; i < 16; i++) {
            float4 v = col[i];
            int mb = m0 + h * 64 + i * 4;
            ins5(v.x, mb,     tv, ti);
            ins5(v.y, mb + 1, tv, ti);
            ins5(v.z, mb + 2, tv, ti);
            ins5(v.w, mb + 3, tv, ti);
        }
        float ov[TOPK]; int oi[TOPK];
#pragma unroll
        for (int r = 0; r < TOPK; r++) {
            ov[r] = __shfl_down_sync(0xffffffff, tv[r], 1);
            oi[r] = __shfl_down_sync(0xffffffff, ti[r], 1);
        }
        if (h == 0) {
#pragma unroll
            for (int r = 0; r < TOPK; r++) ins5(ov[r], oi[r], tv, ti);
            size_t base = ((size_t)blockIdx.x * B_Q + q) * TOPK;
#pragma unroll
            for (int r = 0; r < TOPK; r++) {
                g_cand_val[base + r] = tv[r];
                g_cand_idx[base + r] = ti[r];
            }
        }
    }
#undef LOAD_B
#undef LOADSTORE_A
}

// ---------------- kernel C: fused merge -> top-16 pool -> exact refine -> top-5 ----------------
template <int K>
__device__ __forceinline__ void mergeK(float* av, int* ai, const float* bv, const int* bi) {
    float ov[K]; int oi[K];
    int ia = 0, ib = 0;
#pragma unroll
    for (int r = 0; r < K; r++) {
        bool ta = (ib >= K) || (ia < K && better(av[ia], ai[ia], bv[ib], bi[ib]));
        if (ta) { ov[r] = av[ia]; oi[r] = ai[ia]; ia++; }
        else    { ov[r] = bv[ib]; oi[r] = bi[ib]; ib++; }
    }
#pragma unroll
    for (int r = 0; r < K; r++) { av[r] = ov[r]; ai[r] = oi[r]; }
}

__global__ __launch_bounds__(256) void k_mergeref(const float* __restrict__ query,
                                                 const float* __restrict__ mem) {
    __shared__ float sv[256][KC];
    __shared__ int   si[256][KC];
    __shared__ float qv[D_DIM];
    __shared__ float s_qn[8];
    __shared__ float s_sims[KC];

    const int q = blockIdx.x, tid = threadIdx.x;
    const int lane = tid & 31, wr = tid >> 5;   // 8 warps

    // phase 0: load query + norm (also warms qv for refine)
    float p = 0.f;
    for (int d = tid; d < D_DIM; d += 256) {
        float v = query[(size_t)q * D_DIM + d];
        qv[d] = v;
        p += v * v;
    }
#pragma unroll
    for (int o = 16; o > 0; o >>= 1) p += __shfl_xor_sync(0xffffffff, p, o);
    if (lane == 0) s_qn[wr] = p;

    // phase 1: merge slab candidates into coarse top-16
    float tv[KC]; int ti[KC];
#pragma unroll
    for (int r = 0; r < KC; r++) { tv[r] = -3.4e38f; ti[r] = 0x7fffffff; }
    for (int s = tid; s < NSLAB; s += 256) {
        size_t base = ((size_t)s * B_Q + q) * TOPK;
#pragma unroll
        for (int r = 0; r < TOPK; r++)
            insK<KC>(g_cand_val[base + r], g_cand_idx[base + r], tv, ti);
    }
#pragma unroll
    for (int r = 0; r < KC; r++) { sv[tid][r] = tv[r]; si[tid][r] = ti[r]; }
    __syncthreads();
    for (int o = 128; o > 0; o >>= 1) {
        if (tid < o) mergeK<KC>(sv[tid], si[tid], sv[tid + o], si[tid + o]);
        __syncthreads();
    }

    // phase 2: exact fp32 refine of the 16 candidates (2 per warp)
    float qs = 0.f;
#pragma unroll
    for (int i = 0; i < 8; i++) qs += s_qn[i];
    float rq = 1.0f / fmaxf(sqrtf(qs), 1e-8f);

    for (int c = wr; c < KC; c += 8) {
        int mi = si[0][c];
        const float* mv = mem + (size_t)mi * D_DIM;
        float dot = 0.f, msq = 0.f;
        for (int d = lane; d < D_DIM; d += 32) {
            float m = mv[d];
            dot += qv[d] * m;
            msq += m * m;
        }
#pragma unroll
        for (int o = 16; o > 0; o >>= 1) {
            dot += __shfl_xor_sync(0xffffffff, dot, o);
            msq += __shfl_xor_sync(0xffffffff, msq, o);
        }
        if (lane == 0)
            s_sims[c] = dot * rq / fmaxf(sqrtf(msq), 1e-8f) + g_act[mi];
    }
    __syncthreads();

    if (tid == 0) {
        float fv[TOPK]; int fi[TOPK];
#pragma unroll
        for (int r = 0; r < TOPK; r++) { fv[r] = -3.4e38f; fi[r] = 0x7fffffff; }
        for (int c = 0; c < KC; c++)
            ins5(s_sims[c], si[0][c], fv, fi);
#pragma unroll
        for (int r = 0; r < TOPK; r++)
            g_topk[q * TOPK + r] = fi[r];
    }
}

// ---------------- kernel D1: x_proj + gate GEMM [1536 x 1024 x 384], fused h0 ----------------
#define XP_AHI 0
#define XP_ALO 34816
#define XP_BHI 69632
#define XP_BLO 104448
#define XP_SMEM 139264

__global__ __launch_bounds__(256, 1) void k_xproj(
    const float* __restrict__ query, const float* __restrict__ mem,
    const float* __restrict__ bih, const float* __restrict__ gb,
    const float* __restrict__ bhh)
{
    extern __shared__ char smem[];
    const uint32_t sb = smem_u32(smem);
    const int tid = threadIdx.x, l = tid & 31, w = tid >> 5;
    const int wm = w & 3, wn = w >> 2;
    const int bm = blockIdx.x, bn = blockIdx.y;

    const int lrow = tid >> 1, kh = tid & 1;
    int r = bm * 128 + lrow;
    int t = r >> 8, q = r & 255;
    const float* aptr;
    if (t == 0) aptr = query + (size_t)q * D_DIM;
    else        aptr = mem + (size_t)g_topk[q * TOPK + t - 1] * D_DIM;
    aptr += kh * 64;

    float acc[2][8][4];
#pragma unroll
    for (int a = 0; a < 2; a++)
#pragma unroll
        for (int p = 0; p < 8; p++)
#pragma unroll
            for (int rr = 0; rr < 4; rr++) acc[a][p][rr] = 0.f;

#pragma unroll 1
    for (int c = 0; c < 3; c++) {
        __syncthreads();
#pragma unroll
        for (int i = 0; i < 8; i++) {
            int idx = i * 256 + tid;
            int row = idx >> 4, s = idx & 15;
            uint32_t d = sb + (uint32_t)(row * 272 + s * 16);
            size_t go = (size_t)(bn * 128 + row) * D_DIM + c * 128 + s * 8;
            CPA16(d + XP_BHI, (const void*)(g_wcat_h + go));
            CPA16(d + XP_BLO, (const void*)(g_wcat_l + go));
        }
        CPA_COMMIT();
        {
            char* ah = smem + XP_AHI;
            char* al = smem + XP_ALO;
            const float4* src = (const float4*)(aptr + c * 128);
#pragma unroll
            for (int i = 0; i < 16; i++) {
                float4 v = src[i];
                uint32_t h0, l0, h1, l1;
                splt2(v.x, v.y, h0, l0);
                splt2(v.z, v.w, h1, l1);
                uint32_t so = (uint32_t)(lrow * 272 + kh * 128 + i * 8);
                *(uint2*)(ah + so) = make_uint2(h0, h1);
                *(uint2*)(al + so) = make_uint2(l0, l1);
            }
        }
        CPA_WAIT0();
        __syncthreads();

        const uint32_t aB = sb + XP_AHI + (uint32_t)((wm * 32 + (l & 15)) * 272 + (l >> 4) * 16);
        const uint32_t bB = sb + XP_BHI + (uint32_t)((wn * 64 + (l & 15)) * 272 + (l >> 4) * 16);
#pragma unroll 1
        for (int kk = 0; kk < 8; kk++) {
            uint32_t bh[16], bl[16];
#pragma unroll
            for (int pp = 0; pp < 4; pp++) {
                uint32_t ba = bB + (uint32_t)(pp * 16 * 272 + kk * 32);
                ldsm4(bh + pp * 4, ba);
                ldsm4(bl + pp * 4, ba + (XP_BLO - XP_BHI));
            }
#pragma unroll
            for (int a = 0; a < 2; a++) {
                uint32_t ah4[4], al4[4];
                uint32_t aa = aB + (uint32_t)(a * 16 * 272 + kk * 32);
                ldsm4(ah4, aa);
                ldsm4(al4, aa + (XP_ALO - XP_AHI));
#pragma unroll
                for (int p = 0; p < 8; p++) {
                    int pp = p >> 1, hi = p & 1;
                    mma16816(acc[a][p], ah4, bh[pp * 4 + hi], bh[pp * 4 + hi + 2]);
                    mma16816(acc[a][p], ah4, bl[pp * 4 + hi], bl[pp * 4 + hi + 2]);
                    mma16816(acc[a][p], al4, bh[pp * 4 + hi], bh[pp * 4 + hi + 2]);
                }
            }
        }
    }

    const bool fuse_h0 = (bm < 2) && (bn < 4);   // t==0 rows, h-columns
#pragma unroll
    for (int a = 0; a < 2; a++) {
        int rA = bm * 128 + wm * 32 + a * 16 + (l >> 2);
#pragma unroll
        for (int p = 0; p < 8; p++) {
            int cg = bn * 128 + wn * 64 + p * 8 + (l & 3) * 2;
            float b0 = (cg < 512) ? bih[cg] : gb[cg - 512];
            float b1 = (cg < 512) ? bih[cg + 1] : gb[cg + 1 - 512];
            float v00 = acc[a][p][0] + b0, v01 = acc[a][p][1] + b1;
            float v10 = acc[a][p][2] + b0, v11 = acc[a][p][3] + b1;
            g_xp[(size_t)rA * 1024 + cg]           = v00;
            g_xp[(size_t)rA * 1024 + cg + 1]       = v01;
            g_xp[(size_t)(rA + 8) * 1024 + cg]     = v10;
            g_xp[(size_t)(rA + 8) * 1024 + cg + 1] = v11;
            if (fuse_h0) {
                float bh0 = bhh[cg], bh1 = bhh[cg + 1];
                float h00 = tanhf(v00 + bh0), h01 = tanhf(v01 + bh1);
                float h10 = tanhf(v10 + bh0), h11 = tanhf(v11 + bh1);
                size_t o0 = (size_t)rA * H_DIM + cg;
                size_t o1 = (size_t)(rA + 8) * H_DIM + cg;
                g_hf[o0] = h00; g_hf[o0 + 1] = h01;
                g_hf[o1] = h10; g_hf[o1 + 1] = h11;
                __nv_bfloat16 q00 = __float2bfloat16(h00), q01 = __float2bfloat16(h01);
                __nv_bfloat16 q10 = __float2bfloat16(h10), q11 = __float2bfloat16(h11);
                g_hbh[0][o0] = q00; g_hbh[0][o0 + 1] = q01;
                g_hbh[0][o1] = q10; g_hbh[0][o1 + 1] = q11;
                g_hbl[0][o0] = __float2bfloat16(h00 - __bfloat162float(q00));
                g_hbl[0][o0 + 1] = __float2bfloat16(h01 - __bfloat162float(q01));
                g_hbl[0][o1] = __float2bfloat16(h10 - __bfloat162float(q10));
                g_hbl[0][o1 + 1] = __float2bfloat16(h11 - __bfloat162float(q11));
            }
        }
    }
}

// ---------------- kernel D3: recurrence step GEMM, 32 CTAs, double-buffered ----------------
#define ST2_AHI 0
#define ST2_ALO 17408
#define ST2_BHI 34816
#define ST2_BLO 52224
#define ST2_STG 69632
#define ST2_SMEM (2 * ST2_STG)   // 139264

__global__ __launch_bounds__(256, 1) void k_step(int t, const float* __restrict__ bhh) {
    extern __shared__ char smem[];
    const uint32_t sb = smem_u32(smem);
    const int tid = threadIdx.x, l = tid & 31, w = tid >> 5;
    const int wm = w & 3, wn = w >> 2;   // warp tile 16 x 32
    const int mt = blockIdx.x, nt = blockIdx.y;   // (4, 8)
    const int bin = (t + 1) & 1, bout = t & 1;
    const __nv_bfloat16* Ah = g_hbh[bin];
    const __nv_bfloat16* Al = g_hbl[bin];

    float acc[4][4];
#pragma unroll
    for (int p = 0; p < 4; p++)
#pragma unroll
        for (int rr = 0; rr < 4; rr++) acc[p][rr] = 0.f;

#define ST_LOAD(cc) do {                                                      \
    uint32_t stn = sb + ((cc) & 1) * ST2_STG;                                 \
    _Pragma("unroll")                                                         \
    for (int i = 0; i < 4; i++) {                                             \
        int idx = i * 256 + tid;                                              \
        int row = idx >> 4, s = idx & 15;                                     \
        uint32_t d = stn + (uint32_t)(row * 272 + s * 16);                    \
        size_t goA = (size_t)(mt * 64 + row) * H_DIM + (cc) * 128 + s * 8;    \
        size_t goB = (size_t)(nt * 64 + row) * H_DIM + (cc) * 128 + s * 8;    \
        CPA16(d + ST2_AHI, (const void*)(Ah + goA));                          \
        CPA16(d + ST2_ALO, (const void*)(Al + goA));                          \
        CPA16(d + ST2_BHI, (const void*)(g_whh_h + goB));                     \
        CPA16(d + ST2_BLO, (const void*)(g_whh_l + goB));                     \
    }                                                                         \
    CPA_COMMIT();                                                             \
} while (0)

    ST_LOAD(0);

#pragma unroll 1
    for (int c = 0; c < 4; c++) {
        __syncthreads();
        if (c < 3) ST_LOAD(c + 1);
        if (c < 3) CPA_WAIT1(); else CPA_WAIT0();
        __syncthreads();

        const uint32_t st = sb + (c & 1) * ST2_STG;
        const uint32_t aB = st + ST2_AHI + (uint32_t)((wm * 16 + (l & 15)) * 272 + (l >> 4) * 16);
        const uint32_t bB = st + ST2_BHI + (uint32_t)((wn * 32 + (l & 15)) * 272 + (l >> 4) * 16);
#pragma unroll 1
        for (int kk = 0; kk < 8; kk++) {
            uint32_t bh[8], bl[8];
#pragma unroll
            for (int pp = 0; pp < 2; pp++) {
                uint32_t ba = bB + (uint32_t)(pp * 16 * 272 + kk * 32);
                ldsm4(bh + pp * 4, ba);
                ldsm4(bl + pp * 4, ba + (ST2_BLO - ST2_BHI));
            }
            uint32_t ah4[4], al4[4];
            ldsm4(ah4, aB + (uint32_t)(kk * 32));
            ldsm4(al4, aB + (uint32_t)(kk * 32) + (ST2_ALO - ST2_AHI));
#pragma unroll
            for (int p = 0; p < 4; p++) {
                int pp = p >> 1, hi = p & 1;
                mma16816(acc[p], ah4, bh[pp * 4 + hi], bh[pp * 4 + hi + 2]);
                mma16816(acc[p], ah4, bl[pp * 4 + hi], bl[pp * 4 + hi + 2]);
                mma16816(acc[p], al4, bh[pp * 4 + hi], bh[pp * 4 + hi + 2]);
            }
        }
    }

    int q0 = mt * 64 + wm * 16 + (l >> 2);
#pragma unroll
    for (int p = 0; p < 4; p++) {
        int h = nt * 64 + wn * 32 + p * 8 + (l & 3) * 2;
#pragma unroll
        for (int rr = 0; rr < 4; rr++) {
            int qq = q0 + ((rr >> 1) ? 8 : 0);
            int hh = h + (rr & 1);
            float v = acc[p][rr] + g_xp[(size_t)(t * 256 + qq) * 1024 + hh] + bhh[hh];
            float ht = tanhf(v);
            size_t o = (size_t)qq * H_DIM + hh;
            g_hf[o] = ht;
            __nv_bfloat16 hb = __float2bfloat16(ht);
            g_hbh[bout][o] = hb;
            g_hbl[bout][o] = __float2bfloat16(ht - __bfloat162float(hb));
        }
    }
#undef ST_LOAD
}

// ---------------- kernel D4: output gate mix ----------------
__global__ void k_out(float* __restrict__ out) {
    int i = blockIdx.x * blockDim.x + threadIdx.x;
    int q = i >> 9, h = i & 511;
    float gpre = g_xp[(size_t)q * 1024 + 512 + h];
    float g = 1.0f / (1.0f + expf(-gpre));
    float proj = g_xp[(size_t)q * 1024 + h];
    out[i] = g * g_hf[i] + (1.0f - g) * proj;
}

// ---------------- launch ----------------
extern "C" void kernel_launch(void* const* d_in, const int* in_sizes, int n_in,
                              void* d_out, int out_size) {
    const float* query  = (const float*)d_in[0];
    const float* mem    = (const float*)d_in[1];
    const float* coords = (const float*)d_in[2];
    const float* sw     = (const float*)d_in[3];
    const float* Wih    = (const float*)d_in[4];
    const float* bih    = (const float*)d_in[5];
    const float* Whh    = (const float*)d_in[6];
    const float* bhh    = (const float*)d_in[7];
    const float* gW     = (const float*)d_in[8];
    const float* gb     = (const float*)d_in[9];
    float* out = (float*)d_out;

    cudaFuncSetAttribute(k_sims_mma, cudaFuncAttributeMaxDynamicSharedMemorySize, SIMS_SMEM);
    cudaFuncSetAttribute(k_xproj,    cudaFuncAttributeMaxDynamicSharedMemorySize, XP_SMEM);
    cudaFuncSetAttribute(k_step,     cudaFuncAttributeMaxDynamicSharedMemorySize, ST2_SMEM);

    // k_sims as launch #4 -> lands in the ncu capture window
    k_center<<<1, 256>>>(sw);
    k_act<<<(M_MEM + 255) / 256, 256>>>(coords);
    k_qnorm<<<B_Q, 128>>>(query);
    k_sims_mma<<<NSLAB, 512, SIMS_SMEM>>>(mem);
    k_prep<<<(H_DIM * H_DIM + 1024 * D_DIM + 255) / 256, 256>>>(Whh, Wih, gW);
    k_mergeref<<<B_Q, 256>>>(query, mem);
    k_xproj<<<dim3(12, 8), 256, XP_SMEM>>>(query, mem, bih, gb, bhh);
    for (int t = 1; t <= TOPK; t++)
        k_step<<<dim3(4, 8), 256, ST2_SMEM>>>(t, bhh);
    k_out<<<(B_Q * H_DIM) / 256, 256>>>(out);
}

// round 12
// speedup vs baseline: 1.6475x; 1.1126x over previous
#include <cuda_runtime.h>
#include <cuda_bf16.h>
#include <math.h>
#include <stdint.h>

// Problem constants
#define B_Q   256
#define M_MEM 200000
#define D_DIM 384
#define H_DIM 512
#define TOPK  5
#define KC    16
#define TM    128
#define NSLAB ((M_MEM + TM - 1) / TM)   // 1563

// ---------------- device scratch ----------------
__device__ float g_center[2];
__device__ float g_act[M_MEM];
__device__ __align__(16) __nv_bfloat16 g_qhi[B_Q * D_DIM];
__device__ float g_cand_val[(size_t)NSLAB * B_Q * TOPK];
__device__ int   g_cand_idx[(size_t)NSLAB * B_Q * TOPK];
__device__ int   g_topk[B_Q * TOPK];
// RNN path scratch
__device__ __align__(16) __nv_bfloat16 g_whh_h[H_DIM * H_DIM];
__device__ __align__(16) __nv_bfloat16 g_whh_l[H_DIM * H_DIM];
__device__ __align__(16) __nv_bfloat16 g_wcat_h[1024 * D_DIM];
__device__ __align__(16) __nv_bfloat16 g_wcat_l[1024 * D_DIM];
__device__ float g_xp[1536 * 1024];
__device__ __align__(16) __nv_bfloat16 g_hbh[2][B_Q * H_DIM];
__device__ __align__(16) __nv_bfloat16 g_hbl[2][B_Q * H_DIM];
__device__ float g_hf[B_Q * H_DIM];

// ---------------- helpers ----------------
__device__ __forceinline__ uint32_t smem_u32(const void* p) {
    uint32_t a;
    asm("{ .reg .u64 t; cvta.to.shared.u64 t, %1; cvt.u32.u64 %0, t; }" : "=r"(a) : "l"(p));
    return a;
}
#define CPA16(s, g)  asm volatile("cp.async.cg.shared.global [%0], [%1], 16;" :: "r"(s), "l"(g) : "memory")
#define CPA_COMMIT() asm volatile("cp.async.commit_group;" ::: "memory")
#define CPA_WAIT0()  asm volatile("cp.async.wait_group 0;" ::: "memory")
#define CPA_WAIT1()  asm volatile("cp.async.wait_group 1;" ::: "memory")

__device__ __forceinline__ void ldsm4(uint32_t* r, uint32_t addr) {
    asm volatile("ldmatrix.sync.aligned.m8n8.x4.shared.b16 {%0,%1,%2,%3}, [%4];"
        : "=r"(r[0]), "=r"(r[1]), "=r"(r[2]), "=r"(r[3]) : "r"(addr));
}
__device__ __forceinline__ void mma16816(float* d, const uint32_t* a, uint32_t b0, uint32_t b1) {
    asm volatile("mma.sync.aligned.m16n8k16.row.col.f32.bf16.bf16.f32 "
        "{%0,%1,%2,%3}, {%4,%5,%6,%7}, {%8,%9}, {%0,%1,%2,%3};"
        : "+f"(d[0]), "+f"(d[1]), "+f"(d[2]), "+f"(d[3])
        : "r"(a[0]), "r"(a[1]), "r"(a[2]), "r"(a[3]), "r"(b0), "r"(b1));
}
__device__ __forceinline__ void splt2(float x, float y, uint32_t& hw, uint32_t& lw) {
    __nv_bfloat16 hx = __float2bfloat16(x), hy = __float2bfloat16(y);
    __nv_bfloat16 lx = __float2bfloat16(x - __bfloat162float(hx));
    __nv_bfloat16 ly = __float2bfloat16(y - __bfloat162float(hy));
    __nv_bfloat162 hp = __halves2bfloat162(hx, hy);
    __nv_bfloat162 lp = __halves2bfloat162(lx, ly);
    hw = *(uint32_t*)&hp; lw = *(uint32_t*)&lp;
}
__device__ __forceinline__ uint32_t pk2hi(float x, float y) {
    __nv_bfloat162 hp = __halves2bfloat162(__float2bfloat16(x), __float2bfloat16(y));
    return *(uint32_t*)&hp;
}

__device__ __forceinline__ bool better(float v, int i, float w, int j) {
    return (v > w) || (v == w && i < j);
}
template <int K>
__device__ __forceinline__ void insK(float v, int i, float* tv, int* ti) {
    if (!better(v, i, tv[K - 1], ti[K - 1])) return;
#pragma unroll
    for (int r = 0; r < K; r++) {
        if (better(v, i, tv[r], ti[r])) {
            float fv = tv[r]; int fi = ti[r];
            tv[r] = v; ti[r] = i;
            v = fv; i = fi;
        }
    }
}
#define ins5 insK<TOPK>

// ---------------- kernel A0: center ----------------
__global__ void k_center(const float* __restrict__ sw) {
    __shared__ float sx[256], sy[256];
    int tid = threadIdx.x;
    float x = 0.f, y = 0.f;
    for (int i = tid; i < H_DIM; i += 256) { x += sw[2 * i]; y += sw[2 * i + 1]; }
    sx[tid] = x; sy[tid] = y;
    __syncthreads();
    for (int o = 128; o > 0; o >>= 1) {
        if (tid < o) { sx[tid] += sx[tid + o]; sy[tid] += sy[tid + o]; }
        __syncthreads();
    }
    if (tid == 0) {
        g_center[0] = sx[0] / (float)H_DIM;
        g_center[1] = sy[0] / (float)H_DIM;
    }
}

// ---------------- kernel A1: activations ----------------
__global__ void k_act(const float* __restrict__ coords) {
    int i = blockIdx.x * blockDim.x + threadIdx.x;
    if (i < M_MEM) {
        float dx = coords[2 * i]     - g_center[0];
        float dy = coords[2 * i + 1] - g_center[1];
        g_act[i] = 1.0f / (1.0f + sqrtf(dx * dx + dy * dy));
    }
}

// ---------------- kernel A2: normalize queries -> bf16 hi ----------------
__global__ void k_qnorm(const float* __restrict__ q) {
    __shared__ float red[128];
    int b = blockIdx.x, tid = threadIdx.x;
    float s = 0.f;
    for (int d = tid; d < D_DIM; d += 128) {
        float v = q[(size_t)b * D_DIM + d];
        s += v * v;
    }
    red[tid] = s;
    __syncthreads();
    for (int o = 64; o > 0; o >>= 1) {
        if (tid < o) red[tid] += red[tid + o];
        __syncthreads();
    }
    float r = 1.0f / fmaxf(sqrtf(red[0]), 1e-8f);
    for (int d = tid; d < D_DIM; d += 128)
        g_qhi[(size_t)b * D_DIM + d] = __float2bfloat16(q[(size_t)b * D_DIM + d] * r);
}

// ---------------- kernel A3: weight split prep ----------------
__global__ void k_prep(const float* __restrict__ Whh, const float* __restrict__ Wih,
                       const float* __restrict__ gW) {
    int i = blockIdx.x * blockDim.x + threadIdx.x;
    if (i < H_DIM * H_DIM) {
        float v = Whh[i];
        __nv_bfloat16 h = __float2bfloat16(v);
        g_whh_h[i] = h;
        g_whh_l[i] = __float2bfloat16(v - __bfloat162float(h));
    } else if (i < H_DIM * H_DIM + 1024 * D_DIM) {
        int j = i - H_DIM * H_DIM;
        int row = j / D_DIM, col = j % D_DIM;
        float v = (row < 512) ? Wih[row * D_DIM + col] : gW[(row - 512) * D_DIM + col];
        __nv_bfloat16 h = __float2bfloat16(v);
        g_wcat_h[j] = h;
        g_wcat_l[j] = __float2bfloat16(v - __bfloat162float(h));
    }
}

// ---------------- kernel B: 1-term coarse sims, coalesced A path ----------------
// chunk K=128 bf16 (256B/row, PADB=272). Stage: Ahi (128x272) | Bhi (256x272).
#define S2_B   34816
#define STG2   104448
#define HDR2   4096
#define SIMS_SMEM (HDR2 + 2 * STG2)   // 212992
#define E_STG  HDR2                   // 256 x 132 f32 = 135168

__global__ __launch_bounds__(512, 1) void k_sims_mma(const float* __restrict__ mem) {
    extern __shared__ char smem[];
    const uint32_t sb = smem_u32(smem);
    float* s_rn  = (float*)smem;                 // 128 f32
    float* s_act = (float*)(smem + 512);         // 128 f32

    const int tid = threadIdx.x;
    const int l   = tid & 31;
    const int w   = tid >> 5;       // 0..15
    const int wm  = w & 3;          // m rows wm*32..+32
    const int wn  = w >> 2;         // queries wn*64..+64
    const int m0  = blockIdx.x * TM;

    if (tid < 128) {
        bool ok = (m0 + tid) < M_MEM;
        s_act[tid] = ok ? g_act[m0 + tid] : -1e30f;
    }

    float acc[2][8][4];
#pragma unroll
    for (int a = 0; a < 2; a++)
#pragma unroll
        for (int p = 0; p < 8; p++)
#pragma unroll
            for (int r = 0; r < 4; r++) acc[a][p][r] = 0.f;

    // A: warp-per-row coalesced. Warp w owns rows w*8..w*8+7; lane covers 16B.
    const int ar0 = w * 8;
    const float* arowp[8];
#pragma unroll
    for (int r = 0; r < 8; r++) {
        int gr = m0 + ar0 + r; if (gr >= M_MEM) gr = M_MEM - 1;
        arowp[r] = mem + (size_t)gr * D_DIM + l * 4;
    }
    float nsq8[8];
#pragma unroll
    for (int r = 0; r < 8; r++) nsq8[r] = 0.f;

    const uint32_t aoff = (uint32_t)((wm * 32 + (l & 15)) * 272 + (l >> 4) * 16);
    const uint32_t boff = S2_B + (uint32_t)((wn * 64 + (l & 15)) * 272 + (l >> 4) * 16);

#define LOAD_B(st, cc) do {                                                   \
    _Pragma("unroll")                                                         \
    for (int i = 0; i < 8; i++) {                                             \
        int idx = i * 512 + tid;                                              \
        int row = idx >> 4, s = idx & 15;                                     \
        size_t go = (size_t)row * D_DIM + (cc) * 128 + s * 8;                 \
        CPA16((st) + S2_B + (uint32_t)(row * 272 + s * 16),                   \
              (const void*)(g_qhi + go));                                     \
    }                                                                         \
    CPA_COMMIT();                                                             \
} while (0)

// coalesced A: per row one warp-wide LDG.128 (512B), convert, contiguous STS.64
#define STORE_A(sc, cc) do {                                                  \
    float4 av[8];                                                             \
    _Pragma("unroll")                                                         \
    for (int r = 0; r < 8; r++)                                               \
        av[r] = *(const float4*)(arowp[r] + (cc) * 128);                      \
    _Pragma("unroll")                                                         \
    for (int r = 0; r < 8; r++) {                                             \
        float4 v = av[r];                                                     \
        nsq8[r] += v.x * v.x + v.y * v.y + v.z * v.z + v.w * v.w;             \
        uint32_t h0 = pk2hi(v.x, v.y), h1 = pk2hi(v.z, v.w);                  \
        *(uint2*)((sc) + (ar0 + r) * 272 + l * 8) = make_uint2(h0, h1);       \
    }                                                                         \
} while (0)

    // ---- prologue: chunks 0, 1 ----
    LOAD_B(sb + HDR2, 0);
    LOAD_B(sb + HDR2 + STG2, 1);
    STORE_A(smem + HDR2, 0);
    STORE_A(smem + HDR2 + STG2, 1);

#pragma unroll 1
    for (int c = 0; c < 3; c++) {
        const uint32_t st = sb + HDR2 + (c & 1) * STG2;
        if (c == 2) CPA_WAIT0(); else CPA_WAIT1();
        __syncthreads();

        const uint32_t aB = st + aoff;
        const uint32_t bB = st + boff;
#pragma unroll
        for (int kk = 0; kk < 8; kk++) {
            uint32_t bh[16];
#pragma unroll
            for (int pp = 0; pp < 4; pp++)
                ldsm4(bh + pp * 4, bB + (uint32_t)(pp * 16 * 272 + kk * 32));
#pragma unroll
            for (int a = 0; a < 2; a++) {
                uint32_t ah4[4];
                ldsm4(ah4, aB + (uint32_t)(a * 16 * 272 + kk * 32));
#pragma unroll
                for (int p = 0; p < 8; p++) {
                    int pp = p >> 1, hi = p & 1;
                    mma16816(acc[a][p], ah4, bh[pp * 4 + hi], bh[pp * 4 + hi + 2]);
                }
            }
        }

        if (c < 1) {
            __syncthreads();
            STORE_A(smem + HDR2 + (c & 1) * STG2, c + 2);
            LOAD_B(st, c + 2);
        }
    }

    // ---- norms: per-row warp reduction ----
    __syncthreads();
#pragma unroll
    for (int r = 0; r < 8; r++) {
        float s = nsq8[r];
#pragma unroll
        for (int o = 16; o > 0; o >>= 1) s += __shfl_xor_sync(0xffffffff, s, o);
        if (l == 0) {
            int row = ar0 + r;
            bool ok = (m0 + row) < M_MEM;
            s_rn[row] = ok ? 1.0f / fmaxf(sqrtf(s), 1e-8f) : 0.0f;
        }
    }
    __syncthreads();

    // ---- epilogue: scale + bias, stage query-major (256 queries) ----
    float* stg = (float*)(smem + E_STG);
#pragma unroll
    for (int a = 0; a < 2; a++) {
        int mA = wm * 32 + a * 16 + (l >> 2);
        float rnA = s_rn[mA],     acA = s_act[mA];
        float rnB = s_rn[mA + 8], acB = s_act[mA + 8];
#pragma unroll
        for (int p = 0; p < 8; p++) {
            int q = wn * 64 + p * 8 + (l & 3) * 2;
            stg[q * 132 + mA]           = acc[a][p][0] * rnA + acA;
            stg[(q + 1) * 132 + mA]     = acc[a][p][1] * rnA + acA;
            stg[q * 132 + mA + 8]       = acc[a][p][2] * rnB + acB;
            stg[(q + 1) * 132 + mA + 8] = acc[a][p][3] * rnB + acB;
        }
    }
    __syncthreads();

    // top-5: 2 threads per query, shuffle merge
    {
        int q = tid >> 1, h = tid & 1;
        float tv[TOPK]; int ti[TOPK];
#pragma unroll
        for (int r = 0; r < TOPK; r++) { tv[r] = -3.4e38f; ti[r] = 0x7fffffff; }
        const float4* col = (const float4*)(stg + q * 132 + h * 64);
#pragma unroll 4
        for (int i = 0; i < 16; i++) {
            float4 v = col[i];
            int mb = m0 + h * 64 + i * 4;
            ins5(v.x, mb,     tv, ti);
            ins5(v.y, mb + 1, tv, ti);
            ins5(v.z, mb + 2, tv, ti);
            ins5(v.w, mb + 3, tv, ti);
        }
        float ov[TOPK]; int oi[TOPK];
#pragma unroll
        for (int r = 0; r < TOPK; r++) {
            ov[r] = __shfl_down_sync(0xffffffff, tv[r], 1);
            oi[r] = __shfl_down_sync(0xffffffff, ti[r], 1);
        }
        if (h == 0) {
#pragma unroll
            for (int r = 0; r < TOPK; r++) ins5(ov[r], oi[r], tv, ti);
            size_t base = ((size_t)blockIdx.x * B_Q + q) * TOPK;
#pragma unroll
            for (int r = 0; r < TOPK; r++) {
                g_cand_val[base + r] = tv[r];
                g_cand_idx[base + r] = ti[r];
            }
        }
    }
#undef LOAD_B
#undef STORE_A
}

// ---------------- kernel C: fused merge -> top-16 pool -> exact refine -> top-5 ----------------
template <int K>
__device__ __forceinline__ void mergeK(float* av, int* ai, const float* bv, const int* bi) {
    float ov[K]; int oi[K];
    int ia = 0, ib = 0;
#pragma unroll
    for (int r = 0; r < K; r++) {
        bool ta = (ib >= K) || (ia < K && better(av[ia], ai[ia], bv[ib], bi[ib]));
        if (ta) { ov[r] = av[ia]; oi[r] = ai[ia]; ia++; }
        else    { ov[r] = bv[ib]; oi[r] = bi[ib]; ib++; }
    }
#pragma unroll
    for (int r = 0; r < K; r++) { av[r] = ov[r]; ai[r] = oi[r]; }
}

__global__ __launch_bounds__(256) void k_mergeref(const float* __restrict__ query,
                                                 const float* __restrict__ mem) {
    __shared__ float sv[256][KC];
    __shared__ int   si[256][KC];
    __shared__ float qv[D_DIM];
    __shared__ float s_qn[8];
    __shared__ float s_sims[KC];

    const int q = blockIdx.x, tid = threadIdx.x;
    const int lane = tid & 31, wr = tid >> 5;   // 8 warps

    float p = 0.f;
    for (int d = tid; d < D_DIM; d += 256) {
        float v = query[(size_t)q * D_DIM + d];
        qv[d] = v;
        p += v * v;
    }
#pragma unroll
    for (int o = 16; o > 0; o >>= 1) p += __shfl_xor_sync(0xffffffff, p, o);
    if (lane == 0) s_qn[wr] = p;

    float tv[KC]; int ti[KC];
#pragma unroll
    for (int r = 0; r < KC; r++) { tv[r] = -3.4e38f; ti[r] = 0x7fffffff; }
    for (int s = tid; s < NSLAB; s += 256) {
        size_t base = ((size_t)s * B_Q + q) * TOPK;
#pragma unroll
        for (int r = 0; r < TOPK; r++)
            insK<KC>(g_cand_val[base + r], g_cand_idx[base + r], tv, ti);
    }
#pragma unroll
    for (int r = 0; r < KC; r++) { sv[tid][r] = tv[r]; si[tid][r] = ti[r]; }
    __syncthreads();
    for (int o = 128; o > 0; o >>= 1) {
        if (tid < o) mergeK<KC>(sv[tid], si[tid], sv[tid + o], si[tid + o]);
        __syncthreads();
    }

    float qs = 0.f;
#pragma unroll
    for (int i = 0; i < 8; i++) qs += s_qn[i];
    float rq = 1.0f / fmaxf(sqrtf(qs), 1e-8f);

    for (int c = wr; c < KC; c += 8) {
        int mi = si[0][c];
        const float* mv = mem + (size_t)mi * D_DIM;
        float dot = 0.f, msq = 0.f;
        for (int d = lane; d < D_DIM; d += 32) {
            float m = mv[d];
            dot += qv[d] * m;
            msq += m * m;
        }
#pragma unroll
        for (int o = 16; o > 0; o >>= 1) {
            dot += __shfl_xor_sync(0xffffffff, dot, o);
            msq += __shfl_xor_sync(0xffffffff, msq, o);
        }
        if (lane == 0)
            s_sims[c] = dot * rq / fmaxf(sqrtf(msq), 1e-8f) + g_act[mi];
    }
    __syncthreads();

    if (tid == 0) {
        float fv[TOPK]; int fi[TOPK];
#pragma unroll
        for (int r = 0; r < TOPK; r++) { fv[r] = -3.4e38f; fi[r] = 0x7fffffff; }
        for (int c = 0; c < KC; c++)
            ins5(s_sims[c], si[0][c], fv, fi);
#pragma unroll
        for (int r = 0; r < TOPK; r++)
            g_topk[q * TOPK + r] = fi[r];
    }
}

// ---------------- kernel D1: x_proj + gate GEMM [1536 x 1024 x 384], fused h0 ----------------
#define XP_AHI 0
#define XP_ALO 34816
#define XP_BHI 69632
#define XP_BLO 104448
#define XP_SMEM 139264

__global__ __launch_bounds__(256, 1) void k_xproj(
    const float* __restrict__ query, const float* __restrict__ mem,
    const float* __restrict__ bih, const float* __restrict__ gb,
    const float* __restrict__ bhh)
{
    extern __shared__ char smem[];
    const uint32_t sb = smem_u32(smem);
    const int tid = threadIdx.x, l = tid & 31, w = tid >> 5;
    const int wm = w & 3, wn = w >> 2;
    const int bm = blockIdx.x, bn = blockIdx.y;

    const int lrow = tid >> 1, kh = tid & 1;
    int r = bm * 128 + lrow;
    int t = r >> 8, q = r & 255;
    const float* aptr;
    if (t == 0) aptr = query + (size_t)q * D_DIM;
    else        aptr = mem + (size_t)g_topk[q * TOPK + t - 1] * D_DIM;
    aptr += kh * 64;

    float acc[2][8][4];
#pragma unroll
    for (int a = 0; a < 2; a++)
#pragma unroll
        for (int p = 0; p < 8; p++)
#pragma unroll
            for (int rr = 0; rr < 4; rr++) acc[a][p][rr] = 0.f;

#pragma unroll 1
    for (int c = 0; c < 3; c++) {
        __syncthreads();
#pragma unroll
        for (int i = 0; i < 8; i++) {
            int idx = i * 256 + tid;
            int row = idx >> 4, s = idx & 15;
            uint32_t d = sb + (uint32_t)(row * 272 + s * 16);
            size_t go = (size_t)(bn * 128 + row) * D_DIM + c * 128 + s * 8;
            CPA16(d + XP_BHI, (const void*)(g_wcat_h + go));
            CPA16(d + XP_BLO, (const void*)(g_wcat_l + go));
        }
        CPA_COMMIT();
        {
            char* ah = smem + XP_AHI;
            char* al = smem + XP_ALO;
            const float4* src = (const float4*)(aptr + c * 128);
#pragma unroll
            for (int i = 0; i < 16; i++) {
                float4 v = src[i];
                uint32_t h0, l0, h1, l1;
                splt2(v.x, v.y, h0, l0);
                splt2(v.z, v.w, h1, l1);
                uint32_t so = (uint32_t)(lrow * 272 + kh * 128 + i * 8);
                *(uint2*)(ah + so) = make_uint2(h0, h1);
                *(uint2*)(al + so) = make_uint2(l0, l1);
            }
        }
        CPA_WAIT0();
        __syncthreads();

        const uint32_t aB = sb + XP_AHI + (uint32_t)((wm * 32 + (l & 15)) * 272 + (l >> 4) * 16);
        const uint32_t bB = sb + XP_BHI + (uint32_t)((wn * 64 + (l & 15)) * 272 + (l >> 4) * 16);
#pragma unroll 1
        for (int kk = 0; kk < 8; kk++) {
            uint32_t bh[16], bl[16];
#pragma unroll
            for (int pp = 0; pp < 4; pp++) {
                uint32_t ba = bB + (uint32_t)(pp * 16 * 272 + kk * 32);
                ldsm4(bh + pp * 4, ba);
                ldsm4(bl + pp * 4, ba + (XP_BLO - XP_BHI));
            }
#pragma unroll
            for (int a = 0; a < 2; a++) {
                uint32_t ah4[4], al4[4];
                uint32_t aa = aB + (uint32_t)(a * 16 * 272 + kk * 32);
                ldsm4(ah4, aa);
                ldsm4(al4, aa + (XP_ALO - XP_AHI));
#pragma unroll
                for (int p = 0; p < 8; p++) {
                    int pp = p >> 1, hi = p & 1;
                    mma16816(acc[a][p], ah4, bh[pp * 4 + hi], bh[pp * 4 + hi + 2]);
                    mma16816(acc[a][p], ah4, bl[pp * 4 + hi], bl[pp * 4 + hi + 2]);
                    mma16816(acc[a][p], al4, bh[pp * 4 + hi], bh[pp * 4 + hi + 2]);
                }
            }
        }
    }

    const bool fuse_h0 = (bm < 2) && (bn < 4);
#pragma unroll
    for (int a = 0; a < 2; a++) {
        int rA = bm * 128 + wm * 32 + a * 16 + (l >> 2);
#pragma unroll
        for (int p = 0; p < 8; p++) {
            int cg = bn * 128 + wn * 64 + p * 8 + (l & 3) * 2;
            float b0 = (cg < 512) ? bih[cg] : gb[cg - 512];
            float b1 = (cg < 512) ? bih[cg + 1] : gb[cg + 1 - 512];
            float v00 = acc[a][p][0] + b0, v01 = acc[a][p][1] + b1;
            float v10 = acc[a][p][2] + b0, v11 = acc[a][p][3] + b1;
            g_xp[(size_t)rA * 1024 + cg]           = v00;
            g_xp[(size_t)rA * 1024 + cg + 1]       = v01;
            g_xp[(size_t)(rA + 8) * 1024 + cg]     = v10;
            g_xp[(size_t)(rA + 8) * 1024 + cg + 1] = v11;
            if (fuse_h0) {
                float bh0 = bhh[cg], bh1 = bhh[cg + 1];
                float h00 = tanhf(v00 + bh0), h01 = tanhf(v01 + bh1);
                float h10 = tanhf(v10 + bh0), h11 = tanhf(v11 + bh1);
                size_t o0 = (size_t)rA * H_DIM + cg;
                size_t o1 = (size_t)(rA + 8) * H_DIM + cg;
                g_hf[o0] = h00; g_hf[o0 + 1] = h01;
                g_hf[o1] = h10; g_hf[o1 + 1] = h11;
                __nv_bfloat16 q00 = __float2bfloat16(h00), q01 = __float2bfloat16(h01);
                __nv_bfloat16 q10 = __float2bfloat16(h10), q11 = __float2bfloat16(h11);
                g_hbh[0][o0] = q00; g_hbh[0][o0 + 1] = q01;
                g_hbh[0][o1] = q10; g_hbh[0][o1 + 1] = q11;
                g_hbl[0][o0] = __float2bfloat16(h00 - __bfloat162float(q00));
                g_hbl[0][o0 + 1] = __float2bfloat16(h01 - __bfloat162float(q01));
                g_hbl[0][o1] = __float2bfloat16(h10 - __bfloat162float(q10));
                g_hbl[0][o1 + 1] = __float2bfloat16(h11 - __bfloat162float(q11));
            }
        }
    }
}

// ---------------- kernel D3: recurrence step GEMM, 32 CTAs, double-buffered ----------------
#define ST2_AHI 0
#define ST2_ALO 17408
#define ST2_BHI 34816
#define ST2_BLO 52224
#define ST2_STG 69632
#define ST2_SMEM (2 * ST2_STG)   // 139264

__global__ __launch_bounds__(256, 1) void k_step(int t, const float* __restrict__ bhh) {
    extern __shared__ char smem[];
    const uint32_t sb = smem_u32(smem);
    const int tid = threadIdx.x, l = tid & 31, w = tid >> 5;
    const int wm = w & 3, wn = w >> 2;   // warp tile 16 x 32
    const int mt = blockIdx.x, nt = blockIdx.y;   // (4, 8)
    const int bin = (t + 1) & 1, bout = t & 1;
    const __nv_bfloat16* Ah = g_hbh[bin];
    const __nv_bfloat16* Al = g_hbl[bin];

    float acc[4][4];
#pragma unroll
    for (int p = 0; p < 4; p++)
#pragma unroll
        for (int rr = 0; rr < 4; rr++) acc[p][rr] = 0.f;

#define ST_LOAD(cc) do {                                                      \
    uint32_t stn = sb + ((cc) & 1) * ST2_STG;                                 \
    _Pragma("unroll")                                                         \
    for (int i = 0; i < 4; i++) {                                             \
        int idx = i * 256 + tid;                                              \
        int row = idx >> 4, s = idx & 15;                                     \
        uint32_t d = stn + (uint32_t)(row * 272 + s * 16);                    \
        size_t goA = (size_t)(mt * 64 + row) * H_DIM + (cc) * 128 + s * 8;    \
        size_t goB = (size_t)(nt * 64 + row) * H_DIM + (cc) * 128 + s * 8;    \
        CPA16(d + ST2_AHI, (const void*)(Ah + goA));                          \
        CPA16(d + ST2_ALO, (const void*)(Al + goA));                          \
        CPA16(d + ST2_BHI, (const void*)(g_whh_h + goB));                     \
        CPA16(d + ST2_BLO, (const void*)(g_whh_l + goB));                     \
    }                                                                         \
    CPA_COMMIT();                                                             \
} while (0)

    ST_LOAD(0);

#pragma unroll 1
    for (int c = 0; c < 4; c++) {
        __syncthreads();
        if (c < 3) ST_LOAD(c + 1);
        if (c < 3) CPA_WAIT1(); else CPA_WAIT0();
        __syncthreads();

        const uint32_t st = sb + (c & 1) * ST2_STG;
        const uint32_t aB = st + ST2_AHI + (uint32_t)((wm * 16 + (l & 15)) * 272 + (l >> 4) * 16);
        const uint32_t bB = st + ST2_BHI + (uint32_t)((wn * 32 + (l & 15)) * 272 + (l >> 4) * 16);
#pragma unroll 1
        for (int kk = 0; kk < 8; kk++) {
            uint32_t bh[8], bl[8];
#pragma unroll
            for (int pp = 0; pp < 2; pp++) {
                uint32_t ba = bB + (uint32_t)(pp * 16 * 272 + kk * 32);
                ldsm4(bh + pp * 4, ba);
                ldsm4(bl + pp * 4, ba + (ST2_BLO - ST2_BHI));
            }
            uint32_t ah4[4], al4[4];
            ldsm4(ah4, aB + (uint32_t)(kk * 32));
            ldsm4(al4, aB + (uint32_t)(kk * 32) + (ST2_ALO - ST2_AHI));
#pragma unroll
            for (int p = 0; p < 4; p++) {
                int pp = p >> 1, hi = p & 1;
                mma16816(acc[p], ah4, bh[pp * 4 + hi], bh[pp * 4 + hi + 2]);
                mma16816(acc[p], ah4, bl[pp * 4 + hi], bl[pp * 4 + hi + 2]);
                mma16816(acc[p], al4, bh[pp * 4 + hi], bh[pp * 4 + hi + 2]);
            }
        }
    }

    int q0 = mt * 64 + wm * 16 + (l >> 2);
#pragma unroll
    for (int p = 0; p < 4; p++) {
        int h = nt * 64 + wn * 32 + p * 8 + (l & 3) * 2;
#pragma unroll
        for (int rr = 0; rr < 4; rr++) {
            int qq = q0 + ((rr >> 1) ? 8 : 0);
            int hh = h + (rr & 1);
            float v = acc[p][rr] + g_xp[(size_t)(t * 256 + qq) * 1024 + hh] + bhh[hh];
            float ht = tanhf(v);
            size_t o = (size_t)qq * H_DIM + hh;
            g_hf[o] = ht;
            __nv_bfloat16 hb = __float2bfloat16(ht);
            g_hbh[bout][o] = hb;
            g_hbl[bout][o] = __float2bfloat16(ht - __bfloat162float(hb));
        }
    }
#undef ST_LOAD
}

// ---------------- kernel D4: output gate mix ----------------
__global__ void k_out(float* __restrict__ out) {
    int i = blockIdx.x * blockDim.x + threadIdx.x;
    int q = i >> 9, h = i & 511;
    float gpre = g_xp[(size_t)q * 1024 + 512 + h];
    float g = 1.0f / (1.0f + expf(-gpre));
    float proj = g_xp[(size_t)q * 1024 + h];
    out[i] = g * g_hf[i] + (1.0f - g) * proj;
}

// ---------------- launch ----------------
extern "C" void kernel_launch(void* const* d_in, const int* in_sizes, int n_in,
                              void* d_out, int out_size) {
    const float* query  = (const float*)d_in[0];
    const float* mem    = (const float*)d_in[1];
    const float* coords = (const float*)d_in[2];
    const float* sw     = (const float*)d_in[3];
    const float* Wih    = (const float*)d_in[4];
    const float* bih    = (const float*)d_in[5];
    const float* Whh    = (const float*)d_in[6];
    const float* bhh    = (const float*)d_in[7];
    const float* gW     = (const float*)d_in[8];
    const float* gb     = (const float*)d_in[9];
    float* out = (float*)d_out;

    cudaFuncSetAttribute(k_sims_mma, cudaFuncAttributeMaxDynamicSharedMemorySize, SIMS_SMEM);
    cudaFuncSetAttribute(k_xproj,    cudaFuncAttributeMaxDynamicSharedMemorySize, XP_SMEM);
    cudaFuncSetAttribute(k_step,     cudaFuncAttributeMaxDynamicSharedMemorySize, ST2_SMEM);

    // k_sims as launch #4 -> lands in the ncu capture window
    k_center<<<1, 256>>>(sw);
    k_act<<<(M_MEM + 255) / 256, 256>>>(coords);
    k_qnorm<<<B_Q, 128>>>(query);
    k_sims_mma<<<NSLAB, 512, SIMS_SMEM>>>(mem);
    k_prep<<<(H_DIM * H_DIM + 1024 * D_DIM + 255) / 256, 256>>>(Whh, Wih, gW);
    k_mergeref<<<B_Q, 256>>>(query, mem);
    k_xproj<<<dim3(12, 8), 256, XP_SMEM>>>(query, mem, bih, gb, bhh);
    for (int t = 1; t <= TOPK; t++)
        k_step<<<dim3(4, 8), 256, ST2_SMEM>>>(t, bhh);
    k_out<<<(B_Q * H_DIM) / 256, 256>>>(out);
}